// round 3
// baseline (speedup 1.0000x reference)
#include <cuda_runtime.h>

// ----------------------------------------------------------------------------
// PositionAttention: B=4, L=1024, HD=512, H=8, D=64
// out = OutProj( MHA( QKVProj(q,k,v), bias=kernel^T, mask ) )
// Round 2: resubmit of Round 1 (container infra failed; kernel unvalidated).
// attn_mask elements are 4-byte (int32/float32 from jax bool): u32 != 0.
// ----------------------------------------------------------------------------

#define BATCH 4
#define SEQ   1024
#define HDIM  512
#define NHEAD 8
#define DHEAD 64
#define ROWS  (BATCH*SEQ)          // 4096

// scratch (allocation-free: device globals)
__device__ float g_qkv[3u * ROWS * HDIM];   // [z][row][hd]
__device__ float g_attn[ROWS * HDIM];       // attention output pre-projection

// ============================================================================
// Generic fp32 GEMM: C[M x N] = A[M x K] @ W[N x K]^T + bias[N]
// 128x128 block, BK=16, 256 threads, 8x8 micro-tile (2x2 groups of 4x4).
// ============================================================================
#define GBM 128
#define GBN 128
#define GBK 16

__device__ __forceinline__ void gemm_body(
    const float* __restrict__ A, const float* __restrict__ W,
    const float* __restrict__ bias, float* __restrict__ C,
    int K, int N)
{
    __shared__ float As[GBK][GBM];
    __shared__ float Bs[GBK][GBN];
    const int tid = threadIdx.x;
    const int tx = tid & 15, ty = tid >> 4;
    const int bm = blockIdx.y * GBM;
    const int bn = blockIdx.x * GBN;

    float acc[8][8];
#pragma unroll
    for (int i = 0; i < 8; i++)
#pragma unroll
        for (int j = 0; j < 8; j++) acc[i][j] = 0.f;

    for (int k0 = 0; k0 < K; k0 += GBK) {
#pragma unroll
        for (int t = 0; t < 2; t++) {
            int lin = t * 256 + tid;
            int row = lin >> 2;
            int kq  = (lin & 3) << 2;
            float4 a = *(const float4*)(A + (size_t)(bm + row) * K + k0 + kq);
            As[kq + 0][row] = a.x; As[kq + 1][row] = a.y;
            As[kq + 2][row] = a.z; As[kq + 3][row] = a.w;
            float4 w = *(const float4*)(W + (size_t)(bn + row) * K + k0 + kq);
            Bs[kq + 0][row] = w.x; Bs[kq + 1][row] = w.y;
            Bs[kq + 2][row] = w.z; Bs[kq + 3][row] = w.w;
        }
        __syncthreads();
#pragma unroll
        for (int k = 0; k < GBK; k++) {
            float a[8], b[8];
            *(float4*)(a)     = *(const float4*)&As[k][ty * 4];
            *(float4*)(a + 4) = *(const float4*)&As[k][64 + ty * 4];
            *(float4*)(b)     = *(const float4*)&Bs[k][tx * 4];
            *(float4*)(b + 4) = *(const float4*)&Bs[k][64 + tx * 4];
#pragma unroll
            for (int i = 0; i < 8; i++)
#pragma unroll
                for (int j = 0; j < 8; j++)
                    acc[i][j] = fmaf(a[i], b[j], acc[i][j]);
        }
        __syncthreads();
    }

#pragma unroll
    for (int i = 0; i < 8; i++) {
        int r = bm + ((i < 4) ? (ty * 4 + i) : (64 + ty * 4 + i - 4));
#pragma unroll
        for (int hh = 0; hh < 2; hh++) {
            int c = bn + hh * 64 + tx * 4;
            float4 o;
            o.x = acc[i][hh * 4 + 0] + bias[c + 0];
            o.y = acc[i][hh * 4 + 1] + bias[c + 1];
            o.z = acc[i][hh * 4 + 2] + bias[c + 2];
            o.w = acc[i][hh * 4 + 3] + bias[c + 3];
            *(float4*)(C + (size_t)r * N + c) = o;
        }
    }
}

__global__ void __launch_bounds__(256)
qkv_gemm_kernel(const float* __restrict__ q, const float* __restrict__ k,
                const float* __restrict__ v, const float* __restrict__ W,
                const float* __restrict__ bias)
{
    int z = blockIdx.z;
    const float* A = (z == 0) ? q : (z == 1) ? k : v;
    gemm_body(A, W + (size_t)z * HDIM * HDIM, bias + z * HDIM,
              g_qkv + (size_t)z * ROWS * HDIM, HDIM, HDIM);
}

__global__ void __launch_bounds__(256)
outproj_kernel(const float* __restrict__ W, const float* __restrict__ bias,
               float* __restrict__ out)
{
    gemm_body(g_attn, W, bias, out, HDIM, HDIM);
}

// ============================================================================
// Fused attention: per (bh, 64-row q block), flash-style over 16 k-tiles of 64.
// scores = scale*(Q K^T) + kernel[bh][k][q]; mask -> -inf; online softmax; O=P@V
// ============================================================================
#define PAD 68   // 64 + 4 floats row pad (keeps 16B alignment, breaks conflicts)

__global__ void __launch_bounds__(256)
attn_kernel(const float* __restrict__ kern, const unsigned int* __restrict__ amask,
            float scale)
{
    extern __shared__ float sm[];
    float* Qs = sm;                 // [64][PAD]
    float* Ks = Qs + 64 * PAD;
    float* Vs = Ks + 64 * PAD;
    float* Ps = Vs + 64 * PAD;      // probabilities tile
    float* Bb = Ps + 64 * PAD;      // bias tile: Bb[k][q]
    unsigned char* Ms = (unsigned char*)(Bb + 64 * PAD);  // mask tile 64x64 bytes

    const int bh = blockIdx.y;            // 0..31
    const int b  = bh >> 3, h = bh & 7;
    const int qb = blockIdx.x * 64;
    const int tid = threadIdx.x;
    const int tx = tid & 15, ty = tid >> 4;

    const float* Qg = g_qkv + ((size_t)b * SEQ) * HDIM + h * DHEAD;
    const float* Kg = g_qkv + (size_t)ROWS * HDIM + (size_t)b * SEQ * HDIM + h * DHEAD;
    const float* Vg = g_qkv + (size_t)2 * ROWS * HDIM + (size_t)b * SEQ * HDIM + h * DHEAD;

    // load Q tile (64 x 64), coalesced float4
#pragma unroll
    for (int t = 0; t < 4; t++) {
        int lin = t * 256 + tid;
        int r = lin >> 4, c4 = (lin & 15) << 2;
        *(float4*)&Qs[r * PAD + c4] =
            *(const float4*)(Qg + (size_t)(qb + r) * HDIM + c4);
    }

    float m_i[4], l_i[4], o[4][4];
#pragma unroll
    for (int i = 0; i < 4; i++) {
        m_i[i] = -1e30f; l_i[i] = 0.f;
#pragma unroll
        for (int j = 0; j < 4; j++) o[i][j] = 0.f;
    }

    for (int kb = 0; kb < 16; kb++) {
        __syncthreads();   // previous iteration done with Ks/Vs/Bb/Ps, Qs ready
#pragma unroll
        for (int t = 0; t < 4; t++) {
            int lin = t * 256 + tid;
            int r = lin >> 4, c4 = (lin & 15) << 2;
            *(float4*)&Ks[r * PAD + c4] =
                *(const float4*)(Kg + (size_t)(kb * 64 + r) * HDIM + c4);
            *(float4*)&Vs[r * PAD + c4] =
                *(const float4*)(Vg + (size_t)(kb * 64 + r) * HDIM + c4);
            // bias tile, coalesced: kernel[bh][kb*64+r][qb+c4..]
            *(float4*)&Bb[r * PAD + c4] =
                *(const float4*)(kern + ((size_t)bh * SEQ + kb * 64 + r) * SEQ + qb + c4);
        }
        // mask tile: 4096 u32 elements (jax bool widened to 4 bytes).
        // Nonzero word == masked. Works for int32 {0,1} and fp32 {0.0,1.0}.
#pragma unroll
        for (int t = 0; t < 16; t++) {
            int lin = t * 256 + tid;
            int r = lin >> 6, c = lin & 63;
            unsigned int w = amask[((size_t)bh * SEQ + qb + r) * SEQ + kb * 64 + c];
            Ms[lin] = (w != 0u) ? 1 : 0;
        }
        __syncthreads();

        // S = Q K^T (4x4 per thread: rows ty*4+i, cols tx*4+j)
        float s[4][4];
#pragma unroll
        for (int i = 0; i < 4; i++)
#pragma unroll
            for (int j = 0; j < 4; j++) s[i][j] = 0.f;
#pragma unroll
        for (int d4 = 0; d4 < 64; d4 += 4) {
            float qv[4][4], kv[4][4];
#pragma unroll
            for (int i = 0; i < 4; i++)
                *(float4*)qv[i] = *(const float4*)&Qs[(ty * 4 + i) * PAD + d4];
#pragma unroll
            for (int j = 0; j < 4; j++)
                *(float4*)kv[j] = *(const float4*)&Ks[(tx * 4 + j) * PAD + d4];
#pragma unroll
            for (int d = 0; d < 4; d++)
#pragma unroll
                for (int i = 0; i < 4; i++)
#pragma unroll
                    for (int j = 0; j < 4; j++)
                        s[i][j] = fmaf(qv[i][d], kv[j][d], s[i][j]);
        }
        // scale + bias (kernel^T) + mask
#pragma unroll
        for (int i = 0; i < 4; i++) {
            int r = ty * 4 + i;
#pragma unroll
            for (int j = 0; j < 4; j++) {
                int c = tx * 4 + j;
                float sc = s[i][j] * scale + Bb[c * PAD + r];
                s[i][j] = Ms[r * 64 + c] ? -1e30f : sc;
            }
        }

        // online softmax (row reduce across 16 lanes sharing ty)
#pragma unroll
        for (int i = 0; i < 4; i++) {
            float tmax = fmaxf(fmaxf(s[i][0], s[i][1]), fmaxf(s[i][2], s[i][3]));
#pragma unroll
            for (int off = 8; off >= 1; off >>= 1)
                tmax = fmaxf(tmax, __shfl_xor_sync(0xffffffffu, tmax, off));
            float mn = fmaxf(m_i[i], tmax);
            float f  = __expf(m_i[i] - mn);
            float ps = 0.f;
#pragma unroll
            for (int j = 0; j < 4; j++) {
                float p = (s[i][j] < -1e29f) ? 0.f : __expf(s[i][j] - mn);
                s[i][j] = p; ps += p;
            }
#pragma unroll
            for (int off = 8; off >= 1; off >>= 1)
                ps += __shfl_xor_sync(0xffffffffu, ps, off);
            l_i[i] = l_i[i] * f + ps;
            m_i[i] = mn;
#pragma unroll
            for (int j = 0; j < 4; j++) o[i][j] *= f;
        }

        // publish P tile
#pragma unroll
        for (int i = 0; i < 4; i++) {
            float4 pv = make_float4(s[i][0], s[i][1], s[i][2], s[i][3]);
            *(float4*)&Ps[(ty * 4 + i) * PAD + tx * 4] = pv;
        }
        __syncthreads();

        // O += P @ V  (rows ty*4+i, dims tx*4+j)
#pragma unroll
        for (int c4 = 0; c4 < 64; c4 += 4) {
            float pv[4][4], vv[4][4];
#pragma unroll
            for (int i = 0; i < 4; i++)
                *(float4*)pv[i] = *(const float4*)&Ps[(ty * 4 + i) * PAD + c4];
#pragma unroll
            for (int cc = 0; cc < 4; cc++)
                *(float4*)vv[cc] = *(const float4*)&Vs[(c4 + cc) * PAD + tx * 4];
#pragma unroll
            for (int cc = 0; cc < 4; cc++)
#pragma unroll
                for (int i = 0; i < 4; i++)
#pragma unroll
                    for (int j = 0; j < 4; j++)
                        o[i][j] = fmaf(pv[i][cc], vv[cc][j], o[i][j]);
        }
    }

    // epilogue: normalize and write merged-head layout
    float* Og = g_attn + ((size_t)b * SEQ + qb) * HDIM + h * DHEAD;
#pragma unroll
    for (int i = 0; i < 4; i++) {
        float inv = 1.0f / l_i[i];
        float4 ov = make_float4(o[i][0] * inv, o[i][1] * inv,
                                o[i][2] * inv, o[i][3] * inv);
        *(float4*)(Og + (size_t)(ty * 4 + i) * HDIM + tx * 4) = ov;
    }
}

// ============================================================================
// Launch
// ============================================================================
extern "C" void kernel_launch(void* const* d_in, const int* in_sizes, int n_in,
                              void* d_out, int out_size)
{
    const float* query        = (const float*)d_in[0];
    const float* key_         = (const float*)d_in[1];
    const float* value        = (const float*)d_in[2];
    const unsigned int* amask = (const unsigned int*)d_in[3];  // bool widened to 4B
    // d_in[4] = key_padding_mask (scalar, unused)
    const float* kern         = (const float*)d_in[5];
    const float* ipw          = (const float*)d_in[6];
    const float* ipb          = (const float*)d_in[7];
    const float* outw         = (const float*)d_in[8];
    const float* outb         = (const float*)d_in[9];
    float* out = (float*)d_out;

    const int attn_smem = (5 * 64 * PAD) * (int)sizeof(float) + 64 * 64;
    cudaFuncSetAttribute(attn_kernel,
                         cudaFuncAttributeMaxDynamicSharedMemorySize, attn_smem);

    dim3 gq(HDIM / GBN, ROWS / GBM, 3);
    qkv_gemm_kernel<<<gq, 256>>>(query, key_, value, ipw, ipb);

    dim3 ga(SEQ / 64, BATCH * NHEAD, 1);
    attn_kernel<<<ga, 256, attn_smem>>>(kern, amask, 0.125f);

    dim3 go(HDIM / GBN, ROWS / GBM, 1);
    outproj_kernel<<<go, 256>>>(outw, outb, out);
}

// round 4
// speedup vs baseline: 1.8600x; 1.8600x over previous
#include <cuda_runtime.h>
#include <cstdint>

// ----------------------------------------------------------------------------
// PositionAttention: B=4, L=1024, HD=512, H=8, D=64
// Round 3: attention mainloop -> mma.sync m16n8k8 TF32 tensor cores.
// Projections remain fp32 SIMT (precision budget).
// ----------------------------------------------------------------------------

#define BATCH 4
#define SEQ   1024
#define HDIM  512
#define NHEAD 8
#define DHEAD 64
#define ROWS  (BATCH*SEQ)          // 4096

__device__ float g_qkv[3u * ROWS * HDIM];   // [z][row][hd]
__device__ float g_attn[ROWS * HDIM];       // attention output pre-projection

// ============================================================================
// fp32 GEMM (unchanged from round 2): C = A[MxK] @ W[NxK]^T + bias
// ============================================================================
#define GBM 128
#define GBN 128
#define GBK 16

__device__ __forceinline__ void gemm_body(
    const float* __restrict__ A, const float* __restrict__ W,
    const float* __restrict__ bias, float* __restrict__ C,
    int K, int N)
{
    __shared__ float As[GBK][GBM];
    __shared__ float Bs[GBK][GBN];
    const int tid = threadIdx.x;
    const int tx = tid & 15, ty = tid >> 4;
    const int bm = blockIdx.y * GBM;
    const int bn = blockIdx.x * GBN;

    float acc[8][8];
#pragma unroll
    for (int i = 0; i < 8; i++)
#pragma unroll
        for (int j = 0; j < 8; j++) acc[i][j] = 0.f;

    for (int k0 = 0; k0 < K; k0 += GBK) {
#pragma unroll
        for (int t = 0; t < 2; t++) {
            int lin = t * 256 + tid;
            int row = lin >> 2;
            int kq  = (lin & 3) << 2;
            float4 a = *(const float4*)(A + (size_t)(bm + row) * K + k0 + kq);
            As[kq + 0][row] = a.x; As[kq + 1][row] = a.y;
            As[kq + 2][row] = a.z; As[kq + 3][row] = a.w;
            float4 w = *(const float4*)(W + (size_t)(bn + row) * K + k0 + kq);
            Bs[kq + 0][row] = w.x; Bs[kq + 1][row] = w.y;
            Bs[kq + 2][row] = w.z; Bs[kq + 3][row] = w.w;
        }
        __syncthreads();
#pragma unroll
        for (int k = 0; k < GBK; k++) {
            float a[8], b[8];
            *(float4*)(a)     = *(const float4*)&As[k][ty * 4];
            *(float4*)(a + 4) = *(const float4*)&As[k][64 + ty * 4];
            *(float4*)(b)     = *(const float4*)&Bs[k][tx * 4];
            *(float4*)(b + 4) = *(const float4*)&Bs[k][64 + tx * 4];
#pragma unroll
            for (int i = 0; i < 8; i++)
#pragma unroll
                for (int j = 0; j < 8; j++)
                    acc[i][j] = fmaf(a[i], b[j], acc[i][j]);
        }
        __syncthreads();
    }

#pragma unroll
    for (int i = 0; i < 8; i++) {
        int r = bm + ((i < 4) ? (ty * 4 + i) : (64 + ty * 4 + i - 4));
#pragma unroll
        for (int hh = 0; hh < 2; hh++) {
            int c = bn + hh * 64 + tx * 4;
            float4 o;
            o.x = acc[i][hh * 4 + 0] + bias[c + 0];
            o.y = acc[i][hh * 4 + 1] + bias[c + 1];
            o.z = acc[i][hh * 4 + 2] + bias[c + 2];
            o.w = acc[i][hh * 4 + 3] + bias[c + 3];
            *(float4*)(C + (size_t)r * N + c) = o;
        }
    }
}

__global__ void __launch_bounds__(256)
qkv_gemm_kernel(const float* __restrict__ q, const float* __restrict__ k,
                const float* __restrict__ v, const float* __restrict__ W,
                const float* __restrict__ bias)
{
    int z = blockIdx.z;
    const float* A = (z == 0) ? q : (z == 1) ? k : v;
    gemm_body(A, W + (size_t)z * HDIM * HDIM, bias + z * HDIM,
              g_qkv + (size_t)z * ROWS * HDIM, HDIM, HDIM);
}

__global__ void __launch_bounds__(256)
outproj_kernel(const float* __restrict__ W, const float* __restrict__ bias,
               float* __restrict__ out)
{
    gemm_body(g_attn, W, bias, out, HDIM, HDIM);
}

// ============================================================================
// TF32 tensor-core flash attention.
// Block: 128 q-rows (QB) x full head; loop over 16 key-tiles of 64 (KB).
// 8 warps; warp w owns q-rows [w*16, w*16+16). mma.sync m16n8k8 tf32.
// ============================================================================
#define QB 128
#define KB 64
#define PADK 68    // (68*g + t) % 32 unique over quad -> conflict-free B-frags
#define PADV 72    // (72*t + g) % 32 = (8t+g)       -> conflict-free
#define PADP 68
#define PADB 132   // 132*4 = 528 bytes, 16B aligned rows

__device__ __forceinline__ uint32_t f2tf32(float f) {
    uint32_t r;
    asm("cvt.rna.tf32.f32 %0, %1;" : "=r"(r) : "f"(f));
    return r;
}

__device__ __forceinline__ void mma_tf32(float c[4],
    uint32_t a0, uint32_t a1, uint32_t a2, uint32_t a3,
    uint32_t b0, uint32_t b1)
{
    asm volatile(
        "mma.sync.aligned.m16n8k8.row.col.f32.tf32.tf32.f32 "
        "{%0,%1,%2,%3}, {%4,%5,%6,%7}, {%8,%9}, {%0,%1,%2,%3};"
        : "+f"(c[0]), "+f"(c[1]), "+f"(c[2]), "+f"(c[3])
        : "r"(a0), "r"(a1), "r"(a2), "r"(a3), "r"(b0), "r"(b1));
}

__global__ void __launch_bounds__(256, 2)
attn_mma_kernel(const float* __restrict__ kern,
                const unsigned int* __restrict__ amask, float scale)
{
    extern __shared__ float sm[];
    float* Ks  = sm;                        // KB x PADK (tf32 bits)
    float* Vs  = Ks + KB * PADK;            // KB x PADV (tf32 bits)
    float* Ps  = Vs + KB * PADV;            // QB x PADP (P tf32; Q staging)
    float* Bbs = Ps + QB * PADP;            // KB x PADB (bias [k][q])
    unsigned char* Msk = (unsigned char*)(Bbs + KB * PADB);  // QB x KB bytes

    const int bh = blockIdx.y, b = bh >> 3, h = bh & 7;
    const int qb = blockIdx.x * QB;
    const int tid  = threadIdx.x;
    const int w    = tid >> 5;
    const int lane = tid & 31;
    const int g = lane >> 2, t = lane & 3;   // groupID, threadID-in-group

    const float* Qg = g_qkv + (size_t)b * SEQ * HDIM + h * DHEAD;
    const float* Kg = g_qkv + (size_t)ROWS * HDIM + (size_t)b * SEQ * HDIM + h * DHEAD;
    const float* Vg = g_qkv + (size_t)2 * ROWS * HDIM + (size_t)b * SEQ * HDIM + h * DHEAD;

    // ---- stage Q tile (QB x 64) into Ps area, tf32-rounded, coalesced ----
#pragma unroll
    for (int it = 0; it < 8; it++) {
        int lin = (it * 256 + tid) * 4;      // element index
        int r = lin >> 6, c = lin & 63;
        float4 v = *(const float4*)(Qg + (size_t)(qb + r) * HDIM + c);
        v.x = __uint_as_float(f2tf32(v.x)); v.y = __uint_as_float(f2tf32(v.y));
        v.z = __uint_as_float(f2tf32(v.z)); v.w = __uint_as_float(f2tf32(v.w));
        *(float4*)&Ps[r * PADP + c] = v;
    }
    __syncthreads();

    // ---- build Q A-fragments (held in regs for all k-tiles) ----
    uint32_t qa[8][4];
    const int qr = w * 16 + g;
#pragma unroll
    for (int k = 0; k < 8; k++) {
        qa[k][0] = __float_as_uint(Ps[qr * PADP + k * 8 + t]);
        qa[k][1] = __float_as_uint(Ps[(qr + 8) * PADP + k * 8 + t]);
        qa[k][2] = __float_as_uint(Ps[qr * PADP + k * 8 + t + 4]);
        qa[k][3] = __float_as_uint(Ps[(qr + 8) * PADP + k * 8 + t + 4]);
    }
    // warp w reads/writes only its own 16 Ps rows hereafter -> no extra sync.

    float o[8][4];
#pragma unroll
    for (int f = 0; f < 8; f++)
#pragma unroll
        for (int u = 0; u < 4; u++) o[f][u] = 0.f;
    float m_[2] = {-1e30f, -1e30f}, l_[2] = {0.f, 0.f};

    for (int kb = 0; kb < 16; kb++) {
        __syncthreads();    // prev iter done with Ks/Vs/Bbs/Msk
        // ---- stage K, V (tf32), bias, mask ----
#pragma unroll
        for (int it = 0; it < 4; it++) {
            int lin = (it * 256 + tid) * 4;
            int r = lin >> 6, c = lin & 63;
            float4 kv = *(const float4*)(Kg + (size_t)(kb * KB + r) * HDIM + c);
            kv.x = __uint_as_float(f2tf32(kv.x)); kv.y = __uint_as_float(f2tf32(kv.y));
            kv.z = __uint_as_float(f2tf32(kv.z)); kv.w = __uint_as_float(f2tf32(kv.w));
            *(float4*)&Ks[r * PADK + c] = kv;
            float4 vv = *(const float4*)(Vg + (size_t)(kb * KB + r) * HDIM + c);
            vv.x = __uint_as_float(f2tf32(vv.x)); vv.y = __uint_as_float(f2tf32(vv.y));
            vv.z = __uint_as_float(f2tf32(vv.z)); vv.w = __uint_as_float(f2tf32(vv.w));
            *(float4*)&Vs[r * PADV + c] = vv;
        }
#pragma unroll
        for (int it = 0; it < 8; it++) {
            int lin = (it * 256 + tid) * 4;
            int kr = lin >> 7, qc = lin & 127;
            float4 bb = *(const float4*)(kern +
                ((size_t)bh * SEQ + kb * KB + kr) * SEQ + qb + qc);
            *(float4*)&Bbs[kr * PADB + qc] = bb;
        }
#pragma unroll
        for (int it = 0; it < 8; it++) {
            int widx = it * 256 + tid;
            int lin = widx * 4;
            int r = lin >> 6, c = lin & 63;
            uint4 mw = *(const uint4*)(amask +
                ((size_t)bh * SEQ + qb + r) * SEQ + kb * KB + c);
            unsigned pk = (mw.x ? 1u : 0u) | (mw.y ? 0x100u : 0u) |
                          (mw.z ? 0x10000u : 0u) | (mw.w ? 0x1000000u : 0u);
            ((unsigned*)Msk)[widx] = pk;
        }
        __syncthreads();

        // ---- S = Q K^T (warp: 16 rows x 64 cols) ----
        float sc[8][4];
#pragma unroll
        for (int f = 0; f < 8; f++)
#pragma unroll
            for (int u = 0; u < 4; u++) sc[f][u] = 0.f;
#pragma unroll
        for (int k = 0; k < 8; k++) {
#pragma unroll
            for (int f = 0; f < 8; f++) {
                uint32_t b0 = __float_as_uint(Ks[(f * 8 + g) * PADK + k * 8 + t]);
                uint32_t b1 = __float_as_uint(Ks[(f * 8 + g) * PADK + k * 8 + t + 4]);
                mma_tf32(sc[f], qa[k][0], qa[k][1], qa[k][2], qa[k][3], b0, b1);
            }
        }

        // ---- epilogue: scale + bias(kernel^T) + mask + online softmax ----
#pragma unroll
        for (int e = 0; e < 2; e++) {
            const int qrl = w * 16 + g + e * 8;    // local q row
            float rmax = -1e30f;
#pragma unroll
            for (int f = 0; f < 8; f++) {
#pragma unroll
                for (int u = 0; u < 2; u++) {
                    int kc = f * 8 + 2 * t + u;
                    float s = sc[f][e * 2 + u] * scale + Bbs[kc * PADB + qrl];
                    s = Msk[qrl * KB + kc] ? -1e30f : s;
                    sc[f][e * 2 + u] = s;
                    rmax = fmaxf(rmax, s);
                }
            }
            rmax = fmaxf(rmax, __shfl_xor_sync(0xffffffffu, rmax, 1));
            rmax = fmaxf(rmax, __shfl_xor_sync(0xffffffffu, rmax, 2));
            float mn = fmaxf(m_[e], rmax);
            float fe = __expf(m_[e] - mn);
            float ps = 0.f;
#pragma unroll
            for (int f = 0; f < 8; f++) {
#pragma unroll
                for (int u = 0; u < 2; u++) {
                    float sv = sc[f][e * 2 + u];
                    float p = (sv <= -1e29f) ? 0.f : __expf(sv - mn);
                    sc[f][e * 2 + u] = p;
                    ps += p;
                }
            }
            ps += __shfl_xor_sync(0xffffffffu, ps, 1);
            ps += __shfl_xor_sync(0xffffffffu, ps, 2);
            l_[e] = l_[e] * fe + ps;
            m_[e] = mn;
#pragma unroll
            for (int f = 0; f < 8; f++) {
                o[f][e * 2 + 0] *= fe;
                o[f][e * 2 + 1] *= fe;
            }
            // publish this row's P (tf32) — own-warp rows only
#pragma unroll
            for (int f = 0; f < 8; f++) {
                float2 pv;
                pv.x = __uint_as_float(f2tf32(sc[f][e * 2 + 0]));
                pv.y = __uint_as_float(f2tf32(sc[f][e * 2 + 1]));
                *(float2*)&Ps[qrl * PADP + f * 8 + 2 * t] = pv;
            }
        }
        __syncwarp();   // own-warp STS->LDS visibility

        // ---- O += P @ V ----
#pragma unroll
        for (int k = 0; k < 8; k++) {
            uint32_t a0 = __float_as_uint(Ps[(w * 16 + g) * PADP + k * 8 + t]);
            uint32_t a1 = __float_as_uint(Ps[(w * 16 + g + 8) * PADP + k * 8 + t]);
            uint32_t a2 = __float_as_uint(Ps[(w * 16 + g) * PADP + k * 8 + t + 4]);
            uint32_t a3 = __float_as_uint(Ps[(w * 16 + g + 8) * PADP + k * 8 + t + 4]);
#pragma unroll
            for (int f = 0; f < 8; f++) {
                uint32_t b0 = __float_as_uint(Vs[(k * 8 + t) * PADV + f * 8 + g]);
                uint32_t b1 = __float_as_uint(Vs[(k * 8 + t + 4) * PADV + f * 8 + g]);
                mma_tf32(o[f], a0, a1, a2, a3, b0, b1);
            }
        }
    }

    // ---- normalize + write merged-head layout ----
    float* Og = g_attn + ((size_t)b * SEQ + qb) * HDIM + h * DHEAD;
#pragma unroll
    for (int e = 0; e < 2; e++) {
        float inv = 1.0f / l_[e];
        int qrl = w * 16 + g + e * 8;
#pragma unroll
        for (int f = 0; f < 8; f++) {
            float2 ov;
            ov.x = o[f][e * 2 + 0] * inv;
            ov.y = o[f][e * 2 + 1] * inv;
            *(float2*)(Og + (size_t)qrl * HDIM + f * 8 + 2 * t) = ov;
        }
    }
}

// ============================================================================
// Launch
// ============================================================================
extern "C" void kernel_launch(void* const* d_in, const int* in_sizes, int n_in,
                              void* d_out, int out_size)
{
    const float* query        = (const float*)d_in[0];
    const float* key_         = (const float*)d_in[1];
    const float* value        = (const float*)d_in[2];
    const unsigned int* amask = (const unsigned int*)d_in[3];  // bool widened to 4B
    // d_in[4] = key_padding_mask (scalar, unused)
    const float* kern         = (const float*)d_in[5];
    const float* ipw          = (const float*)d_in[6];
    const float* ipb          = (const float*)d_in[7];
    const float* outw         = (const float*)d_in[8];
    const float* outb         = (const float*)d_in[9];
    float* out = (float*)d_out;

    const int attn_smem =
        (KB * PADK + KB * PADV + QB * PADP + KB * PADB) * (int)sizeof(float)
        + QB * KB;   // = 112640 bytes
    cudaFuncSetAttribute(attn_mma_kernel,
                         cudaFuncAttributeMaxDynamicSharedMemorySize, attn_smem);

    dim3 gq(HDIM / GBN, ROWS / GBM, 3);
    qkv_gemm_kernel<<<gq, 256>>>(query, key_, value, ipw, ipb);

    dim3 ga(SEQ / QB, BATCH * NHEAD, 1);
    attn_mma_kernel<<<ga, 256, attn_smem>>>(kern, amask, 0.125f);

    dim3 go(HDIM / GBN, ROWS / GBM, 1);
    outproj_kernel<<<go, 256>>>(outw, outb, out);
}

// round 5
// speedup vs baseline: 2.6194x; 1.4083x over previous
#include <cuda_runtime.h>
#include <cuda_bf16.h>
#include <cstdint>

// ----------------------------------------------------------------------------
// PositionAttention: B=4, L=1024, HD=512, H=8, D=64
// Round 5: projection GEMMs -> bf16x3 split tensor cores (mma.sync m16n8k16).
// Attention unchanged (TF32 mma, validated at 2.97e-4).
// ----------------------------------------------------------------------------

#define BATCH 4
#define SEQ   1024
#define HDIM  512
#define NHEAD 8
#define DHEAD 64
#define ROWS  (BATCH*SEQ)          // 4096

__device__ float g_qkv[3u * ROWS * HDIM];   // [z][row][hd]
__device__ float g_attn[ROWS * HDIM];       // attention output pre-projection

// ============================================================================
// bf16x3 tensor-core GEMM: C[MxN] = A[MxK] @ W[NxK]^T + bias
// 128x128x32 block, 8 warps (2x4), warp tile 64x32, m16n8k16 bf16 MMA.
// x = hi + lo (bf16 each); x*y ~= hh + hl + lh (lo*lo ~ 4e-6 rel, dropped).
// ============================================================================
#define TBM 128
#define TBN 128
#define TBK 32
#define ASTR 40        // bf16 units per smem row (32 + 8 pad) = 20 words

__device__ __forceinline__ void mma_bf16(float c[4],
    uint32_t a0, uint32_t a1, uint32_t a2, uint32_t a3,
    uint32_t b0, uint32_t b1)
{
    asm volatile(
        "mma.sync.aligned.m16n8k16.row.col.f32.bf16.bf16.f32 "
        "{%0,%1,%2,%3}, {%4,%5,%6,%7}, {%8,%9}, {%0,%1,%2,%3};"
        : "+f"(c[0]), "+f"(c[1]), "+f"(c[2]), "+f"(c[3])
        : "r"(a0), "r"(a1), "r"(a2), "r"(a3), "r"(b0), "r"(b1));
}

__device__ __forceinline__ void split_store(
    __nv_bfloat16* hi_s, __nv_bfloat16* lo_s, int off, float4 v)
{
    __nv_bfloat16 h0 = __float2bfloat16_rn(v.x);
    __nv_bfloat16 h1 = __float2bfloat16_rn(v.y);
    __nv_bfloat16 h2 = __float2bfloat16_rn(v.z);
    __nv_bfloat16 h3 = __float2bfloat16_rn(v.w);
    __nv_bfloat16 l0 = __float2bfloat16_rn(v.x - __bfloat162float(h0));
    __nv_bfloat16 l1 = __float2bfloat16_rn(v.y - __bfloat162float(h1));
    __nv_bfloat16 l2 = __float2bfloat16_rn(v.z - __bfloat162float(h2));
    __nv_bfloat16 l3 = __float2bfloat16_rn(v.w - __bfloat162float(h3));
    __nv_bfloat162 hp0(h0, h1), hp1(h2, h3), lp0(l0, l1), lp1(l2, l3);
    uint2 hw, lw;
    hw.x = *(uint32_t*)&hp0; hw.y = *(uint32_t*)&hp1;
    lw.x = *(uint32_t*)&lp0; lw.y = *(uint32_t*)&lp1;
    *(uint2*)(hi_s + off) = hw;
    *(uint2*)(lo_s + off) = lw;
}

__device__ __forceinline__ void gemm_body_tc(
    const float* __restrict__ A, const float* __restrict__ W,
    const float* __restrict__ bias, float* __restrict__ C,
    int K, int N)
{
    __shared__ __align__(16) __nv_bfloat16 Ah_s[TBM * ASTR];
    __shared__ __align__(16) __nv_bfloat16 Al_s[TBM * ASTR];
    __shared__ __align__(16) __nv_bfloat16 Bh_s[TBN * ASTR];
    __shared__ __align__(16) __nv_bfloat16 Bl_s[TBN * ASTR];

    const int tid  = threadIdx.x;
    const int w    = tid >> 5;
    const int lane = tid & 31;
    const int g = lane >> 2, t = lane & 3;
    const int wm = w >> 2, wn = w & 3;       // warp grid 2(M) x 4(N)
    const int m0 = wm * 64, n0 = wn * 32;
    const int bm = blockIdx.y * TBM;
    const int bn = blockIdx.x * TBN;

    float acc[4][4][4];
#pragma unroll
    for (int mt = 0; mt < 4; mt++)
#pragma unroll
        for (int nt = 0; nt < 4; nt++)
#pragma unroll
            for (int u = 0; u < 4; u++) acc[mt][nt][u] = 0.f;

    const uint32_t* Ahw = (const uint32_t*)Ah_s;
    const uint32_t* Alw = (const uint32_t*)Al_s;
    const uint32_t* Bhw = (const uint32_t*)Bh_s;
    const uint32_t* Blw = (const uint32_t*)Bl_s;

    for (int k0 = 0; k0 < K; k0 += TBK) {
        __syncthreads();
        // stage A (128x32) and W (128x32), fp32 -> hi/lo bf16
#pragma unroll
        for (int it = 0; it < 4; it++) {
            int idx = it * 256 + tid;
            int row = idx >> 3, c4 = (idx & 7) << 2;
            float4 av = *(const float4*)(A + (size_t)(bm + row) * K + k0 + c4);
            split_store(Ah_s, Al_s, row * ASTR + c4, av);
            float4 wv = *(const float4*)(W + (size_t)(bn + row) * K + k0 + c4);
            split_store(Bh_s, Bl_s, row * ASTR + c4, wv);
        }
        __syncthreads();

#pragma unroll
        for (int ks = 0; ks < 2; ks++) {
            // B fragments for 4 n-tiles (hi + lo)
            uint32_t bh[4][2], bl[4][2];
#pragma unroll
            for (int nt = 0; nt < 4; nt++) {
                int wb = (n0 + nt * 8 + g) * (ASTR / 2) + ks * 8 + t;
                bh[nt][0] = Bhw[wb]; bh[nt][1] = Bhw[wb + 4];
                bl[nt][0] = Blw[wb]; bl[nt][1] = Blw[wb + 4];
            }
#pragma unroll
            for (int mt = 0; mt < 4; mt++) {
                int wa = (m0 + mt * 16 + g) * (ASTR / 2) + ks * 8 + t;
                uint32_t ah0 = Ahw[wa],       ah1 = Ahw[wa + 8 * (ASTR / 2)];
                uint32_t ah2 = Ahw[wa + 4],   ah3 = Ahw[wa + 8 * (ASTR / 2) + 4];
                uint32_t al0 = Alw[wa],       al1 = Alw[wa + 8 * (ASTR / 2)];
                uint32_t al2 = Alw[wa + 4],   al3 = Alw[wa + 8 * (ASTR / 2) + 4];
#pragma unroll
                for (int nt = 0; nt < 4; nt++) {
                    mma_bf16(acc[mt][nt], ah0, ah1, ah2, ah3, bh[nt][0], bh[nt][1]);
                    mma_bf16(acc[mt][nt], ah0, ah1, ah2, ah3, bl[nt][0], bl[nt][1]);
                    mma_bf16(acc[mt][nt], al0, al1, al2, al3, bh[nt][0], bh[nt][1]);
                }
            }
        }
    }

    // epilogue: + bias, fp32 out
#pragma unroll
    for (int mt = 0; mt < 4; mt++) {
#pragma unroll
        for (int nt = 0; nt < 4; nt++) {
            int r = bm + m0 + mt * 16 + g;
            int c = bn + n0 + nt * 8 + 2 * t;
            float bx = bias[c], by = bias[c + 1];
            float2 v0 = make_float2(acc[mt][nt][0] + bx, acc[mt][nt][1] + by);
            float2 v1 = make_float2(acc[mt][nt][2] + bx, acc[mt][nt][3] + by);
            *(float2*)(C + (size_t)r * N + c) = v0;
            *(float2*)(C + (size_t)(r + 8) * N + c) = v1;
        }
    }
}

__global__ void __launch_bounds__(256, 2)
qkv_gemm_kernel(const float* __restrict__ q, const float* __restrict__ k,
                const float* __restrict__ v, const float* __restrict__ W,
                const float* __restrict__ bias)
{
    int z = blockIdx.z;
    const float* A = (z == 0) ? q : (z == 1) ? k : v;
    gemm_body_tc(A, W + (size_t)z * HDIM * HDIM, bias + z * HDIM,
                 g_qkv + (size_t)z * ROWS * HDIM, HDIM, HDIM);
}

__global__ void __launch_bounds__(256, 2)
outproj_kernel(const float* __restrict__ W, const float* __restrict__ bias,
               float* __restrict__ out)
{
    gemm_body_tc(g_attn, W, bias, out, HDIM, HDIM);
}

// ============================================================================
// TF32 tensor-core flash attention (unchanged from round 4, validated).
// ============================================================================
#define QB 128
#define KB 64
#define PADK 68
#define PADV 72
#define PADP 68
#define PADB 132

__device__ __forceinline__ uint32_t f2tf32(float f) {
    uint32_t r;
    asm("cvt.rna.tf32.f32 %0, %1;" : "=r"(r) : "f"(f));
    return r;
}

__device__ __forceinline__ void mma_tf32(float c[4],
    uint32_t a0, uint32_t a1, uint32_t a2, uint32_t a3,
    uint32_t b0, uint32_t b1)
{
    asm volatile(
        "mma.sync.aligned.m16n8k8.row.col.f32.tf32.tf32.f32 "
        "{%0,%1,%2,%3}, {%4,%5,%6,%7}, {%8,%9}, {%0,%1,%2,%3};"
        : "+f"(c[0]), "+f"(c[1]), "+f"(c[2]), "+f"(c[3])
        : "r"(a0), "r"(a1), "r"(a2), "r"(a3), "r"(b0), "r"(b1));
}

__global__ void __launch_bounds__(256, 2)
attn_mma_kernel(const float* __restrict__ kern,
                const unsigned int* __restrict__ amask, float scale)
{
    extern __shared__ float sm[];
    float* Ks  = sm;
    float* Vs  = Ks + KB * PADK;
    float* Ps  = Vs + KB * PADV;
    float* Bbs = Ps + QB * PADP;
    unsigned char* Msk = (unsigned char*)(Bbs + KB * PADB);

    const int bh = blockIdx.y, b = bh >> 3, h = bh & 7;
    const int qb = blockIdx.x * QB;
    const int tid  = threadIdx.x;
    const int w    = tid >> 5;
    const int lane = tid & 31;
    const int g = lane >> 2, t = lane & 3;

    const float* Qg = g_qkv + (size_t)b * SEQ * HDIM + h * DHEAD;
    const float* Kg = g_qkv + (size_t)ROWS * HDIM + (size_t)b * SEQ * HDIM + h * DHEAD;
    const float* Vg = g_qkv + (size_t)2 * ROWS * HDIM + (size_t)b * SEQ * HDIM + h * DHEAD;

#pragma unroll
    for (int it = 0; it < 8; it++) {
        int lin = (it * 256 + tid) * 4;
        int r = lin >> 6, c = lin & 63;
        float4 v = *(const float4*)(Qg + (size_t)(qb + r) * HDIM + c);
        v.x = __uint_as_float(f2tf32(v.x)); v.y = __uint_as_float(f2tf32(v.y));
        v.z = __uint_as_float(f2tf32(v.z)); v.w = __uint_as_float(f2tf32(v.w));
        *(float4*)&Ps[r * PADP + c] = v;
    }
    __syncthreads();

    uint32_t qa[8][4];
    const int qr = w * 16 + g;
#pragma unroll
    for (int k = 0; k < 8; k++) {
        qa[k][0] = __float_as_uint(Ps[qr * PADP + k * 8 + t]);
        qa[k][1] = __float_as_uint(Ps[(qr + 8) * PADP + k * 8 + t]);
        qa[k][2] = __float_as_uint(Ps[qr * PADP + k * 8 + t + 4]);
        qa[k][3] = __float_as_uint(Ps[(qr + 8) * PADP + k * 8 + t + 4]);
    }

    float o[8][4];
#pragma unroll
    for (int f = 0; f < 8; f++)
#pragma unroll
        for (int u = 0; u < 4; u++) o[f][u] = 0.f;
    float m_[2] = {-1e30f, -1e30f}, l_[2] = {0.f, 0.f};

    for (int kb = 0; kb < 16; kb++) {
        __syncthreads();
#pragma unroll
        for (int it = 0; it < 4; it++) {
            int lin = (it * 256 + tid) * 4;
            int r = lin >> 6, c = lin & 63;
            float4 kv = *(const float4*)(Kg + (size_t)(kb * KB + r) * HDIM + c);
            kv.x = __uint_as_float(f2tf32(kv.x)); kv.y = __uint_as_float(f2tf32(kv.y));
            kv.z = __uint_as_float(f2tf32(kv.z)); kv.w = __uint_as_float(f2tf32(kv.w));
            *(float4*)&Ks[r * PADK + c] = kv;
            float4 vv = *(const float4*)(Vg + (size_t)(kb * KB + r) * HDIM + c);
            vv.x = __uint_as_float(f2tf32(vv.x)); vv.y = __uint_as_float(f2tf32(vv.y));
            vv.z = __uint_as_float(f2tf32(vv.z)); vv.w = __uint_as_float(f2tf32(vv.w));
            *(float4*)&Vs[r * PADV + c] = vv;
        }
#pragma unroll
        for (int it = 0; it < 8; it++) {
            int lin = (it * 256 + tid) * 4;
            int kr = lin >> 7, qc = lin & 127;
            float4 bb = *(const float4*)(kern +
                ((size_t)bh * SEQ + kb * KB + kr) * SEQ + qb + qc);
            *(float4*)&Bbs[kr * PADB + qc] = bb;
        }
#pragma unroll
        for (int it = 0; it < 8; it++) {
            int widx = it * 256 + tid;
            int lin = widx * 4;
            int r = lin >> 6, c = lin & 63;
            uint4 mw = *(const uint4*)(amask +
                ((size_t)bh * SEQ + qb + r) * SEQ + kb * KB + c);
            unsigned pk = (mw.x ? 1u : 0u) | (mw.y ? 0x100u : 0u) |
                          (mw.z ? 0x10000u : 0u) | (mw.w ? 0x1000000u : 0u);
            ((unsigned*)Msk)[widx] = pk;
        }
        __syncthreads();

        float sc[8][4];
#pragma unroll
        for (int f = 0; f < 8; f++)
#pragma unroll
            for (int u = 0; u < 4; u++) sc[f][u] = 0.f;
#pragma unroll
        for (int k = 0; k < 8; k++) {
#pragma unroll
            for (int f = 0; f < 8; f++) {
                uint32_t b0 = __float_as_uint(Ks[(f * 8 + g) * PADK + k * 8 + t]);
                uint32_t b1 = __float_as_uint(Ks[(f * 8 + g) * PADK + k * 8 + t + 4]);
                mma_tf32(sc[f], qa[k][0], qa[k][1], qa[k][2], qa[k][3], b0, b1);
            }
        }

#pragma unroll
        for (int e = 0; e < 2; e++) {
            const int qrl = w * 16 + g + e * 8;
            float rmax = -1e30f;
#pragma unroll
            for (int f = 0; f < 8; f++) {
#pragma unroll
                for (int u = 0; u < 2; u++) {
                    int kc = f * 8 + 2 * t + u;
                    float s = sc[f][e * 2 + u] * scale + Bbs[kc * PADB + qrl];
                    s = Msk[qrl * KB + kc] ? -1e30f : s;
                    sc[f][e * 2 + u] = s;
                    rmax = fmaxf(rmax, s);
                }
            }
            rmax = fmaxf(rmax, __shfl_xor_sync(0xffffffffu, rmax, 1));
            rmax = fmaxf(rmax, __shfl_xor_sync(0xffffffffu, rmax, 2));
            float mn = fmaxf(m_[e], rmax);
            float fe = __expf(m_[e] - mn);
            float ps = 0.f;
#pragma unroll
            for (int f = 0; f < 8; f++) {
#pragma unroll
                for (int u = 0; u < 2; u++) {
                    float sv = sc[f][e * 2 + u];
                    float p = (sv <= -1e29f) ? 0.f : __expf(sv - mn);
                    sc[f][e * 2 + u] = p;
                    ps += p;
                }
            }
            ps += __shfl_xor_sync(0xffffffffu, ps, 1);
            ps += __shfl_xor_sync(0xffffffffu, ps, 2);
            l_[e] = l_[e] * fe + ps;
            m_[e] = mn;
#pragma unroll
            for (int f = 0; f < 8; f++) {
                o[f][e * 2 + 0] *= fe;
                o[f][e * 2 + 1] *= fe;
            }
#pragma unroll
            for (int f = 0; f < 8; f++) {
                float2 pv;
                pv.x = __uint_as_float(f2tf32(sc[f][e * 2 + 0]));
                pv.y = __uint_as_float(f2tf32(sc[f][e * 2 + 1]));
                *(float2*)&Ps[qrl * PADP + f * 8 + 2 * t] = pv;
            }
        }
        __syncwarp();

#pragma unroll
        for (int k = 0; k < 8; k++) {
            uint32_t a0 = __float_as_uint(Ps[(w * 16 + g) * PADP + k * 8 + t]);
            uint32_t a1 = __float_as_uint(Ps[(w * 16 + g + 8) * PADP + k * 8 + t]);
            uint32_t a2 = __float_as_uint(Ps[(w * 16 + g) * PADP + k * 8 + t + 4]);
            uint32_t a3 = __float_as_uint(Ps[(w * 16 + g + 8) * PADP + k * 8 + t + 4]);
#pragma unroll
            for (int f = 0; f < 8; f++) {
                uint32_t b0 = __float_as_uint(Vs[(k * 8 + t) * PADV + f * 8 + g]);
                uint32_t b1 = __float_as_uint(Vs[(k * 8 + t + 4) * PADV + f * 8 + g]);
                mma_tf32(o[f], a0, a1, a2, a3, b0, b1);
            }
        }
    }

    float* Og = g_attn + ((size_t)b * SEQ + qb) * HDIM + h * DHEAD;
#pragma unroll
    for (int e = 0; e < 2; e++) {
        float inv = 1.0f / l_[e];
        int qrl = w * 16 + g + e * 8;
#pragma unroll
        for (int f = 0; f < 8; f++) {
            float2 ov;
            ov.x = o[f][e * 2 + 0] * inv;
            ov.y = o[f][e * 2 + 1] * inv;
            *(float2*)(Og + (size_t)qrl * HDIM + f * 8 + 2 * t) = ov;
        }
    }
}

// ============================================================================
// Launch
// ============================================================================
extern "C" void kernel_launch(void* const* d_in, const int* in_sizes, int n_in,
                              void* d_out, int out_size)
{
    const float* query        = (const float*)d_in[0];
    const float* key_         = (const float*)d_in[1];
    const float* value        = (const float*)d_in[2];
    const unsigned int* amask = (const unsigned int*)d_in[3];
    const float* kern         = (const float*)d_in[5];
    const float* ipw          = (const float*)d_in[6];
    const float* ipb          = (const float*)d_in[7];
    const float* outw         = (const float*)d_in[8];
    const float* outb         = (const float*)d_in[9];
    float* out = (float*)d_out;

    const int attn_smem =
        (KB * PADK + KB * PADV + QB * PADP + KB * PADB) * (int)sizeof(float)
        + QB * KB;
    cudaFuncSetAttribute(attn_mma_kernel,
                         cudaFuncAttributeMaxDynamicSharedMemorySize, attn_smem);

    dim3 gq(HDIM / TBN, ROWS / TBM, 3);
    qkv_gemm_kernel<<<gq, 256>>>(query, key_, value, ipw, ipb);

    dim3 ga(SEQ / QB, BATCH * NHEAD, 1);
    attn_mma_kernel<<<ga, 256, attn_smem>>>(kern, amask, 0.125f);

    dim3 go(HDIM / TBN, ROWS / TBM, 1);
    outproj_kernel<<<go, 256>>>(outw, outb, out);
}

// round 7
// speedup vs baseline: 3.0069x; 1.1479x over previous
#include <cuda_runtime.h>
#include <cuda_bf16.h>
#include <cstdint>

// ----------------------------------------------------------------------------
// PositionAttention: B=4, L=1024, HD=512, H=8, D=64
// Round 6: attention -> 2-stage cp.async pipeline (KB=32), shuffle P-transpose,
// no P smem, direct Q fragment loads. GEMMs unchanged (bf16x3).
// ----------------------------------------------------------------------------

#define BATCH 4
#define SEQ   1024
#define HDIM  512
#define NHEAD 8
#define DHEAD 64
#define ROWS  (BATCH*SEQ)          // 4096

__device__ float g_qkv[3u * ROWS * HDIM];   // [z][row][hd]
__device__ float g_attn[ROWS * HDIM];       // attention output pre-projection

// ============================================================================
// bf16x3 tensor-core GEMM (unchanged, validated): C = A[MxK] @ W[NxK]^T + bias
// ============================================================================
#define TBM 128
#define TBN 128
#define TBK 32
#define ASTR 40

__device__ __forceinline__ void mma_bf16(float c[4],
    uint32_t a0, uint32_t a1, uint32_t a2, uint32_t a3,
    uint32_t b0, uint32_t b1)
{
    asm volatile(
        "mma.sync.aligned.m16n8k16.row.col.f32.bf16.bf16.f32 "
        "{%0,%1,%2,%3}, {%4,%5,%6,%7}, {%8,%9}, {%0,%1,%2,%3};"
        : "+f"(c[0]), "+f"(c[1]), "+f"(c[2]), "+f"(c[3])
        : "r"(a0), "r"(a1), "r"(a2), "r"(a3), "r"(b0), "r"(b1));
}

__device__ __forceinline__ void split_store(
    __nv_bfloat16* hi_s, __nv_bfloat16* lo_s, int off, float4 v)
{
    __nv_bfloat16 h0 = __float2bfloat16_rn(v.x);
    __nv_bfloat16 h1 = __float2bfloat16_rn(v.y);
    __nv_bfloat16 h2 = __float2bfloat16_rn(v.z);
    __nv_bfloat16 h3 = __float2bfloat16_rn(v.w);
    __nv_bfloat16 l0 = __float2bfloat16_rn(v.x - __bfloat162float(h0));
    __nv_bfloat16 l1 = __float2bfloat16_rn(v.y - __bfloat162float(h1));
    __nv_bfloat16 l2 = __float2bfloat16_rn(v.z - __bfloat162float(h2));
    __nv_bfloat16 l3 = __float2bfloat16_rn(v.w - __bfloat162float(h3));
    __nv_bfloat162 hp0(h0, h1), hp1(h2, h3), lp0(l0, l1), lp1(l2, l3);
    uint2 hw, lw;
    hw.x = *(uint32_t*)&hp0; hw.y = *(uint32_t*)&hp1;
    lw.x = *(uint32_t*)&lp0; lw.y = *(uint32_t*)&lp1;
    *(uint2*)(hi_s + off) = hw;
    *(uint2*)(lo_s + off) = lw;
}

__device__ __forceinline__ void gemm_body_tc(
    const float* __restrict__ A, const float* __restrict__ W,
    const float* __restrict__ bias, float* __restrict__ C,
    int K, int N)
{
    __shared__ __align__(16) __nv_bfloat16 Ah_s[TBM * ASTR];
    __shared__ __align__(16) __nv_bfloat16 Al_s[TBM * ASTR];
    __shared__ __align__(16) __nv_bfloat16 Bh_s[TBN * ASTR];
    __shared__ __align__(16) __nv_bfloat16 Bl_s[TBN * ASTR];

    const int tid  = threadIdx.x;
    const int w    = tid >> 5;
    const int lane = tid & 31;
    const int g = lane >> 2, t = lane & 3;
    const int wm = w >> 2, wn = w & 3;
    const int m0 = wm * 64, n0 = wn * 32;
    const int bm = blockIdx.y * TBM;
    const int bn = blockIdx.x * TBN;

    float acc[4][4][4];
#pragma unroll
    for (int mt = 0; mt < 4; mt++)
#pragma unroll
        for (int nt = 0; nt < 4; nt++)
#pragma unroll
            for (int u = 0; u < 4; u++) acc[mt][nt][u] = 0.f;

    const uint32_t* Ahw = (const uint32_t*)Ah_s;
    const uint32_t* Alw = (const uint32_t*)Al_s;
    const uint32_t* Bhw = (const uint32_t*)Bh_s;
    const uint32_t* Blw = (const uint32_t*)Bl_s;

    for (int k0 = 0; k0 < K; k0 += TBK) {
        __syncthreads();
#pragma unroll
        for (int it = 0; it < 4; it++) {
            int idx = it * 256 + tid;
            int row = idx >> 3, c4 = (idx & 7) << 2;
            float4 av = *(const float4*)(A + (size_t)(bm + row) * K + k0 + c4);
            split_store(Ah_s, Al_s, row * ASTR + c4, av);
            float4 wv = *(const float4*)(W + (size_t)(bn + row) * K + k0 + c4);
            split_store(Bh_s, Bl_s, row * ASTR + c4, wv);
        }
        __syncthreads();

#pragma unroll
        for (int ks = 0; ks < 2; ks++) {
            uint32_t bh[4][2], bl[4][2];
#pragma unroll
            for (int nt = 0; nt < 4; nt++) {
                int wb = (n0 + nt * 8 + g) * (ASTR / 2) + ks * 8 + t;
                bh[nt][0] = Bhw[wb]; bh[nt][1] = Bhw[wb + 4];
                bl[nt][0] = Blw[wb]; bl[nt][1] = Blw[wb + 4];
            }
#pragma unroll
            for (int mt = 0; mt < 4; mt++) {
                int wa = (m0 + mt * 16 + g) * (ASTR / 2) + ks * 8 + t;
                uint32_t ah0 = Ahw[wa],     ah1 = Ahw[wa + 8 * (ASTR / 2)];
                uint32_t ah2 = Ahw[wa + 4], ah3 = Ahw[wa + 8 * (ASTR / 2) + 4];
                uint32_t al0 = Alw[wa],     al1 = Alw[wa + 8 * (ASTR / 2)];
                uint32_t al2 = Alw[wa + 4], al3 = Alw[wa + 8 * (ASTR / 2) + 4];
#pragma unroll
                for (int nt = 0; nt < 4; nt++) {
                    mma_bf16(acc[mt][nt], ah0, ah1, ah2, ah3, bh[nt][0], bh[nt][1]);
                    mma_bf16(acc[mt][nt], ah0, ah1, ah2, ah3, bl[nt][0], bl[nt][1]);
                    mma_bf16(acc[mt][nt], al0, al1, al2, al3, bh[nt][0], bh[nt][1]);
                }
            }
        }
    }

#pragma unroll
    for (int mt = 0; mt < 4; mt++) {
#pragma unroll
        for (int nt = 0; nt < 4; nt++) {
            int r = bm + m0 + mt * 16 + g;
            int c = bn + n0 + nt * 8 + 2 * t;
            float bx = bias[c], by = bias[c + 1];
            float2 v0 = make_float2(acc[mt][nt][0] + bx, acc[mt][nt][1] + by);
            float2 v1 = make_float2(acc[mt][nt][2] + bx, acc[mt][nt][3] + by);
            *(float2*)(C + (size_t)r * N + c) = v0;
            *(float2*)(C + (size_t)(r + 8) * N + c) = v1;
        }
    }
}

__global__ void __launch_bounds__(256, 2)
qkv_gemm_kernel(const float* __restrict__ q, const float* __restrict__ k,
                const float* __restrict__ v, const float* __restrict__ W,
                const float* __restrict__ bias)
{
    int z = blockIdx.z;
    const float* A = (z == 0) ? q : (z == 1) ? k : v;
    gemm_body_tc(A, W + (size_t)z * HDIM * HDIM, bias + z * HDIM,
                 g_qkv + (size_t)z * ROWS * HDIM, HDIM, HDIM);
}

__global__ void __launch_bounds__(256, 2)
outproj_kernel(const float* __restrict__ W, const float* __restrict__ bias,
               float* __restrict__ out)
{
    gemm_body_tc(g_attn, W, bias, out, HDIM, HDIM);
}

// ============================================================================
// TF32 flash attention, 2-stage cp.async pipeline.
// Block: QB=128 q-rows; 32 key-tiles of KB=32. 8 warps, warp = 16 q-rows.
// Stage layout (fp32 words): K[32x68] | V[32x72] | bias[32x132] | mask[128x40]
// ============================================================================
#define QB 128
#define KB 32
#define PADK 68
#define PADV 72
#define PADB 132
#define PADM 40
#define ST_K 0
#define ST_V (KB*PADK)                         // 2176
#define ST_B (ST_V + KB*PADV)                  // 4480
#define ST_M (ST_B + KB*PADB)                  // 8704
#define ST_WORDS (ST_M + QB*PADM)              // 13824 words per stage
#define ATTN_SMEM (2 * ST_WORDS * 4)           // 110592 bytes

__device__ __forceinline__ uint32_t f2tf32(float f) {
    uint32_t r;
    asm("cvt.rna.tf32.f32 %0, %1;" : "=r"(r) : "f"(f));
    return r;
}

__device__ __forceinline__ void mma_tf32(float c[4],
    uint32_t a0, uint32_t a1, uint32_t a2, uint32_t a3,
    uint32_t b0, uint32_t b1)
{
    asm volatile(
        "mma.sync.aligned.m16n8k8.row.col.f32.tf32.tf32.f32 "
        "{%0,%1,%2,%3}, {%4,%5,%6,%7}, {%8,%9}, {%0,%1,%2,%3};"
        : "+f"(c[0]), "+f"(c[1]), "+f"(c[2]), "+f"(c[3])
        : "r"(a0), "r"(a1), "r"(a2), "r"(a3), "r"(b0), "r"(b1));
}

__device__ __forceinline__ void cp16(uint32_t dst, const void* src) {
    asm volatile("cp.async.cg.shared.global [%0], [%1], 16;"
                 :: "r"(dst), "l"(src));
}

__device__ __forceinline__ void stage_tile(
    uint32_t sbase, int s, int kb,
    const float* Kg, const float* Vg,
    const float* kern_bh, const uint32_t* mask_bh, int qb, int tid)
{
    const uint32_t kbase = sbase + (uint32_t)(s * ST_WORDS) * 4u;
    const uint32_t vbase = kbase + ST_V * 4u;
    const uint32_t bbase = kbase + ST_B * 4u;
    const uint32_t mbase = kbase + ST_M * 4u;
    // K, V: 32 rows x 64 floats (16 chunks/row), 512 chunks each
#pragma unroll
    for (int it = 0; it < 2; it++) {
        int idx = it * 256 + tid;
        int r = idx >> 4, c4 = (idx & 15) << 2;
        cp16(kbase + (uint32_t)(r * PADK + c4) * 4u,
             Kg + (size_t)(kb * KB + r) * HDIM + c4);
        cp16(vbase + (uint32_t)(r * PADV + c4) * 4u,
             Vg + (size_t)(kb * KB + r) * HDIM + c4);
    }
    // bias: 32 k-rows x 128 q floats (32 chunks/row), 1024 chunks
#pragma unroll
    for (int it = 0; it < 4; it++) {
        int idx = it * 256 + tid;
        int r = idx >> 5, q4 = (idx & 31) << 2;
        cp16(bbase + (uint32_t)(r * PADB + q4) * 4u,
             kern_bh + (size_t)(kb * KB + r) * SEQ + qb + q4);
    }
    // mask: 128 q-rows x 32 u32 (8 chunks/row), 1024 chunks
#pragma unroll
    for (int it = 0; it < 4; it++) {
        int idx = it * 256 + tid;
        int r = idx >> 3, k4 = (idx & 7) << 2;
        cp16(mbase + (uint32_t)(r * PADM + k4) * 4u,
             mask_bh + (size_t)(qb + r) * SEQ + kb * KB + k4);
    }
}

__global__ void __launch_bounds__(256, 2)
attn_mma_kernel(const float* __restrict__ kern,
                const uint32_t* __restrict__ amask, float scale)
{
    extern __shared__ float sm[];
    const uint32_t sbase = (uint32_t)__cvta_generic_to_shared(sm);

    const int bh = blockIdx.y, b = bh >> 3, h = bh & 7;
    const int qb = blockIdx.x * QB;
    const int tid  = threadIdx.x;
    const int w    = tid >> 5;
    const int lane = tid & 31;
    const int g = lane >> 2, t = lane & 3;

    const float* Qg = g_qkv + (size_t)b * SEQ * HDIM + h * DHEAD;
    const float* Kg = g_qkv + (size_t)ROWS * HDIM + (size_t)b * SEQ * HDIM + h * DHEAD;
    const float* Vg = g_qkv + 2 * (size_t)ROWS * HDIM + (size_t)b * SEQ * HDIM + h * DHEAD;
    const float* kern_bh = kern + (size_t)bh * SEQ * SEQ;
    const uint32_t* mask_bh = amask + (size_t)bh * SEQ * SEQ;

    // prologue prefetch (stage 0, kb=0)
    stage_tile(sbase, 0, 0, Kg, Vg, kern_bh, mask_bh, qb, tid);
    asm volatile("cp.async.commit_group;");

    // Q fragments straight from gmem (RN tf32), held for all 32 tiles
    uint32_t qa[8][4];
    {
        const float* Qr0 = Qg + (size_t)(qb + w * 16 + g) * HDIM;
        const float* Qr1 = Qr0 + 8 * (size_t)HDIM;
#pragma unroll
        for (int k = 0; k < 8; k++) {
            qa[k][0] = f2tf32(Qr0[k * 8 + t]);
            qa[k][1] = f2tf32(Qr1[k * 8 + t]);
            qa[k][2] = f2tf32(Qr0[k * 8 + t + 4]);
            qa[k][3] = f2tf32(Qr1[k * 8 + t + 4]);
        }
    }

    float o[8][4];
#pragma unroll
    for (int f = 0; f < 8; f++)
#pragma unroll
        for (int u = 0; u < 4; u++) o[f][u] = 0.f;
    float m_[2] = {-1e30f, -1e30f}, l_[2] = {0.f, 0.f};

    for (int kb = 0; kb < SEQ / KB; kb++) {
        const int s = kb & 1;
        if (kb < SEQ / KB - 1) {
            stage_tile(sbase, s ^ 1, kb + 1, Kg, Vg, kern_bh, mask_bh, qb, tid);
            asm volatile("cp.async.commit_group;");
            asm volatile("cp.async.wait_group 1;");
        } else {
            asm volatile("cp.async.wait_group 0;");
        }
        __syncthreads();

        const float* Ks = sm + s * ST_WORDS;
        const float* Vs = Ks + ST_V;
        const float* Bs = Ks + ST_B;
        const uint32_t* Ms = (const uint32_t*)(Ks + ST_M);

        // ---- S = Q K^T : 16 rows x 32 cols per warp ----
        float sc[4][4];
#pragma unroll
        for (int f = 0; f < 4; f++)
#pragma unroll
            for (int u = 0; u < 4; u++) sc[f][u] = 0.f;
#pragma unroll
        for (int k = 0; k < 8; k++) {
#pragma unroll
            for (int f = 0; f < 4; f++) {
                uint32_t b0 = __float_as_uint(Ks[(f * 8 + g) * PADK + k * 8 + t]);
                uint32_t b1 = __float_as_uint(Ks[(f * 8 + g) * PADK + k * 8 + t + 4]);
                mma_tf32(sc[f], qa[k][0], qa[k][1], qa[k][2], qa[k][3], b0, b1);
            }
        }

        // ---- scale + bias(kernel^T) + mask + online softmax ----
#pragma unroll
        for (int e = 0; e < 2; e++) {
            const int qrl = w * 16 + g + e * 8;
            float rmax = -1e30f;
#pragma unroll
            for (int f = 0; f < 4; f++) {
#pragma unroll
                for (int u = 0; u < 2; u++) {
                    int kc = f * 8 + 2 * t + u;
                    float sv = sc[f][e * 2 + u] * scale + Bs[kc * PADB + qrl];
                    sv = Ms[qrl * PADM + kc] ? -1e30f : sv;
                    sc[f][e * 2 + u] = sv;
                    rmax = fmaxf(rmax, sv);
                }
            }
            rmax = fmaxf(rmax, __shfl_xor_sync(0xffffffffu, rmax, 1));
            rmax = fmaxf(rmax, __shfl_xor_sync(0xffffffffu, rmax, 2));
            float mn = fmaxf(m_[e], rmax);
            float fe = __expf(m_[e] - mn);
            float ps = 0.f;
#pragma unroll
            for (int f = 0; f < 4; f++) {
#pragma unroll
                for (int u = 0; u < 2; u++) {
                    float sv = sc[f][e * 2 + u];
                    float p = (sv <= -1e29f) ? 0.f : __expf(sv - mn);
                    sc[f][e * 2 + u] = p;
                    ps += p;
                }
            }
            ps += __shfl_xor_sync(0xffffffffu, ps, 1);
            ps += __shfl_xor_sync(0xffffffffu, ps, 2);
            l_[e] = l_[e] * fe + ps;
            m_[e] = mn;
#pragma unroll
            for (int f = 0; f < 4; f++) {
                o[2 * f][e * 2 + 0] *= fe;   o[2 * f][e * 2 + 1] *= fe;
                o[2 * f + 1][e * 2 + 0] *= fe; o[2 * f + 1][e * 2 + 1] *= fe;
            }
        }

        // ---- O += P @ V : C-frag -> A-frag transpose via shuffles ----
#pragma unroll
        for (int kk = 0; kk < 4; kk++) {
            const int src = g * 4 + (t >> 1);
            float p00 = __shfl_sync(0xffffffffu, sc[kk][0], src);
            float p01 = __shfl_sync(0xffffffffu, sc[kk][1], src);
            float p02 = __shfl_sync(0xffffffffu, sc[kk][0], src + 2);
            float p03 = __shfl_sync(0xffffffffu, sc[kk][1], src + 2);
            float p10 = __shfl_sync(0xffffffffu, sc[kk][2], src);
            float p11 = __shfl_sync(0xffffffffu, sc[kk][3], src);
            float p12 = __shfl_sync(0xffffffffu, sc[kk][2], src + 2);
            float p13 = __shfl_sync(0xffffffffu, sc[kk][3], src + 2);
            const bool odd = (t & 1);
            uint32_t a0 = f2tf32(odd ? p01 : p00);
            uint32_t a1 = f2tf32(odd ? p11 : p10);
            uint32_t a2 = f2tf32(odd ? p03 : p02);
            uint32_t a3 = f2tf32(odd ? p13 : p12);
#pragma unroll
            for (int f = 0; f < 8; f++) {
                uint32_t b0 = __float_as_uint(Vs[(kk * 8 + t) * PADV + f * 8 + g]);
                uint32_t b1 = __float_as_uint(Vs[(kk * 8 + t + 4) * PADV + f * 8 + g]);
                mma_tf32(o[f], a0, a1, a2, a3, b0, b1);
            }
        }
        __syncthreads();   // all reads of stage s done before it is re-staged
    }

    // ---- normalize + write merged-head layout ----
    float* Og = g_attn + ((size_t)b * SEQ + qb) * HDIM + h * DHEAD;
#pragma unroll
    for (int e = 0; e < 2; e++) {
        float inv = 1.0f / l_[e];
        int qrl = w * 16 + g + e * 8;
#pragma unroll
        for (int f = 0; f < 8; f++) {
            float2 ov;
            ov.x = o[f][e * 2 + 0] * inv;
            ov.y = o[f][e * 2 + 1] * inv;
            *(float2*)(Og + (size_t)qrl * HDIM + f * 8 + 2 * t) = ov;
        }
    }
}

// ============================================================================
// Launch
// ============================================================================
extern "C" void kernel_launch(void* const* d_in, const int* in_sizes, int n_in,
                              void* d_out, int out_size)
{
    const float* query        = (const float*)d_in[0];
    const float* key_         = (const float*)d_in[1];
    const float* value        = (const float*)d_in[2];
    const uint32_t* amask     = (const uint32_t*)d_in[3];
    const float* kern         = (const float*)d_in[5];
    const float* ipw          = (const float*)d_in[6];
    const float* ipb          = (const float*)d_in[7];
    const float* outw         = (const float*)d_in[8];
    const float* outb         = (const float*)d_in[9];
    float* out = (float*)d_out;

    cudaFuncSetAttribute(attn_mma_kernel,
                         cudaFuncAttributeMaxDynamicSharedMemorySize, ATTN_SMEM);

    dim3 gq(HDIM / TBN, ROWS / TBM, 3);
    qkv_gemm_kernel<<<gq, 256>>>(query, key_, value, ipw, ipb);

    dim3 ga(SEQ / QB, BATCH * NHEAD, 1);
    attn_mma_kernel<<<ga, 256, ATTN_SMEM>>>(kern, amask, 0.125f);

    dim3 go(HDIM / TBN, ROWS / TBM, 1);
    outproj_kernel<<<go, 256>>>(outw, outb, out);
}

// round 8
// speedup vs baseline: 3.1586x; 1.0505x over previous
#include <cuda_runtime.h>
#include <cuda_bf16.h>
#include <cstdint>

// ----------------------------------------------------------------------------
// PositionAttention: B=4, L=1024, HD=512, H=8, D=64
// Round 8: GEMMs -> pre-split bf16 hi/lo operands + 2-stage cp.async pipeline
// (pure bf16x3 mainloop, no in-loop conversion). Attention mainloop unchanged;
// its epilogue now emits hi/lo bf16 directly for the out-projection.
// ----------------------------------------------------------------------------

#define BATCH 4
#define SEQ   1024
#define HDIM  512
#define NHEAD 8
#define DHEAD 64
#define ROWS  (BATCH*SEQ)          // 4096

// scratch (allocation-free: device globals)
__device__ float          g_qkv[3u * ROWS * HDIM];   // fp32 q/k/v for attention
__device__ __nv_bfloat16  g_inh[3u * ROWS * HDIM];   // split inputs (q,k,v src)
__device__ __nv_bfloat16  g_inl[3u * ROWS * HDIM];
__device__ __nv_bfloat16  g_wh[4u * HDIM * HDIM];    // [0..3HD*HD)=ipw, rest=outw
__device__ __nv_bfloat16  g_wl[4u * HDIM * HDIM];
__device__ __nv_bfloat16  g_ah[ROWS * HDIM];         // attention out hi
__device__ __nv_bfloat16  g_al[ROWS * HDIM];         // attention out lo

// ============================================================================
// fp32 -> (hi, lo) bf16 split, streaming
// ============================================================================
__device__ __forceinline__ void split4(float4 v, uint2& hw, uint2& lw)
{
    __nv_bfloat16 h0 = __float2bfloat16_rn(v.x);
    __nv_bfloat16 h1 = __float2bfloat16_rn(v.y);
    __nv_bfloat16 h2 = __float2bfloat16_rn(v.z);
    __nv_bfloat16 h3 = __float2bfloat16_rn(v.w);
    __nv_bfloat16 l0 = __float2bfloat16_rn(v.x - __bfloat162float(h0));
    __nv_bfloat16 l1 = __float2bfloat16_rn(v.y - __bfloat162float(h1));
    __nv_bfloat16 l2 = __float2bfloat16_rn(v.z - __bfloat162float(h2));
    __nv_bfloat16 l3 = __float2bfloat16_rn(v.w - __bfloat162float(h3));
    __nv_bfloat162 hp0(h0, h1), hp1(h2, h3), lp0(l0, l1), lp1(l2, l3);
    hw.x = *(uint32_t*)&hp0; hw.y = *(uint32_t*)&hp1;
    lw.x = *(uint32_t*)&lp0; lw.y = *(uint32_t*)&lp1;
}

__global__ void __launch_bounds__(256)
split_kernel(const float* __restrict__ in, __nv_bfloat16* __restrict__ hi,
             __nv_bfloat16* __restrict__ lo, int n4)
{
    int i = blockIdx.x * 256 + threadIdx.x;
    if (i >= n4) return;
    uint2 hw, lw;
    split4(((const float4*)in)[i], hw, lw);
    ((uint2*)hi)[i] = hw;
    ((uint2*)lo)[i] = lw;
}

// ============================================================================
// Pure-bf16x3 tensor-core GEMM, 2-stage cp.async.
// C[MxN] = (Ah+Al)[MxK] @ (Bh+Bl)[NxK]^T + bias   (3 terms: hh, hl, lh)
// 128x128x32 block, 8 warps (2x4), warp tile 64x32, m16n8k16.
// Stage: Ah|Al|Bh|Bl, each 128 rows x 32 bf16, row stride 40 bf16.
// ============================================================================
#define TBM 128
#define TBN 128
#define TBK 32
#define RSTR 40                         // bf16 per smem row (20 words)
#define MATW (TBM * RSTR / 2)           // 2560 words per matrix
#define GSTW (4 * MATW)                 // 10240 words per stage
#define GEMM_SMEM (2 * GSTW * 4)        // 81920 bytes

__device__ __forceinline__ void mma_bf16(float c[4],
    uint32_t a0, uint32_t a1, uint32_t a2, uint32_t a3,
    uint32_t b0, uint32_t b1)
{
    asm volatile(
        "mma.sync.aligned.m16n8k16.row.col.f32.bf16.bf16.f32 "
        "{%0,%1,%2,%3}, {%4,%5,%6,%7}, {%8,%9}, {%0,%1,%2,%3};"
        : "+f"(c[0]), "+f"(c[1]), "+f"(c[2]), "+f"(c[3])
        : "r"(a0), "r"(a1), "r"(a2), "r"(a3), "r"(b0), "r"(b1));
}

__device__ __forceinline__ void cp16(uint32_t dst, const void* src) {
    asm volatile("cp.async.cg.shared.global [%0], [%1], 16;"
                 :: "r"(dst), "l"(src));
}

__device__ __forceinline__ void gemm_stage(
    uint32_t sbase, int s,
    const __nv_bfloat16* __restrict__ Ah, const __nv_bfloat16* __restrict__ Al,
    const __nv_bfloat16* __restrict__ Bh, const __nv_bfloat16* __restrict__ Bl,
    int bm, int bn, int k0, int K, int tid)
{
    const uint32_t base = sbase + (uint32_t)s * GSTW * 4u;
#pragma unroll
    for (int it = 0; it < 2; it++) {
        int idx = it * 256 + tid;
        int row = idx >> 2, c8 = (idx & 3) << 3;
        uint32_t off = (uint32_t)(row * RSTR + c8) * 2u;
        cp16(base + off,                  Ah + (size_t)(bm + row) * K + k0 + c8);
        cp16(base + MATW * 4u + off,      Al + (size_t)(bm + row) * K + k0 + c8);
        cp16(base + 2u * MATW * 4u + off, Bh + (size_t)(bn + row) * K + k0 + c8);
        cp16(base + 3u * MATW * 4u + off, Bl + (size_t)(bn + row) * K + k0 + c8);
    }
}

__device__ __forceinline__ void gemm_body_bf16(
    const __nv_bfloat16* __restrict__ Ah, const __nv_bfloat16* __restrict__ Al,
    const __nv_bfloat16* __restrict__ Bh, const __nv_bfloat16* __restrict__ Bl,
    const float* __restrict__ bias, float* __restrict__ C,
    int K, int N, uint32_t* smem)
{
    const int tid  = threadIdx.x;
    const int w    = tid >> 5;
    const int lane = tid & 31;
    const int g = lane >> 2, t = lane & 3;
    const int wm = w >> 2, wn = w & 3;
    const int m0 = wm * 64, n0 = wn * 32;
    const int bm = blockIdx.y * TBM;
    const int bn = blockIdx.x * TBN;
    const uint32_t sbase = (uint32_t)__cvta_generic_to_shared(smem);

    float acc[4][4][4];
#pragma unroll
    for (int mt = 0; mt < 4; mt++)
#pragma unroll
        for (int nt = 0; nt < 4; nt++)
#pragma unroll
            for (int u = 0; u < 4; u++) acc[mt][nt][u] = 0.f;

    gemm_stage(sbase, 0, Ah, Al, Bh, Bl, bm, bn, 0, K, tid);
    asm volatile("cp.async.commit_group;");

    const int NT = K / TBK;
    for (int kt = 0; kt < NT; kt++) {
        const int s = kt & 1;
        if (kt < NT - 1) {
            gemm_stage(sbase, s ^ 1, Ah, Al, Bh, Bl, bm, bn, (kt + 1) * TBK, K, tid);
            asm volatile("cp.async.commit_group;");
            asm volatile("cp.async.wait_group 1;");
        } else {
            asm volatile("cp.async.wait_group 0;");
        }
        __syncthreads();

        const uint32_t* Sw  = smem + s * GSTW;
        const uint32_t* AhW = Sw;
        const uint32_t* AlW = Sw + MATW;
        const uint32_t* BhW = Sw + 2 * MATW;
        const uint32_t* BlW = Sw + 3 * MATW;

#pragma unroll
        for (int ks = 0; ks < 2; ks++) {
            uint32_t bh[4][2], bl[4][2];
#pragma unroll
            for (int nt = 0; nt < 4; nt++) {
                int wb = (n0 + nt * 8 + g) * (RSTR / 2) + ks * 8 + t;
                bh[nt][0] = BhW[wb]; bh[nt][1] = BhW[wb + 4];
                bl[nt][0] = BlW[wb]; bl[nt][1] = BlW[wb + 4];
            }
#pragma unroll
            for (int mt = 0; mt < 4; mt++) {
                int wa = (m0 + mt * 16 + g) * (RSTR / 2) + ks * 8 + t;
                uint32_t ah0 = AhW[wa],     ah1 = AhW[wa + 8 * (RSTR / 2)];
                uint32_t ah2 = AhW[wa + 4], ah3 = AhW[wa + 8 * (RSTR / 2) + 4];
                uint32_t al0 = AlW[wa],     al1 = AlW[wa + 8 * (RSTR / 2)];
                uint32_t al2 = AlW[wa + 4], al3 = AlW[wa + 8 * (RSTR / 2) + 4];
#pragma unroll
                for (int nt = 0; nt < 4; nt++) {
                    mma_bf16(acc[mt][nt], ah0, ah1, ah2, ah3, bh[nt][0], bh[nt][1]);
                    mma_bf16(acc[mt][nt], ah0, ah1, ah2, ah3, bl[nt][0], bl[nt][1]);
                    mma_bf16(acc[mt][nt], al0, al1, al2, al3, bh[nt][0], bh[nt][1]);
                }
            }
        }
        __syncthreads();   // reads done before this buffer is re-staged
    }

#pragma unroll
    for (int mt = 0; mt < 4; mt++) {
#pragma unroll
        for (int nt = 0; nt < 4; nt++) {
            int r = bm + m0 + mt * 16 + g;
            int c = bn + n0 + nt * 8 + 2 * t;
            float bx = bias[c], by = bias[c + 1];
            float2 v0 = make_float2(acc[mt][nt][0] + bx, acc[mt][nt][1] + by);
            float2 v1 = make_float2(acc[mt][nt][2] + bx, acc[mt][nt][3] + by);
            *(float2*)(C + (size_t)r * N + c) = v0;
            *(float2*)(C + (size_t)(r + 8) * N + c) = v1;
        }
    }
}

__global__ void __launch_bounds__(256, 2)
qkv_gemm_kernel(const float* __restrict__ ipb)
{
    extern __shared__ uint32_t smem_g[];
    const int z = blockIdx.z;
    gemm_body_bf16(g_inh + (size_t)z * ROWS * HDIM, g_inl + (size_t)z * ROWS * HDIM,
                   g_wh + (size_t)z * HDIM * HDIM,  g_wl + (size_t)z * HDIM * HDIM,
                   ipb + z * HDIM, g_qkv + (size_t)z * ROWS * HDIM,
                   HDIM, HDIM, smem_g);
}

__global__ void __launch_bounds__(256, 2)
outproj_kernel(const float* __restrict__ outb, float* __restrict__ out)
{
    extern __shared__ uint32_t smem_g[];
    gemm_body_bf16(g_ah, g_al,
                   g_wh + 3u * HDIM * HDIM, g_wl + 3u * HDIM * HDIM,
                   outb, out, HDIM, HDIM, smem_g);
}

// ============================================================================
// TF32 flash attention, 2-stage cp.async pipeline (mainloop unchanged,
// validated R6). Epilogue now writes hi/lo bf16 for the out-projection.
// ============================================================================
#define QB 128
#define KB 32
#define PADK 68
#define PADV 72
#define PADB 132
#define PADM 40
#define ST_V (KB*PADK)
#define ST_B (ST_V + KB*PADV)
#define ST_M (ST_B + KB*PADB)
#define ST_WORDS (ST_M + QB*PADM)
#define ATTN_SMEM (2 * ST_WORDS * 4)

__device__ __forceinline__ uint32_t f2tf32(float f) {
    uint32_t r;
    asm("cvt.rna.tf32.f32 %0, %1;" : "=r"(r) : "f"(f));
    return r;
}

__device__ __forceinline__ void mma_tf32(float c[4],
    uint32_t a0, uint32_t a1, uint32_t a2, uint32_t a3,
    uint32_t b0, uint32_t b1)
{
    asm volatile(
        "mma.sync.aligned.m16n8k8.row.col.f32.tf32.tf32.f32 "
        "{%0,%1,%2,%3}, {%4,%5,%6,%7}, {%8,%9}, {%0,%1,%2,%3};"
        : "+f"(c[0]), "+f"(c[1]), "+f"(c[2]), "+f"(c[3])
        : "r"(a0), "r"(a1), "r"(a2), "r"(a3), "r"(b0), "r"(b1));
}

__device__ __forceinline__ void stage_tile(
    uint32_t sbase, int s, int kb,
    const float* Kg, const float* Vg,
    const float* kern_bh, const uint32_t* mask_bh, int qb, int tid)
{
    const uint32_t kbase = sbase + (uint32_t)(s * ST_WORDS) * 4u;
    const uint32_t vbase = kbase + ST_V * 4u;
    const uint32_t bbase = kbase + ST_B * 4u;
    const uint32_t mbase = kbase + ST_M * 4u;
#pragma unroll
    for (int it = 0; it < 2; it++) {
        int idx = it * 256 + tid;
        int r = idx >> 4, c4 = (idx & 15) << 2;
        cp16(kbase + (uint32_t)(r * PADK + c4) * 4u,
             Kg + (size_t)(kb * KB + r) * HDIM + c4);
        cp16(vbase + (uint32_t)(r * PADV + c4) * 4u,
             Vg + (size_t)(kb * KB + r) * HDIM + c4);
    }
#pragma unroll
    for (int it = 0; it < 4; it++) {
        int idx = it * 256 + tid;
        int r = idx >> 5, q4 = (idx & 31) << 2;
        cp16(bbase + (uint32_t)(r * PADB + q4) * 4u,
             kern_bh + (size_t)(kb * KB + r) * SEQ + qb + q4);
    }
#pragma unroll
    for (int it = 0; it < 4; it++) {
        int idx = it * 256 + tid;
        int r = idx >> 3, k4 = (idx & 7) << 2;
        cp16(mbase + (uint32_t)(r * PADM + k4) * 4u,
             mask_bh + (size_t)(qb + r) * SEQ + kb * KB + k4);
    }
}

__global__ void __launch_bounds__(256, 2)
attn_mma_kernel(const float* __restrict__ kern,
                const uint32_t* __restrict__ amask, float scale)
{
    extern __shared__ float sm[];
    const uint32_t sbase = (uint32_t)__cvta_generic_to_shared(sm);

    const int bh = blockIdx.y, b = bh >> 3, h = bh & 7;
    const int qb = blockIdx.x * QB;
    const int tid  = threadIdx.x;
    const int w    = tid >> 5;
    const int lane = tid & 31;
    const int g = lane >> 2, t = lane & 3;

    const float* Qg = g_qkv + (size_t)b * SEQ * HDIM + h * DHEAD;
    const float* Kg = g_qkv + (size_t)ROWS * HDIM + (size_t)b * SEQ * HDIM + h * DHEAD;
    const float* Vg = g_qkv + 2 * (size_t)ROWS * HDIM + (size_t)b * SEQ * HDIM + h * DHEAD;
    const float* kern_bh = kern + (size_t)bh * SEQ * SEQ;
    const uint32_t* mask_bh = amask + (size_t)bh * SEQ * SEQ;

    stage_tile(sbase, 0, 0, Kg, Vg, kern_bh, mask_bh, qb, tid);
    asm volatile("cp.async.commit_group;");

    uint32_t qa[8][4];
    {
        const float* Qr0 = Qg + (size_t)(qb + w * 16 + g) * HDIM;
        const float* Qr1 = Qr0 + 8 * (size_t)HDIM;
#pragma unroll
        for (int k = 0; k < 8; k++) {
            qa[k][0] = f2tf32(Qr0[k * 8 + t]);
            qa[k][1] = f2tf32(Qr1[k * 8 + t]);
            qa[k][2] = f2tf32(Qr0[k * 8 + t + 4]);
            qa[k][3] = f2tf32(Qr1[k * 8 + t + 4]);
        }
    }

    float o[8][4];
#pragma unroll
    for (int f = 0; f < 8; f++)
#pragma unroll
        for (int u = 0; u < 4; u++) o[f][u] = 0.f;
    float m_[2] = {-1e30f, -1e30f}, l_[2] = {0.f, 0.f};

    for (int kb = 0; kb < SEQ / KB; kb++) {
        const int s = kb & 1;
        if (kb < SEQ / KB - 1) {
            stage_tile(sbase, s ^ 1, kb + 1, Kg, Vg, kern_bh, mask_bh, qb, tid);
            asm volatile("cp.async.commit_group;");
            asm volatile("cp.async.wait_group 1;");
        } else {
            asm volatile("cp.async.wait_group 0;");
        }
        __syncthreads();

        const float* Ks = sm + s * ST_WORDS;
        const float* Vs = Ks + ST_V;
        const float* Bs = Ks + ST_B;
        const uint32_t* Ms = (const uint32_t*)(Ks + ST_M);

        float sc[4][4];
#pragma unroll
        for (int f = 0; f < 4; f++)
#pragma unroll
            for (int u = 0; u < 4; u++) sc[f][u] = 0.f;
#pragma unroll
        for (int k = 0; k < 8; k++) {
#pragma unroll
            for (int f = 0; f < 4; f++) {
                uint32_t b0 = __float_as_uint(Ks[(f * 8 + g) * PADK + k * 8 + t]);
                uint32_t b1 = __float_as_uint(Ks[(f * 8 + g) * PADK + k * 8 + t + 4]);
                mma_tf32(sc[f], qa[k][0], qa[k][1], qa[k][2], qa[k][3], b0, b1);
            }
        }

#pragma unroll
        for (int e = 0; e < 2; e++) {
            const int qrl = w * 16 + g + e * 8;
            float rmax = -1e30f;
#pragma unroll
            for (int f = 0; f < 4; f++) {
#pragma unroll
                for (int u = 0; u < 2; u++) {
                    int kc = f * 8 + 2 * t + u;
                    float sv = sc[f][e * 2 + u] * scale + Bs[kc * PADB + qrl];
                    sv = Ms[qrl * PADM + kc] ? -1e30f : sv;
                    sc[f][e * 2 + u] = sv;
                    rmax = fmaxf(rmax, sv);
                }
            }
            rmax = fmaxf(rmax, __shfl_xor_sync(0xffffffffu, rmax, 1));
            rmax = fmaxf(rmax, __shfl_xor_sync(0xffffffffu, rmax, 2));
            float mn = fmaxf(m_[e], rmax);
            float fe = __expf(m_[e] - mn);
            float ps = 0.f;
#pragma unroll
            for (int f = 0; f < 4; f++) {
#pragma unroll
                for (int u = 0; u < 2; u++) {
                    float sv = sc[f][e * 2 + u];
                    float p = (sv <= -1e29f) ? 0.f : __expf(sv - mn);
                    sc[f][e * 2 + u] = p;
                    ps += p;
                }
            }
            ps += __shfl_xor_sync(0xffffffffu, ps, 1);
            ps += __shfl_xor_sync(0xffffffffu, ps, 2);
            l_[e] = l_[e] * fe + ps;
            m_[e] = mn;
#pragma unroll
            for (int f = 0; f < 4; f++) {
                o[2 * f][e * 2 + 0] *= fe;     o[2 * f][e * 2 + 1] *= fe;
                o[2 * f + 1][e * 2 + 0] *= fe; o[2 * f + 1][e * 2 + 1] *= fe;
            }
        }

#pragma unroll
        for (int kk = 0; kk < 4; kk++) {
            const int src = g * 4 + (t >> 1);
            float p00 = __shfl_sync(0xffffffffu, sc[kk][0], src);
            float p01 = __shfl_sync(0xffffffffu, sc[kk][1], src);
            float p02 = __shfl_sync(0xffffffffu, sc[kk][0], src + 2);
            float p03 = __shfl_sync(0xffffffffu, sc[kk][1], src + 2);
            float p10 = __shfl_sync(0xffffffffu, sc[kk][2], src);
            float p11 = __shfl_sync(0xffffffffu, sc[kk][3], src);
            float p12 = __shfl_sync(0xffffffffu, sc[kk][2], src + 2);
            float p13 = __shfl_sync(0xffffffffu, sc[kk][3], src + 2);
            const bool odd = (t & 1);
            uint32_t a0 = f2tf32(odd ? p01 : p00);
            uint32_t a1 = f2tf32(odd ? p11 : p10);
            uint32_t a2 = f2tf32(odd ? p03 : p02);
            uint32_t a3 = f2tf32(odd ? p13 : p12);
#pragma unroll
            for (int f = 0; f < 8; f++) {
                uint32_t b0 = __float_as_uint(Vs[(kk * 8 + t) * PADV + f * 8 + g]);
                uint32_t b1 = __float_as_uint(Vs[(kk * 8 + t + 4) * PADV + f * 8 + g]);
                mma_tf32(o[f], a0, a1, a2, a3, b0, b1);
            }
        }
        __syncthreads();
    }

    // ---- normalize + write merged-head hi/lo bf16 for outproj ----
    const size_t obase = ((size_t)b * SEQ + qb) * HDIM + h * DHEAD;
#pragma unroll
    for (int e = 0; e < 2; e++) {
        float inv = 1.0f / l_[e];
        int qrl = w * 16 + g + e * 8;
#pragma unroll
        for (int f = 0; f < 8; f++) {
            float x = o[f][e * 2 + 0] * inv;
            float y = o[f][e * 2 + 1] * inv;
            __nv_bfloat16 hx = __float2bfloat16_rn(x);
            __nv_bfloat16 hy = __float2bfloat16_rn(y);
            __nv_bfloat16 lx = __float2bfloat16_rn(x - __bfloat162float(hx));
            __nv_bfloat16 ly = __float2bfloat16_rn(y - __bfloat162float(hy));
            __nv_bfloat162 hp(hx, hy), lp(lx, ly);
            size_t off = obase + (size_t)qrl * HDIM + f * 8 + 2 * t;
            *(uint32_t*)(g_ah + off) = *(uint32_t*)&hp;
            *(uint32_t*)(g_al + off) = *(uint32_t*)&lp;
        }
    }
}

// ============================================================================
// Launch
// ============================================================================
extern "C" void kernel_launch(void* const* d_in, const int* in_sizes, int n_in,
                              void* d_out, int out_size)
{
    const float* query    = (const float*)d_in[0];
    const float* key_     = (const float*)d_in[1];
    const float* value    = (const float*)d_in[2];
    const uint32_t* amask = (const uint32_t*)d_in[3];
    const float* kern     = (const float*)d_in[5];
    const float* ipw      = (const float*)d_in[6];
    const float* ipb      = (const float*)d_in[7];
    const float* outw     = (const float*)d_in[8];
    const float* outb     = (const float*)d_in[9];
    float* out = (float*)d_out;

    cudaFuncSetAttribute(attn_mma_kernel,
                         cudaFuncAttributeMaxDynamicSharedMemorySize, ATTN_SMEM);
    cudaFuncSetAttribute(qkv_gemm_kernel,
                         cudaFuncAttributeMaxDynamicSharedMemorySize, GEMM_SMEM);
    cudaFuncSetAttribute(outproj_kernel,
                         cudaFuncAttributeMaxDynamicSharedMemorySize, GEMM_SMEM);

    // resolve device-global addresses (host-side, capture-safe)
    __nv_bfloat16 *inh, *inl, *wh, *wl;
    cudaGetSymbolAddress((void**)&inh, g_inh);
    cudaGetSymbolAddress((void**)&inl, g_inl);
    cudaGetSymbolAddress((void**)&wh,  g_wh);
    cudaGetSymbolAddress((void**)&wl,  g_wl);

    const int nIN = ROWS * HDIM / 4;          // 524288 float4 per input
    split_kernel<<<nIN / 256, 256>>>(query, inh, inl, nIN);
    split_kernel<<<nIN / 256, 256>>>(key_,  inh + (size_t)ROWS * HDIM,
                                            inl + (size_t)ROWS * HDIM, nIN);
    split_kernel<<<nIN / 256, 256>>>(value, inh + 2 * (size_t)ROWS * HDIM,
                                            inl + 2 * (size_t)ROWS * HDIM, nIN);
    const int nW3 = 3 * HDIM * HDIM / 4;
    split_kernel<<<nW3 / 256, 256>>>(ipw, wh, wl, nW3);
    const int nW1 = HDIM * HDIM / 4;
    split_kernel<<<nW1 / 256, 256>>>(outw, wh + 3u * HDIM * HDIM,
                                           wl + 3u * HDIM * HDIM, nW1);

    dim3 gq(HDIM / TBN, ROWS / TBM, 3);
    qkv_gemm_kernel<<<gq, 256, GEMM_SMEM>>>(ipb);

    dim3 ga(SEQ / QB, BATCH * NHEAD, 1);
    attn_mma_kernel<<<ga, 256, ATTN_SMEM>>>(kern, amask, 0.125f);

    dim3 go(HDIM / TBN, ROWS / TBM, 1);
    outproj_kernel<<<go, 256, GEMM_SMEM>>>(outb, out);
}

// round 9
// speedup vs baseline: 3.7422x; 1.1847x over previous
#include <cuda_runtime.h>
#include <cuda_bf16.h>
#include <cstdint>

// ----------------------------------------------------------------------------
// PositionAttention: B=4, L=1024, HD=512, H=8, D=64
// Round 9: cp.async.bulk (UBLKCP) + mbarrier staging everywhere.
//  - splits emit pre-padded k-tiled bf16 operands  -> GEMM stage = 4 bulk ops
//  - qkv GEMM writes K/V padded per-head           -> attention K/V = 1 bulk op
//  - attention epilogue writes outproj's tiled layout
// Numerics identical to R8 (rel_err 4.84e-4).
// ----------------------------------------------------------------------------

#define BATCH 4
#define SEQ   1024
#define HDIM  512
#define NHEAD 8
#define DHEAD 64
#define ROWS  (BATCH*SEQ)          // 4096

#define RSTR 40                    // bf16 per tiled row (32 data + 8 pad)
#define NKT  (HDIM/32)             // 16 k-tiles
#define AIR  (3*ROWS)              // 12288 tiled input rows (q,k,v stacked)
#define WR   2048                  // tiled weight rows (ipw 1536 + outw 512)

#define PADK 68
#define PADV 72

// scratch (allocation-free device globals)
__device__ __align__(16) float g_q[ROWS * HDIM];
__device__ __align__(16) float g_kpad[(size_t)BATCH*NHEAD*SEQ*PADK];
__device__ __align__(16) float g_vpad[(size_t)BATCH*NHEAD*SEQ*PADV];
__device__ __align__(16) __nv_bfloat16 g_inh[(size_t)NKT*AIR*RSTR];
__device__ __align__(16) __nv_bfloat16 g_inl[(size_t)NKT*AIR*RSTR];
__device__ __align__(16) __nv_bfloat16 g_wh[(size_t)NKT*WR*RSTR];
__device__ __align__(16) __nv_bfloat16 g_wl[(size_t)NKT*WR*RSTR];
__device__ __align__(16) __nv_bfloat16 g_ah[(size_t)NKT*ROWS*RSTR];
__device__ __align__(16) __nv_bfloat16 g_al[(size_t)NKT*ROWS*RSTR];

// ============================================================================
// mbarrier / bulk-copy primitives
// ============================================================================
__device__ __forceinline__ void mbar_init(uint32_t a, uint32_t cnt) {
    asm volatile("mbarrier.init.shared.b64 [%0], %1;" :: "r"(a), "r"(cnt) : "memory");
}
__device__ __forceinline__ void mbar_expect(uint32_t a, uint32_t bytes) {
    asm volatile("mbarrier.arrive.expect_tx.shared.b64 _, [%0], %1;"
                 :: "r"(a), "r"(bytes) : "memory");
}
__device__ __forceinline__ void mbar_wait(uint32_t a, uint32_t parity) {
    asm volatile(
        "{\n\t.reg .pred P;\n\t"
        "WAIT_%=:\n\t"
        "mbarrier.try_wait.parity.acquire.cta.shared::cta.b64 P, [%0], %1, 0x989680;\n\t"
        "@P bra.uni DONE_%=;\n\t"
        "bra.uni WAIT_%=;\n\t"
        "DONE_%=:\n\t}"
        :: "r"(a), "r"(parity) : "memory");
}
__device__ __forceinline__ void bulk_g2s(uint32_t dst, const void* src,
                                         uint32_t bytes, uint32_t mbar) {
    asm volatile(
        "cp.async.bulk.shared::cta.global.mbarrier::complete_tx::bytes "
        "[%0], [%1], %2, [%3];"
        :: "r"(dst), "l"(src), "r"(bytes), "r"(mbar) : "memory");
}
__device__ __forceinline__ void fence_async_init() {
    asm volatile("fence.proxy.async.shared::cta;" ::: "memory");
}

// ============================================================================
// split kernels: fp32 -> (hi,lo) bf16, k-tiled padded layout [kt][row][RSTR]
// Each thread: 8 consecutive floats (one 32-col tile segment) -> uint4 hi + lo
// ============================================================================
__device__ __forceinline__ void split8(const float* src, uint4& hw, uint4& lw)
{
    float4 a = *(const float4*)src;
    float4 b = *(const float4*)(src + 4);
    float v[8] = {a.x, a.y, a.z, a.w, b.x, b.y, b.z, b.w};
    uint32_t h[4], l[4];
#pragma unroll
    for (int i = 0; i < 4; i++) {
        __nv_bfloat16 h0 = __float2bfloat16_rn(v[2*i]);
        __nv_bfloat16 h1 = __float2bfloat16_rn(v[2*i+1]);
        __nv_bfloat16 l0 = __float2bfloat16_rn(v[2*i]   - __bfloat162float(h0));
        __nv_bfloat16 l1 = __float2bfloat16_rn(v[2*i+1] - __bfloat162float(h1));
        __nv_bfloat162 hp(h0, h1), lp(l0, l1);
        h[i] = *(uint32_t*)&hp; l[i] = *(uint32_t*)&lp;
    }
    hw = make_uint4(h[0], h[1], h[2], h[3]);
    lw = make_uint4(l[0], l[1], l[2], l[3]);
}

__global__ void __launch_bounds__(256)
split_in_kernel(const float* __restrict__ q, const float* __restrict__ k,
                const float* __restrict__ v)
{
    size_t i = (size_t)blockIdx.x * 256 + threadIdx.x;   // 0 .. 3*4096*64-1
    int mat = (int)(i / (ROWS * 64));
    size_t rem = i - (size_t)mat * (ROWS * 64);
    int r = (int)(rem >> 6);
    int kk = ((int)rem & 63) * 8;
    int kt = kk >> 5, km = kk & 31;
    const float* src = (mat == 0 ? q : mat == 1 ? k : v) + ((size_t)r << 9) + kk;
    uint4 hw, lw; split8(src, hw, lw);
    size_t d = ((size_t)kt * AIR + (size_t)mat * ROWS + r) * RSTR + km;
    *(uint4*)(g_inh + d) = hw;
    *(uint4*)(g_inl + d) = lw;
}

__global__ void __launch_bounds__(256)
split_w_kernel(const float* __restrict__ ipw, const float* __restrict__ outw)
{
    size_t i = (size_t)blockIdx.x * 256 + threadIdx.x;   // 0 .. 2048*64-1
    int r = (int)(i >> 6);
    int kk = ((int)i & 63) * 8;
    int kt = kk >> 5, km = kk & 31;
    const float* src = (r < 1536) ? (ipw + ((size_t)r << 9) + kk)
                                  : (outw + ((size_t)(r - 1536) << 9) + kk);
    uint4 hw, lw; split8(src, hw, lw);
    size_t d = ((size_t)kt * WR + r) * RSTR + km;
    *(uint4*)(g_wh + d) = hw;
    *(uint4*)(g_wl + d) = lw;
}

// ============================================================================
// bf16x3 GEMM with bulk-copy 2-stage mbarrier pipeline.
// 128x128x32 block, 8 warps (2x4), warp 64x32, m16n8k16. Stage = 4 x 10240B.
// ============================================================================
#define TBM 128
#define TBN 128
#define MATW (TBM * RSTR / 2)           // 2560 words per matrix tile
#define GSTW (4 * MATW)                 // 10240 words per stage
#define GEMM_SMEM (2 * GSTW * 4 + 16)   // + 2 mbarriers

__device__ __forceinline__ void mma_bf16(float c[4],
    uint32_t a0, uint32_t a1, uint32_t a2, uint32_t a3,
    uint32_t b0, uint32_t b1)
{
    asm volatile(
        "mma.sync.aligned.m16n8k16.row.col.f32.bf16.bf16.f32 "
        "{%0,%1,%2,%3}, {%4,%5,%6,%7}, {%8,%9}, {%0,%1,%2,%3};"
        : "+f"(c[0]), "+f"(c[1]), "+f"(c[2]), "+f"(c[3])
        : "r"(a0), "r"(a1), "r"(a2), "r"(a3), "r"(b0), "r"(b1));
}

// mode: 0 = plain fp32 rows [r][512] into Cplain
//       1 = padded per-head K layout  [bh][row][PADK]
//       2 = padded per-head V layout  [bh][row][PADV]
__device__ __forceinline__ void gemm_core(
    const __nv_bfloat16* __restrict__ Ah, const __nv_bfloat16* __restrict__ Al,
    int AR, int arow0,
    const __nv_bfloat16* __restrict__ Bh, const __nv_bfloat16* __restrict__ Bl,
    int BR, int brow0,
    const float* __restrict__ bias, float* __restrict__ Cout, int mode,
    uint32_t* smem)
{
    const int tid  = threadIdx.x;
    const int w    = tid >> 5;
    const int lane = tid & 31;
    const int g = lane >> 2, t = lane & 3;
    const int wm = w >> 2, wn = w & 3;
    const int m0 = wm * 64, n0 = wn * 32;
    const int bm = blockIdx.y * TBM;
    const int bn = blockIdx.x * TBN;
    const uint32_t sbase = (uint32_t)__cvta_generic_to_shared(smem);
    const uint32_t mb0 = sbase + 2u * GSTW * 4u;
    const uint32_t mb1 = mb0 + 8u;
    const uint32_t STB = GSTW * 4u;   // stage bytes (40960)

    float acc[4][4][4];
#pragma unroll
    for (int mt = 0; mt < 4; mt++)
#pragma unroll
        for (int nt = 0; nt < 4; nt++)
#pragma unroll
            for (int u = 0; u < 4; u++) acc[mt][nt][u] = 0.f;

    if (tid == 0) { mbar_init(mb0, 1); mbar_init(mb1, 1); }
    fence_async_init();
    __syncthreads();

    // issue staging for k-tile kt into stage ss
    auto issue = [&](int ss, int kt) {
        const uint32_t base = sbase + (uint32_t)ss * GSTW * 4u;
        const uint32_t mb = ss ? mb1 : mb0;
        if (tid < 4) {
            const __nv_bfloat16* src;
            size_t off;
            if (tid < 2) {
                src = tid ? Al : Ah;
                off = ((size_t)kt * AR + arow0 + bm) * RSTR;
            } else {
                src = (tid == 2) ? Bh : Bl;
                off = ((size_t)kt * BR + brow0 + bn) * RSTR;
            }
            bulk_g2s(base + (uint32_t)tid * MATW * 4u, src + off, MATW * 4u, mb);
        }
    };

    if (tid == 0) mbar_expect(mb0, STB);
    __syncthreads();
    issue(0, 0);

    for (int kt = 0; kt < NKT; kt++) {
        const int s = kt & 1;
        if (kt < NKT - 1) {
            if (tid == 0) mbar_expect(s ? mb0 : mb1, STB);
            __syncthreads();              // prior reads of stage s^1 done
            issue(s ^ 1, kt + 1);
        }
        mbar_wait(s ? mb1 : mb0, (uint32_t)((kt >> 1) & 1));

        const uint32_t* Sw  = smem + s * GSTW;
        const uint32_t* AhW = Sw;
        const uint32_t* AlW = Sw + MATW;
        const uint32_t* BhW = Sw + 2 * MATW;
        const uint32_t* BlW = Sw + 3 * MATW;

#pragma unroll
        for (int ks = 0; ks < 2; ks++) {
            uint32_t bhf[4][2], blf[4][2];
#pragma unroll
            for (int nt = 0; nt < 4; nt++) {
                int wb = (n0 + nt * 8 + g) * (RSTR / 2) + ks * 8 + t;
                bhf[nt][0] = BhW[wb]; bhf[nt][1] = BhW[wb + 4];
                blf[nt][0] = BlW[wb]; blf[nt][1] = BlW[wb + 4];
            }
#pragma unroll
            for (int mt = 0; mt < 4; mt++) {
                int wa = (m0 + mt * 16 + g) * (RSTR / 2) + ks * 8 + t;
                uint32_t ah0 = AhW[wa],     ah1 = AhW[wa + 8 * (RSTR / 2)];
                uint32_t ah2 = AhW[wa + 4], ah3 = AhW[wa + 8 * (RSTR / 2) + 4];
                uint32_t al0 = AlW[wa],     al1 = AlW[wa + 8 * (RSTR / 2)];
                uint32_t al2 = AlW[wa + 4], al3 = AlW[wa + 8 * (RSTR / 2) + 4];
#pragma unroll
                for (int nt = 0; nt < 4; nt++) {
                    mma_bf16(acc[mt][nt], ah0, ah1, ah2, ah3, bhf[nt][0], bhf[nt][1]);
                    mma_bf16(acc[mt][nt], ah0, ah1, ah2, ah3, blf[nt][0], blf[nt][1]);
                    mma_bf16(acc[mt][nt], al0, al1, al2, al3, bhf[nt][0], bhf[nt][1]);
                }
            }
        }
    }

    // epilogue
#pragma unroll
    for (int mt = 0; mt < 4; mt++) {
#pragma unroll
        for (int nt = 0; nt < 4; nt++) {
            int r = bm + m0 + mt * 16 + g;
            int c = bn + n0 + nt * 8 + 2 * t;
            float bx = bias[c], by = bias[c + 1];
            float2 v0 = make_float2(acc[mt][nt][0] + bx, acc[mt][nt][1] + by);
            float2 v1 = make_float2(acc[mt][nt][2] + bx, acc[mt][nt][3] + by);
            if (mode == 0) {
                *(float2*)(Cout + (size_t)r * HDIM + c) = v0;
                *(float2*)(Cout + (size_t)(r + 8) * HDIM + c) = v1;
            } else {
                const int pw = (mode == 1) ? PADK : PADV;
                int b_ = r >> 10, sr = r & 1023, h_ = c >> 6, d = c & 63;
                float* dst = Cout + ((size_t)(b_ * NHEAD + h_) * SEQ + sr) * pw + d;
                *(float2*)dst = v0;
                *(float2*)(dst + (size_t)8 * pw) = v1;
            }
        }
    }
}

__global__ void __launch_bounds__(256, 2)
qkv_gemm_kernel(const float* __restrict__ ipb)
{
    extern __shared__ uint32_t smem_g[];
    const int z = blockIdx.z;
    float* outp = (z == 0) ? g_q : (z == 1) ? g_kpad : g_vpad;
    gemm_core(g_inh, g_inl, AIR, z * ROWS,
              g_wh, g_wl, WR, z * HDIM,
              ipb + z * HDIM, outp, z, smem_g);
}

__global__ void __launch_bounds__(256, 2)
outproj_kernel(const float* __restrict__ outb, float* __restrict__ out)
{
    extern __shared__ uint32_t smem_g[];
    gemm_core(g_ah, g_al, ROWS, 0,
              g_wh, g_wl, WR, 3 * HDIM,
              outb, out, 0, smem_g);
}

// ============================================================================
// TF32 flash attention, bulk-copy 2-stage mbarrier pipeline.
// QB=128 q-rows, 32 tiles of KB=32. Warp = 16 q-rows. Mainloop math == R6/R8.
// Stage words: K[32x68] | V[32x72] | bias[32x132] | mask[128x40]
// ============================================================================
#define QB 128
#define KB 32
#define PADB 132
#define PADM 40
#define ST_V (KB*PADK)
#define ST_B (ST_V + KB*PADV)
#define ST_M (ST_B + KB*PADB)
#define ST_WORDS (ST_M + QB*PADM)              // 13824 words
#define ATTN_TX (KB*PADK*4 + KB*PADV*4 + KB*512 + QB*128)   // 50688 bytes
#define ATTN_SMEM (2 * ST_WORDS * 4 + 16)

__device__ __forceinline__ uint32_t f2tf32(float f) {
    uint32_t r;
    asm("cvt.rna.tf32.f32 %0, %1;" : "=r"(r) : "f"(f));
    return r;
}

__device__ __forceinline__ void mma_tf32(float c[4],
    uint32_t a0, uint32_t a1, uint32_t a2, uint32_t a3,
    uint32_t b0, uint32_t b1)
{
    asm volatile(
        "mma.sync.aligned.m16n8k8.row.col.f32.tf32.tf32.f32 "
        "{%0,%1,%2,%3}, {%4,%5,%6,%7}, {%8,%9}, {%0,%1,%2,%3};"
        : "+f"(c[0]), "+f"(c[1]), "+f"(c[2]), "+f"(c[3])
        : "r"(a0), "r"(a1), "r"(a2), "r"(a3), "r"(b0), "r"(b1));
}

__global__ void __launch_bounds__(256, 2)
attn_mma_kernel(const float* __restrict__ kern,
                const uint32_t* __restrict__ amask, float scale)
{
    extern __shared__ float sm[];
    const uint32_t sbase = (uint32_t)__cvta_generic_to_shared(sm);
    const uint32_t mb0 = sbase + 2u * ST_WORDS * 4u;
    const uint32_t mb1 = mb0 + 8u;

    const int bh = blockIdx.y, b = bh >> 3, h = bh & 7;
    const int qb = blockIdx.x * QB;
    const int tid  = threadIdx.x;
    const int w    = tid >> 5;
    const int lane = tid & 31;
    const int g = lane >> 2, t = lane & 3;

    const float* Qg = g_q + (size_t)b * SEQ * HDIM + h * DHEAD;
    const float* Kp = g_kpad + (size_t)bh * SEQ * PADK;
    const float* Vp = g_vpad + (size_t)bh * SEQ * PADV;
    const float* kern_bh = kern + (size_t)bh * SEQ * SEQ;
    const uint32_t* mask_bh = amask + (size_t)bh * SEQ * SEQ;

    if (tid == 0) { mbar_init(mb0, 1); mbar_init(mb1, 1); }
    fence_async_init();
    __syncthreads();

    auto issue = [&](int ss, int kb) {
        const uint32_t base = sbase + (uint32_t)(ss * ST_WORDS) * 4u;
        const uint32_t mb = ss ? mb1 : mb0;
        if (tid == 0)
            bulk_g2s(base, Kp + (size_t)kb * KB * PADK, KB * PADK * 4u, mb);
        else if (tid == 1)
            bulk_g2s(base + ST_V * 4u, Vp + (size_t)kb * KB * PADV, KB * PADV * 4u, mb);
        else if (tid >= 32 && tid < 64) {
            int r = tid - 32;
            bulk_g2s(base + (uint32_t)(ST_B + r * PADB) * 4u,
                     kern_bh + (size_t)(kb * KB + r) * SEQ + qb, 512u, mb);
        } else if (tid >= 64 && tid < 192) {
            int r = tid - 64;
            bulk_g2s(base + (uint32_t)(ST_M + r * PADM) * 4u,
                     mask_bh + (size_t)(qb + r) * SEQ + kb * KB, 128u, mb);
        }
    };

    if (tid == 0) mbar_expect(mb0, ATTN_TX);
    __syncthreads();
    issue(0, 0);

    // Q fragments straight from gmem (overlaps with TMA of tile 0)
    uint32_t qa[8][4];
    {
        const float* Qr0 = Qg + (size_t)(qb + w * 16 + g) * HDIM;
        const float* Qr1 = Qr0 + 8 * (size_t)HDIM;
#pragma unroll
        for (int k = 0; k < 8; k++) {
            qa[k][0] = f2tf32(Qr0[k * 8 + t]);
            qa[k][1] = f2tf32(Qr1[k * 8 + t]);
            qa[k][2] = f2tf32(Qr0[k * 8 + t + 4]);
            qa[k][3] = f2tf32(Qr1[k * 8 + t + 4]);
        }
    }

    float o[8][4];
#pragma unroll
    for (int f = 0; f < 8; f++)
#pragma unroll
        for (int u = 0; u < 4; u++) o[f][u] = 0.f;
    float m_[2] = {-1e30f, -1e30f}, l_[2] = {0.f, 0.f};

    const int NT = SEQ / KB;
    for (int kb = 0; kb < NT; kb++) {
        const int s = kb & 1;
        if (kb < NT - 1) {
            if (tid == 0) mbar_expect(s ? mb0 : mb1, ATTN_TX);
            __syncthreads();              // prior reads of stage s^1 done
            issue(s ^ 1, kb + 1);
        }
        mbar_wait(s ? mb1 : mb0, (uint32_t)((kb >> 1) & 1));

        const float* Ks = sm + s * ST_WORDS;
        const float* Vs = Ks + ST_V;
        const float* Bs = Ks + ST_B;
        const uint32_t* Ms = (const uint32_t*)(Ks + ST_M);

        // ---- S = Q K^T ----
        float sc[4][4];
#pragma unroll
        for (int f = 0; f < 4; f++)
#pragma unroll
            for (int u = 0; u < 4; u++) sc[f][u] = 0.f;
#pragma unroll
        for (int k = 0; k < 8; k++) {
#pragma unroll
            for (int f = 0; f < 4; f++) {
                uint32_t b0 = __float_as_uint(Ks[(f * 8 + g) * PADK + k * 8 + t]);
                uint32_t b1 = __float_as_uint(Ks[(f * 8 + g) * PADK + k * 8 + t + 4]);
                mma_tf32(sc[f], qa[k][0], qa[k][1], qa[k][2], qa[k][3], b0, b1);
            }
        }

        // ---- scale + bias(kernel^T) + mask + online softmax ----
#pragma unroll
        for (int e = 0; e < 2; e++) {
            const int qrl = w * 16 + g + e * 8;
            float rmax = -1e30f;
#pragma unroll
            for (int f = 0; f < 4; f++) {
#pragma unroll
                for (int u = 0; u < 2; u++) {
                    int kc = f * 8 + 2 * t + u;
                    float sv = sc[f][e * 2 + u] * scale + Bs[kc * PADB + qrl];
                    sv = Ms[qrl * PADM + kc] ? -1e30f : sv;
                    sc[f][e * 2 + u] = sv;
                    rmax = fmaxf(rmax, sv);
                }
            }
            rmax = fmaxf(rmax, __shfl_xor_sync(0xffffffffu, rmax, 1));
            rmax = fmaxf(rmax, __shfl_xor_sync(0xffffffffu, rmax, 2));
            float mn = fmaxf(m_[e], rmax);
            float fe = __expf(m_[e] - mn);
            float ps = 0.f;
#pragma unroll
            for (int f = 0; f < 4; f++) {
#pragma unroll
                for (int u = 0; u < 2; u++) {
                    float sv = sc[f][e * 2 + u];
                    float p = (sv <= -1e29f) ? 0.f : __expf(sv - mn);
                    sc[f][e * 2 + u] = p;
                    ps += p;
                }
            }
            ps += __shfl_xor_sync(0xffffffffu, ps, 1);
            ps += __shfl_xor_sync(0xffffffffu, ps, 2);
            l_[e] = l_[e] * fe + ps;
            m_[e] = mn;
#pragma unroll
            for (int f = 0; f < 4; f++) {
                o[2 * f][e * 2 + 0] *= fe;     o[2 * f][e * 2 + 1] *= fe;
                o[2 * f + 1][e * 2 + 0] *= fe; o[2 * f + 1][e * 2 + 1] *= fe;
            }
        }

        // ---- O += P @ V (shuffle transpose C->A fragments) ----
#pragma unroll
        for (int kk = 0; kk < 4; kk++) {
            const int src = g * 4 + (t >> 1);
            float p00 = __shfl_sync(0xffffffffu, sc[kk][0], src);
            float p01 = __shfl_sync(0xffffffffu, sc[kk][1], src);
            float p02 = __shfl_sync(0xffffffffu, sc[kk][0], src + 2);
            float p03 = __shfl_sync(0xffffffffu, sc[kk][1], src + 2);
            float p10 = __shfl_sync(0xffffffffu, sc[kk][2], src);
            float p11 = __shfl_sync(0xffffffffu, sc[kk][3], src);
            float p12 = __shfl_sync(0xffffffffu, sc[kk][2], src + 2);
            float p13 = __shfl_sync(0xffffffffu, sc[kk][3], src + 2);
            const bool odd = (t & 1);
            uint32_t a0 = f2tf32(odd ? p01 : p00);
            uint32_t a1 = f2tf32(odd ? p11 : p10);
            uint32_t a2 = f2tf32(odd ? p03 : p02);
            uint32_t a3 = f2tf32(odd ? p13 : p12);
#pragma unroll
            for (int f = 0; f < 8; f++) {
                uint32_t b0 = __float_as_uint(Vs[(kk * 8 + t) * PADV + f * 8 + g]);
                uint32_t b1 = __float_as_uint(Vs[(kk * 8 + t + 4) * PADV + f * 8 + g]);
                mma_tf32(o[f], a0, a1, a2, a3, b0, b1);
            }
        }
    }

    // ---- normalize + write hi/lo bf16 in outproj's tiled layout ----
#pragma unroll
    for (int e = 0; e < 2; e++) {
        float inv = 1.0f / l_[e];
        int qrl = w * 16 + g + e * 8;
        size_t grow = (size_t)b * SEQ + qb + qrl;
#pragma unroll
        for (int f = 0; f < 8; f++) {
            float x = o[f][e * 2 + 0] * inv;
            float y = o[f][e * 2 + 1] * inv;
            __nv_bfloat16 hx = __float2bfloat16_rn(x);
            __nv_bfloat16 hy = __float2bfloat16_rn(y);
            __nv_bfloat16 lx = __float2bfloat16_rn(x - __bfloat162float(hx));
            __nv_bfloat16 ly = __float2bfloat16_rn(y - __bfloat162float(hy));
            __nv_bfloat162 hp(hx, hy), lp(lx, ly);
            int c = h * DHEAD + f * 8 + 2 * t;
            int kt = c >> 5, km = c & 31;
            size_t off = ((size_t)kt * ROWS + grow) * RSTR + km;
            *(uint32_t*)(g_ah + off) = *(uint32_t*)&hp;
            *(uint32_t*)(g_al + off) = *(uint32_t*)&lp;
        }
    }
}

// ============================================================================
// Launch
// ============================================================================
extern "C" void kernel_launch(void* const* d_in, const int* in_sizes, int n_in,
                              void* d_out, int out_size)
{
    const float* query    = (const float*)d_in[0];
    const float* key_     = (const float*)d_in[1];
    const float* value    = (const float*)d_in[2];
    const uint32_t* amask = (const uint32_t*)d_in[3];
    const float* kern     = (const float*)d_in[5];
    const float* ipw      = (const float*)d_in[6];
    const float* ipb      = (const float*)d_in[7];
    const float* outw     = (const float*)d_in[8];
    const float* outb     = (const float*)d_in[9];
    float* out = (float*)d_out;

    cudaFuncSetAttribute(attn_mma_kernel,
                         cudaFuncAttributeMaxDynamicSharedMemorySize, ATTN_SMEM);
    cudaFuncSetAttribute(qkv_gemm_kernel,
                         cudaFuncAttributeMaxDynamicSharedMemorySize, GEMM_SMEM);
    cudaFuncSetAttribute(outproj_kernel,
                         cudaFuncAttributeMaxDynamicSharedMemorySize, GEMM_SMEM);

    split_in_kernel<<<3 * ROWS * 64 / 256, 256>>>(query, key_, value);
    split_w_kernel<<<WR * 64 / 256, 256>>>(ipw, outw);

    dim3 gq(HDIM / TBN, ROWS / TBM, 3);
    qkv_gemm_kernel<<<gq, 256, GEMM_SMEM>>>(ipb);

    dim3 ga(SEQ / QB, BATCH * NHEAD, 1);
    attn_mma_kernel<<<ga, 256, ATTN_SMEM>>>(kern, amask, 0.125f);

    dim3 go(HDIM / TBN, ROWS / TBM, 1);
    outproj_kernel<<<go, 256, GEMM_SMEM>>>(outb, out);
}

// round 10
// speedup vs baseline: 3.8100x; 1.0181x over previous
#include <cuda_runtime.h>
#include <cuda_bf16.h>
#include <cstdint>

// ----------------------------------------------------------------------------
// PositionAttention: B=4, L=1024, HD=512, H=8, D=64
// Round 10: attention fragment loads vectorized via octet-permuted K / V^T
// layouts written by the qkv GEMM epilogue. LDS instr count ~halved.
// Math bit-identical to R9 (rel_err must stay 4.8359e-4).
// ----------------------------------------------------------------------------

#define BATCH 4
#define SEQ   1024
#define HDIM  512
#define NHEAD 8
#define DHEAD 64
#define ROWS  (BATCH*SEQ)          // 4096

#define RSTR 40                    // bf16 per tiled row (32 data + 8 pad)
#define NKT  (HDIM/32)             // 16 k-tiles
#define AIR  (3*ROWS)              // tiled input rows (q,k,v stacked)
#define WR   2048                  // tiled weight rows (ipw 1536 + outw 512)

#define PADK 72                    // K row stride (72 % 32 == 8: conflict-free f2)
#define PADVT 40                   // V^T row stride (40 % 32 == 8)
#define KB  32

// scratch (allocation-free device globals)
__device__ __align__(16) float g_q[ROWS * HDIM];
__device__ __align__(16) float g_kpad[(size_t)BATCH*NHEAD*SEQ*PADK];          // d-permuted
__device__ __align__(16) float g_vt[(size_t)BATCH*NHEAD*(SEQ/KB)*DHEAD*PADVT]; // transposed, k-permuted
__device__ __align__(16) __nv_bfloat16 g_inh[(size_t)NKT*AIR*RSTR];
__device__ __align__(16) __nv_bfloat16 g_inl[(size_t)NKT*AIR*RSTR];
__device__ __align__(16) __nv_bfloat16 g_wh[(size_t)NKT*WR*RSTR];
__device__ __align__(16) __nv_bfloat16 g_wl[(size_t)NKT*WR*RSTR];
__device__ __align__(16) __nv_bfloat16 g_ah[(size_t)NKT*ROWS*RSTR];
__device__ __align__(16) __nv_bfloat16 g_al[(size_t)NKT*ROWS*RSTR];

// octet permutation: (t, t+4) column pairs become adjacent
__device__ __forceinline__ int operm(int d) {
    return (d & ~7) | ((d & 3) << 1) | ((d >> 2) & 1);
}

// ============================================================================
// mbarrier / bulk-copy primitives
// ============================================================================
__device__ __forceinline__ void mbar_init(uint32_t a, uint32_t cnt) {
    asm volatile("mbarrier.init.shared.b64 [%0], %1;" :: "r"(a), "r"(cnt) : "memory");
}
__device__ __forceinline__ void mbar_expect(uint32_t a, uint32_t bytes) {
    asm volatile("mbarrier.arrive.expect_tx.shared.b64 _, [%0], %1;"
                 :: "r"(a), "r"(bytes) : "memory");
}
__device__ __forceinline__ void mbar_wait(uint32_t a, uint32_t parity) {
    asm volatile(
        "{\n\t.reg .pred P;\n\t"
        "WAIT_%=:\n\t"
        "mbarrier.try_wait.parity.acquire.cta.shared::cta.b64 P, [%0], %1, 0x989680;\n\t"
        "@P bra.uni DONE_%=;\n\t"
        "bra.uni WAIT_%=;\n\t"
        "DONE_%=:\n\t}"
        :: "r"(a), "r"(parity) : "memory");
}
__device__ __forceinline__ void bulk_g2s(uint32_t dst, const void* src,
                                         uint32_t bytes, uint32_t mbar) {
    asm volatile(
        "cp.async.bulk.shared::cta.global.mbarrier::complete_tx::bytes "
        "[%0], [%1], %2, [%3];"
        :: "r"(dst), "l"(src), "r"(bytes), "r"(mbar) : "memory");
}
__device__ __forceinline__ void fence_async_init() {
    asm volatile("fence.proxy.async.shared::cta;" ::: "memory");
}

// ============================================================================
// split kernels (unchanged from R9)
// ============================================================================
__device__ __forceinline__ void split8(const float* src, uint4& hw, uint4& lw)
{
    float4 a = *(const float4*)src;
    float4 b = *(const float4*)(src + 4);
    float v[8] = {a.x, a.y, a.z, a.w, b.x, b.y, b.z, b.w};
    uint32_t h[4], l[4];
#pragma unroll
    for (int i = 0; i < 4; i++) {
        __nv_bfloat16 h0 = __float2bfloat16_rn(v[2*i]);
        __nv_bfloat16 h1 = __float2bfloat16_rn(v[2*i+1]);
        __nv_bfloat16 l0 = __float2bfloat16_rn(v[2*i]   - __bfloat162float(h0));
        __nv_bfloat16 l1 = __float2bfloat16_rn(v[2*i+1] - __bfloat162float(h1));
        __nv_bfloat162 hp(h0, h1), lp(l0, l1);
        h[i] = *(uint32_t*)&hp; l[i] = *(uint32_t*)&lp;
    }
    hw = make_uint4(h[0], h[1], h[2], h[3]);
    lw = make_uint4(l[0], l[1], l[2], l[3]);
}

__global__ void __launch_bounds__(256)
split_in_kernel(const float* __restrict__ q, const float* __restrict__ k,
                const float* __restrict__ v)
{
    size_t i = (size_t)blockIdx.x * 256 + threadIdx.x;
    int mat = (int)(i / (ROWS * 64));
    size_t rem = i - (size_t)mat * (ROWS * 64);
    int r = (int)(rem >> 6);
    int kk = ((int)rem & 63) * 8;
    int kt = kk >> 5, km = kk & 31;
    const float* src = (mat == 0 ? q : mat == 1 ? k : v) + ((size_t)r << 9) + kk;
    uint4 hw, lw; split8(src, hw, lw);
    size_t d = ((size_t)kt * AIR + (size_t)mat * ROWS + r) * RSTR + km;
    *(uint4*)(g_inh + d) = hw;
    *(uint4*)(g_inl + d) = lw;
}

__global__ void __launch_bounds__(256)
split_w_kernel(const float* __restrict__ ipw, const float* __restrict__ outw)
{
    size_t i = (size_t)blockIdx.x * 256 + threadIdx.x;
    int r = (int)(i >> 6);
    int kk = ((int)i & 63) * 8;
    int kt = kk >> 5, km = kk & 31;
    const float* src = (r < 1536) ? (ipw + ((size_t)r << 9) + kk)
                                  : (outw + ((size_t)(r - 1536) << 9) + kk);
    uint4 hw, lw; split8(src, hw, lw);
    size_t d = ((size_t)kt * WR + r) * RSTR + km;
    *(uint4*)(g_wh + d) = hw;
    *(uint4*)(g_wl + d) = lw;
}

// ============================================================================
// bf16x3 GEMM, bulk-copy 2-stage (mainloop unchanged from R9).
// Epilogue modes: 0 = plain fp32 [r][512]
//                 1 = K: [bh][seq][PADK], d octet-permuted
//                 2 = V^T: [bh][kb][d][PADVT], k octet-permuted
// ============================================================================
#define TBM 128
#define TBN 128
#define MATW (TBM * RSTR / 2)
#define GSTW (4 * MATW)
#define GEMM_SMEM (2 * GSTW * 4 + 16)

__device__ __forceinline__ void mma_bf16(float c[4],
    uint32_t a0, uint32_t a1, uint32_t a2, uint32_t a3,
    uint32_t b0, uint32_t b1)
{
    asm volatile(
        "mma.sync.aligned.m16n8k16.row.col.f32.bf16.bf16.f32 "
        "{%0,%1,%2,%3}, {%4,%5,%6,%7}, {%8,%9}, {%0,%1,%2,%3};"
        : "+f"(c[0]), "+f"(c[1]), "+f"(c[2]), "+f"(c[3])
        : "r"(a0), "r"(a1), "r"(a2), "r"(a3), "r"(b0), "r"(b1));
}

__device__ __forceinline__ void gemm_core(
    const __nv_bfloat16* __restrict__ Ah, const __nv_bfloat16* __restrict__ Al,
    int AR, int arow0,
    const __nv_bfloat16* __restrict__ Bh, const __nv_bfloat16* __restrict__ Bl,
    int BR, int brow0,
    const float* __restrict__ bias, float* __restrict__ Cout, int mode,
    uint32_t* smem)
{
    const int tid  = threadIdx.x;
    const int w    = tid >> 5;
    const int lane = tid & 31;
    const int g = lane >> 2, t = lane & 3;
    const int wm = w >> 2, wn = w & 3;
    const int m0 = wm * 64, n0 = wn * 32;
    const int bm = blockIdx.y * TBM;
    const int bn = blockIdx.x * TBN;
    const uint32_t sbase = (uint32_t)__cvta_generic_to_shared(smem);
    const uint32_t mb0 = sbase + 2u * GSTW * 4u;
    const uint32_t mb1 = mb0 + 8u;
    const uint32_t STB = GSTW * 4u;

    float acc[4][4][4];
#pragma unroll
    for (int mt = 0; mt < 4; mt++)
#pragma unroll
        for (int nt = 0; nt < 4; nt++)
#pragma unroll
            for (int u = 0; u < 4; u++) acc[mt][nt][u] = 0.f;

    if (tid == 0) { mbar_init(mb0, 1); mbar_init(mb1, 1); }
    fence_async_init();
    __syncthreads();

    auto issue = [&](int ss, int kt) {
        const uint32_t base = sbase + (uint32_t)ss * GSTW * 4u;
        const uint32_t mb = ss ? mb1 : mb0;
        if (tid < 4) {
            const __nv_bfloat16* src;
            size_t off;
            if (tid < 2) {
                src = tid ? Al : Ah;
                off = ((size_t)kt * AR + arow0 + bm) * RSTR;
            } else {
                src = (tid == 2) ? Bh : Bl;
                off = ((size_t)kt * BR + brow0 + bn) * RSTR;
            }
            bulk_g2s(base + (uint32_t)tid * MATW * 4u, src + off, MATW * 4u, mb);
        }
    };

    if (tid == 0) mbar_expect(mb0, STB);
    __syncthreads();
    issue(0, 0);

    for (int kt = 0; kt < NKT; kt++) {
        const int s = kt & 1;
        if (kt < NKT - 1) {
            if (tid == 0) mbar_expect(s ? mb0 : mb1, STB);
            __syncthreads();
            issue(s ^ 1, kt + 1);
        }
        mbar_wait(s ? mb1 : mb0, (uint32_t)((kt >> 1) & 1));

        const uint32_t* Sw  = smem + s * GSTW;
        const uint32_t* AhW = Sw;
        const uint32_t* AlW = Sw + MATW;
        const uint32_t* BhW = Sw + 2 * MATW;
        const uint32_t* BlW = Sw + 3 * MATW;

#pragma unroll
        for (int ks = 0; ks < 2; ks++) {
            uint32_t bhf[4][2], blf[4][2];
#pragma unroll
            for (int nt = 0; nt < 4; nt++) {
                int wb = (n0 + nt * 8 + g) * (RSTR / 2) + ks * 8 + t;
                bhf[nt][0] = BhW[wb]; bhf[nt][1] = BhW[wb + 4];
                blf[nt][0] = BlW[wb]; blf[nt][1] = BlW[wb + 4];
            }
#pragma unroll
            for (int mt = 0; mt < 4; mt++) {
                int wa = (m0 + mt * 16 + g) * (RSTR / 2) + ks * 8 + t;
                uint32_t ah0 = AhW[wa],     ah1 = AhW[wa + 8 * (RSTR / 2)];
                uint32_t ah2 = AhW[wa + 4], ah3 = AhW[wa + 8 * (RSTR / 2) + 4];
                uint32_t al0 = AlW[wa],     al1 = AlW[wa + 8 * (RSTR / 2)];
                uint32_t al2 = AlW[wa + 4], al3 = AlW[wa + 8 * (RSTR / 2) + 4];
#pragma unroll
                for (int nt = 0; nt < 4; nt++) {
                    mma_bf16(acc[mt][nt], ah0, ah1, ah2, ah3, bhf[nt][0], bhf[nt][1]);
                    mma_bf16(acc[mt][nt], ah0, ah1, ah2, ah3, blf[nt][0], blf[nt][1]);
                    mma_bf16(acc[mt][nt], al0, al1, al2, al3, bhf[nt][0], bhf[nt][1]);
                }
            }
        }
    }

    // epilogue
#pragma unroll
    for (int mt = 0; mt < 4; mt++) {
#pragma unroll
        for (int nt = 0; nt < 4; nt++) {
            int r = bm + m0 + mt * 16 + g;
            int c = bn + n0 + nt * 8 + 2 * t;
            float bx = bias[c], by = bias[c + 1];
            float2 v0 = make_float2(acc[mt][nt][0] + bx, acc[mt][nt][1] + by);
            float2 v1 = make_float2(acc[mt][nt][2] + bx, acc[mt][nt][3] + by);
            if (mode == 0) {
                *(float2*)(Cout + (size_t)r * HDIM + c) = v0;
                *(float2*)(Cout + (size_t)(r + 8) * HDIM + c) = v1;
            } else if (mode == 1) {
                // K: [bh][seq][PADK], d columns octet-permuted
                int b_ = r >> 10, sr = r & 1023, h_ = c >> 6;
                int d0 = c & 63;
                float* base = Cout + ((size_t)(b_ * NHEAD + h_) * SEQ + sr) * PADK;
                int p0 = operm(d0), p1 = operm(d0 + 1);
                base[p0] = v0.x; base[p1] = v0.y;
                base += (size_t)8 * PADK;
                base[p0] = v1.x; base[p1] = v1.y;
            } else {
                // V^T: [bh][kb][d][PADVT], k columns octet-permuted
                int b_ = r >> 10, sr = r & 1023, h_ = c >> 6;
                int kb = sr >> 5, kin = sr & 31, d0 = c & 63;
                int kp = operm(kin);          // operm(kin+8) == kp + 8
                float* base = Cout +
                    (((size_t)(b_ * NHEAD + h_) * (SEQ / KB) + kb) * DHEAD) * PADVT;
                base[(size_t)d0 * PADVT + kp]           = v0.x;
                base[(size_t)(d0 + 1) * PADVT + kp]     = v0.y;
                base[(size_t)d0 * PADVT + kp + 8]       = v1.x;
                base[(size_t)(d0 + 1) * PADVT + kp + 8] = v1.y;
            }
        }
    }
}

__global__ void __launch_bounds__(256, 2)
qkv_gemm_kernel(const float* __restrict__ ipb)
{
    extern __shared__ uint32_t smem_g[];
    const int z = blockIdx.z;
    float* outp = (z == 0) ? g_q : (z == 1) ? g_kpad : g_vt;
    gemm_core(g_inh, g_inl, AIR, z * ROWS,
              g_wh, g_wl, WR, z * HDIM,
              ipb + z * HDIM, outp, z, smem_g);
}

__global__ void __launch_bounds__(256, 2)
outproj_kernel(const float* __restrict__ outb, float* __restrict__ out)
{
    extern __shared__ uint32_t smem_g[];
    gemm_core(g_ah, g_al, ROWS, 0,
              g_wh, g_wl, WR, 3 * HDIM,
              outb, out, 0, smem_g);
}

// ============================================================================
// TF32 flash attention, bulk 2-stage; vectorized fragment loads.
// Stage words: K[32x72] | V^T[64x40] | bias[32x132] | mask[128x40]
// ============================================================================
#define QB 128
#define PADB 132
#define PADM 40
#define ST_V (KB*PADK)                          // 2304
#define ST_B (ST_V + DHEAD*PADVT)               // 2304+2560 = 4864
#define ST_M (ST_B + KB*PADB)                   // 9088
#define ST_WORDS (ST_M + QB*PADM)               // 14208
#define ATTN_TX (KB*PADK*4 + DHEAD*PADVT*4 + KB*512 + QB*128)   // 52224
#define ATTN_SMEM (2 * ST_WORDS * 4 + 16)

__device__ __forceinline__ uint32_t f2tf32(float f) {
    uint32_t r;
    asm("cvt.rna.tf32.f32 %0, %1;" : "=r"(r) : "f"(f));
    return r;
}

__device__ __forceinline__ void mma_tf32(float c[4],
    uint32_t a0, uint32_t a1, uint32_t a2, uint32_t a3,
    uint32_t b0, uint32_t b1)
{
    asm volatile(
        "mma.sync.aligned.m16n8k8.row.col.f32.tf32.tf32.f32 "
        "{%0,%1,%2,%3}, {%4,%5,%6,%7}, {%8,%9}, {%0,%1,%2,%3};"
        : "+f"(c[0]), "+f"(c[1]), "+f"(c[2]), "+f"(c[3])
        : "r"(a0), "r"(a1), "r"(a2), "r"(a3), "r"(b0), "r"(b1));
}

__global__ void __launch_bounds__(256, 2)
attn_mma_kernel(const float* __restrict__ kern,
                const uint32_t* __restrict__ amask, float scale)
{
    extern __shared__ float sm[];
    const uint32_t sbase = (uint32_t)__cvta_generic_to_shared(sm);
    const uint32_t mb0 = sbase + 2u * ST_WORDS * 4u;
    const uint32_t mb1 = mb0 + 8u;

    const int bh = blockIdx.y, b = bh >> 3, h = bh & 7;
    const int qb = blockIdx.x * QB;
    const int tid  = threadIdx.x;
    const int w    = tid >> 5;
    const int lane = tid & 31;
    const int g = lane >> 2, t = lane & 3;

    const float* Qg = g_q + (size_t)b * SEQ * HDIM + h * DHEAD;
    const float* Kp = g_kpad + (size_t)bh * SEQ * PADK;
    const float* Vt = g_vt + (size_t)bh * (SEQ / KB) * DHEAD * PADVT;
    const float* kern_bh = kern + (size_t)bh * SEQ * SEQ;
    const uint32_t* mask_bh = amask + (size_t)bh * SEQ * SEQ;

    if (tid == 0) { mbar_init(mb0, 1); mbar_init(mb1, 1); }
    fence_async_init();
    __syncthreads();

    auto issue = [&](int ss, int kb) {
        const uint32_t base = sbase + (uint32_t)(ss * ST_WORDS) * 4u;
        const uint32_t mb = ss ? mb1 : mb0;
        if (tid == 0)
            bulk_g2s(base, Kp + (size_t)kb * KB * PADK, KB * PADK * 4u, mb);
        else if (tid == 1)
            bulk_g2s(base + ST_V * 4u, Vt + (size_t)kb * DHEAD * PADVT,
                     DHEAD * PADVT * 4u, mb);
        else if (tid >= 32 && tid < 64) {
            int r = tid - 32;
            bulk_g2s(base + (uint32_t)(ST_B + r * PADB) * 4u,
                     kern_bh + (size_t)(kb * KB + r) * SEQ + qb, 512u, mb);
        } else if (tid >= 64 && tid < 192) {
            int r = tid - 64;
            bulk_g2s(base + (uint32_t)(ST_M + r * PADM) * 4u,
                     mask_bh + (size_t)(qb + r) * SEQ + kb * KB, 128u, mb);
        }
    };

    if (tid == 0) mbar_expect(mb0, ATTN_TX);
    __syncthreads();
    issue(0, 0);

    uint32_t qa[8][4];
    {
        const float* Qr0 = Qg + (size_t)(qb + w * 16 + g) * HDIM;
        const float* Qr1 = Qr0 + 8 * (size_t)HDIM;
#pragma unroll
        for (int k = 0; k < 8; k++) {
            qa[k][0] = f2tf32(Qr0[k * 8 + t]);
            qa[k][1] = f2tf32(Qr1[k * 8 + t]);
            qa[k][2] = f2tf32(Qr0[k * 8 + t + 4]);
            qa[k][3] = f2tf32(Qr1[k * 8 + t + 4]);
        }
    }

    float o[8][4];
#pragma unroll
    for (int f = 0; f < 8; f++)
#pragma unroll
        for (int u = 0; u < 4; u++) o[f][u] = 0.f;
    float m_[2] = {-1e30f, -1e30f}, l_[2] = {0.f, 0.f};

    const int NT = SEQ / KB;
    for (int kb = 0; kb < NT; kb++) {
        const int s = kb & 1;
        if (kb < NT - 1) {
            if (tid == 0) mbar_expect(s ? mb0 : mb1, ATTN_TX);
            __syncthreads();
            issue(s ^ 1, kb + 1);
        }
        mbar_wait(s ? mb1 : mb0, (uint32_t)((kb >> 1) & 1));

        const float* Ks = sm + s * ST_WORDS;
        const float* Vs = Ks + ST_V;
        const float* Bs = Ks + ST_B;
        const uint32_t* Ms = (const uint32_t*)(Ks + ST_M);

        // ---- S = Q K^T (K b-frags: one LDS.64 per (k,f)) ----
        float sc[4][4];
#pragma unroll
        for (int f = 0; f < 4; f++)
#pragma unroll
            for (int u = 0; u < 4; u++) sc[f][u] = 0.f;
#pragma unroll
        for (int k = 0; k < 8; k++) {
#pragma unroll
            for (int f = 0; f < 4; f++) {
                float2 kv = *(const float2*)&Ks[(f * 8 + g) * PADK + k * 8 + 2 * t];
                mma_tf32(sc[f], qa[k][0], qa[k][1], qa[k][2], qa[k][3],
                         __float_as_uint(kv.x), __float_as_uint(kv.y));
            }
        }

        // ---- scale + bias + mask (uint2) + online softmax ----
#pragma unroll
        for (int e = 0; e < 2; e++) {
            const int qrl = w * 16 + g + e * 8;
            const uint2* Mrow = (const uint2*)(Ms + qrl * PADM);
            float rmax = -1e30f;
#pragma unroll
            for (int f = 0; f < 4; f++) {
                uint2 mw = Mrow[f * 4 + t];
                int kc = f * 8 + 2 * t;
                float s0 = sc[f][e * 2 + 0] * scale + Bs[kc * PADB + qrl];
                float s1 = sc[f][e * 2 + 1] * scale + Bs[(kc + 1) * PADB + qrl];
                s0 = mw.x ? -1e30f : s0;
                s1 = mw.y ? -1e30f : s1;
                sc[f][e * 2 + 0] = s0;
                sc[f][e * 2 + 1] = s1;
                rmax = fmaxf(rmax, fmaxf(s0, s1));
            }
            rmax = fmaxf(rmax, __shfl_xor_sync(0xffffffffu, rmax, 1));
            rmax = fmaxf(rmax, __shfl_xor_sync(0xffffffffu, rmax, 2));
            float mn = fmaxf(m_[e], rmax);
            float fe = __expf(m_[e] - mn);
            float ps = 0.f;
#pragma unroll
            for (int f = 0; f < 4; f++) {
#pragma unroll
                for (int u = 0; u < 2; u++) {
                    float sv = sc[f][e * 2 + u];
                    float p = (sv <= -1e29f) ? 0.f : __expf(sv - mn);
                    sc[f][e * 2 + u] = p;
                    ps += p;
                }
            }
            ps += __shfl_xor_sync(0xffffffffu, ps, 1);
            ps += __shfl_xor_sync(0xffffffffu, ps, 2);
            l_[e] = l_[e] * fe + ps;
            m_[e] = mn;
#pragma unroll
            for (int f = 0; f < 4; f++) {
                o[2 * f][e * 2 + 0] *= fe;     o[2 * f][e * 2 + 1] *= fe;
                o[2 * f + 1][e * 2 + 0] *= fe; o[2 * f + 1][e * 2 + 1] *= fe;
            }
        }

        // ---- O += P @ V (V^T b-frags: one LDS.64 per (kk,f)) ----
#pragma unroll
        for (int kk = 0; kk < 4; kk++) {
            const int src = g * 4 + (t >> 1);
            float p00 = __shfl_sync(0xffffffffu, sc[kk][0], src);
            float p01 = __shfl_sync(0xffffffffu, sc[kk][1], src);
            float p02 = __shfl_sync(0xffffffffu, sc[kk][0], src + 2);
            float p03 = __shfl_sync(0xffffffffu, sc[kk][1], src + 2);
            float p10 = __shfl_sync(0xffffffffu, sc[kk][2], src);
            float p11 = __shfl_sync(0xffffffffu, sc[kk][3], src);
            float p12 = __shfl_sync(0xffffffffu, sc[kk][2], src + 2);
            float p13 = __shfl_sync(0xffffffffu, sc[kk][3], src + 2);
            const bool odd = (t & 1);
            uint32_t a0 = f2tf32(odd ? p01 : p00);
            uint32_t a1 = f2tf32(odd ? p11 : p10);
            uint32_t a2 = f2tf32(odd ? p03 : p02);
            uint32_t a3 = f2tf32(odd ? p13 : p12);
#pragma unroll
            for (int f = 0; f < 8; f++) {
                float2 vv = *(const float2*)&Vs[(f * 8 + g) * PADVT + kk * 8 + 2 * t];
                mma_tf32(o[f], a0, a1, a2, a3,
                         __float_as_uint(vv.x), __float_as_uint(vv.y));
            }
        }
    }

    // ---- normalize + write hi/lo bf16 in outproj's tiled layout ----
#pragma unroll
    for (int e = 0; e < 2; e++) {
        float inv = 1.0f / l_[e];
        int qrl = w * 16 + g + e * 8;
        size_t grow = (size_t)b * SEQ + qb + qrl;
#pragma unroll
        for (int f = 0; f < 8; f++) {
            float x = o[f][e * 2 + 0] * inv;
            float y = o[f][e * 2 + 1] * inv;
            __nv_bfloat16 hx = __float2bfloat16_rn(x);
            __nv_bfloat16 hy = __float2bfloat16_rn(y);
            __nv_bfloat16 lx = __float2bfloat16_rn(x - __bfloat162float(hx));
            __nv_bfloat16 ly = __float2bfloat16_rn(y - __bfloat162float(hy));
            __nv_bfloat162 hp(hx, hy), lp(lx, ly);
            int c = h * DHEAD + f * 8 + 2 * t;
            int kt = c >> 5, km = c & 31;
            size_t off = ((size_t)kt * ROWS + grow) * RSTR + km;
            *(uint32_t*)(g_ah + off) = *(uint32_t*)&hp;
            *(uint32_t*)(g_al + off) = *(uint32_t*)&lp;
        }
    }
}

// ============================================================================
// Launch
// ============================================================================
extern "C" void kernel_launch(void* const* d_in, const int* in_sizes, int n_in,
                              void* d_out, int out_size)
{
    const float* query    = (const float*)d_in[0];
    const float* key_     = (const float*)d_in[1];
    const float* value    = (const float*)d_in[2];
    const uint32_t* amask = (const uint32_t*)d_in[3];
    const float* kern     = (const float*)d_in[5];
    const float* ipw      = (const float*)d_in[6];
    const float* ipb      = (const float*)d_in[7];
    const float* outw     = (const float*)d_in[8];
    const float* outb     = (const float*)d_in[9];
    float* out = (float*)d_out;

    cudaFuncSetAttribute(attn_mma_kernel,
                         cudaFuncAttributeMaxDynamicSharedMemorySize, ATTN_SMEM);
    cudaFuncSetAttribute(qkv_gemm_kernel,
                         cudaFuncAttributeMaxDynamicSharedMemorySize, GEMM_SMEM);
    cudaFuncSetAttribute(outproj_kernel,
                         cudaFuncAttributeMaxDynamicSharedMemorySize, GEMM_SMEM);

    split_in_kernel<<<3 * ROWS * 64 / 256, 256>>>(query, key_, value);
    split_w_kernel<<<WR * 64 / 256, 256>>>(ipw, outw);

    dim3 gq(HDIM / TBN, ROWS / TBM, 3);
    qkv_gemm_kernel<<<gq, 256, GEMM_SMEM>>>(ipb);

    dim3 ga(SEQ / QB, BATCH * NHEAD, 1);
    attn_mma_kernel<<<ga, 256, ATTN_SMEM>>>(kern, amask, 0.125f);

    dim3 go(HDIM / TBN, ROWS / TBM, 1);
    outproj_kernel<<<go, 256, GEMM_SMEM>>>(outb, out);
}

// round 11
// speedup vs baseline: 4.1407x; 1.0868x over previous
#include <cuda_runtime.h>
#include <cuda_bf16.h>
#include <cuda_fp16.h>
#include <cstdint>

// ----------------------------------------------------------------------------
// PositionAttention: B=4, L=1024, HD=512, H=8, D=64
// Round 11: attention -> fp16 m16n8k16 MMA. P feeds PV directly from the S
// C-fragment (half2 packs, no shuffle transpose); K / V^T stored fp16 natural
// layout by the qkv GEMM epilogue. GEMMs unchanged (bf16x3 + bulk pipeline).
// ----------------------------------------------------------------------------

#define BATCH 4
#define SEQ   1024
#define HDIM  512
#define NHEAD 8
#define DHEAD 64
#define ROWS  (BATCH*SEQ)          // 4096

#define RSTR 40                    // bf16 per tiled row (32 data + 8 pad)
#define NKT  (HDIM/32)             // 16 k-tiles
#define AIR  (3*ROWS)
#define WR   2048

#define KB    32
#define PADKH 72                   // K row stride in fp16 (36 words: conflict-free)
#define PADVTH 40                  // V^T row stride in fp16 (20 words: conflict-free)

// scratch (allocation-free device globals)
__device__ __align__(16) float  g_q[ROWS * HDIM];
__device__ __align__(16) __half g_kh[(size_t)BATCH*NHEAD*SEQ*PADKH];
__device__ __align__(16) __half g_vth[(size_t)BATCH*NHEAD*(SEQ/KB)*DHEAD*PADVTH];
__device__ __align__(16) __nv_bfloat16 g_inh[(size_t)NKT*AIR*RSTR];
__device__ __align__(16) __nv_bfloat16 g_inl[(size_t)NKT*AIR*RSTR];
__device__ __align__(16) __nv_bfloat16 g_wh[(size_t)NKT*WR*RSTR];
__device__ __align__(16) __nv_bfloat16 g_wl[(size_t)NKT*WR*RSTR];
__device__ __align__(16) __nv_bfloat16 g_ah[(size_t)NKT*ROWS*RSTR];
__device__ __align__(16) __nv_bfloat16 g_al[(size_t)NKT*ROWS*RSTR];

// ============================================================================
// mbarrier / bulk-copy primitives
// ============================================================================
__device__ __forceinline__ void mbar_init(uint32_t a, uint32_t cnt) {
    asm volatile("mbarrier.init.shared.b64 [%0], %1;" :: "r"(a), "r"(cnt) : "memory");
}
__device__ __forceinline__ void mbar_expect(uint32_t a, uint32_t bytes) {
    asm volatile("mbarrier.arrive.expect_tx.shared.b64 _, [%0], %1;"
                 :: "r"(a), "r"(bytes) : "memory");
}
__device__ __forceinline__ void mbar_wait(uint32_t a, uint32_t parity) {
    asm volatile(
        "{\n\t.reg .pred P;\n\t"
        "WAIT_%=:\n\t"
        "mbarrier.try_wait.parity.acquire.cta.shared::cta.b64 P, [%0], %1, 0x989680;\n\t"
        "@P bra.uni DONE_%=;\n\t"
        "bra.uni WAIT_%=;\n\t"
        "DONE_%=:\n\t}"
        :: "r"(a), "r"(parity) : "memory");
}
__device__ __forceinline__ void bulk_g2s(uint32_t dst, const void* src,
                                         uint32_t bytes, uint32_t mbar) {
    asm volatile(
        "cp.async.bulk.shared::cta.global.mbarrier::complete_tx::bytes "
        "[%0], [%1], %2, [%3];"
        :: "r"(dst), "l"(src), "r"(bytes), "r"(mbar) : "memory");
}
__device__ __forceinline__ void fence_async_init() {
    asm volatile("fence.proxy.async.shared::cta;" ::: "memory");
}

// ============================================================================
// split kernels (unchanged)
// ============================================================================
__device__ __forceinline__ void split8(const float* src, uint4& hw, uint4& lw)
{
    float4 a = *(const float4*)src;
    float4 b = *(const float4*)(src + 4);
    float v[8] = {a.x, a.y, a.z, a.w, b.x, b.y, b.z, b.w};
    uint32_t h[4], l[4];
#pragma unroll
    for (int i = 0; i < 4; i++) {
        __nv_bfloat16 h0 = __float2bfloat16_rn(v[2*i]);
        __nv_bfloat16 h1 = __float2bfloat16_rn(v[2*i+1]);
        __nv_bfloat16 l0 = __float2bfloat16_rn(v[2*i]   - __bfloat162float(h0));
        __nv_bfloat16 l1 = __float2bfloat16_rn(v[2*i+1] - __bfloat162float(h1));
        __nv_bfloat162 hp(h0, h1), lp(l0, l1);
        h[i] = *(uint32_t*)&hp; l[i] = *(uint32_t*)&lp;
    }
    hw = make_uint4(h[0], h[1], h[2], h[3]);
    lw = make_uint4(l[0], l[1], l[2], l[3]);
}

__global__ void __launch_bounds__(256)
split_in_kernel(const float* __restrict__ q, const float* __restrict__ k,
                const float* __restrict__ v)
{
    size_t i = (size_t)blockIdx.x * 256 + threadIdx.x;
    int mat = (int)(i / (ROWS * 64));
    size_t rem = i - (size_t)mat * (ROWS * 64);
    int r = (int)(rem >> 6);
    int kk = ((int)rem & 63) * 8;
    int kt = kk >> 5, km = kk & 31;
    const float* src = (mat == 0 ? q : mat == 1 ? k : v) + ((size_t)r << 9) + kk;
    uint4 hw, lw; split8(src, hw, lw);
    size_t d = ((size_t)kt * AIR + (size_t)mat * ROWS + r) * RSTR + km;
    *(uint4*)(g_inh + d) = hw;
    *(uint4*)(g_inl + d) = lw;
}

__global__ void __launch_bounds__(256)
split_w_kernel(const float* __restrict__ ipw, const float* __restrict__ outw)
{
    size_t i = (size_t)blockIdx.x * 256 + threadIdx.x;
    int r = (int)(i >> 6);
    int kk = ((int)i & 63) * 8;
    int kt = kk >> 5, km = kk & 31;
    const float* src = (r < 1536) ? (ipw + ((size_t)r << 9) + kk)
                                  : (outw + ((size_t)(r - 1536) << 9) + kk);
    uint4 hw, lw; split8(src, hw, lw);
    size_t d = ((size_t)kt * WR + r) * RSTR + km;
    *(uint4*)(g_wh + d) = hw;
    *(uint4*)(g_wl + d) = lw;
}

// ============================================================================
// bf16x3 GEMM, bulk 2-stage (mainloop unchanged).
// Epilogue modes: 0 = plain fp32 [r][512]
//                 1 = K fp16: [bh][seq][PADKH], natural d order
//                 2 = V^T fp16: [bh][kb][d][PADVTH], natural k order
// ============================================================================
#define TBM 128
#define TBN 128
#define MATW (TBM * RSTR / 2)
#define GSTW (4 * MATW)
#define GEMM_SMEM (2 * GSTW * 4 + 16)

__device__ __forceinline__ void mma_bf16(float c[4],
    uint32_t a0, uint32_t a1, uint32_t a2, uint32_t a3,
    uint32_t b0, uint32_t b1)
{
    asm volatile(
        "mma.sync.aligned.m16n8k16.row.col.f32.bf16.bf16.f32 "
        "{%0,%1,%2,%3}, {%4,%5,%6,%7}, {%8,%9}, {%0,%1,%2,%3};"
        : "+f"(c[0]), "+f"(c[1]), "+f"(c[2]), "+f"(c[3])
        : "r"(a0), "r"(a1), "r"(a2), "r"(a3), "r"(b0), "r"(b1));
}

__device__ __forceinline__ void gemm_core(
    const __nv_bfloat16* __restrict__ Ah, const __nv_bfloat16* __restrict__ Al,
    int AR, int arow0,
    const __nv_bfloat16* __restrict__ Bh, const __nv_bfloat16* __restrict__ Bl,
    int BR, int brow0,
    const float* __restrict__ bias, void* __restrict__ Cout, int mode,
    uint32_t* smem)
{
    const int tid  = threadIdx.x;
    const int w    = tid >> 5;
    const int lane = tid & 31;
    const int g = lane >> 2, t = lane & 3;
    const int wm = w >> 2, wn = w & 3;
    const int m0 = wm * 64, n0 = wn * 32;
    const int bm = blockIdx.y * TBM;
    const int bn = blockIdx.x * TBN;
    const uint32_t sbase = (uint32_t)__cvta_generic_to_shared(smem);
    const uint32_t mb0 = sbase + 2u * GSTW * 4u;
    const uint32_t mb1 = mb0 + 8u;
    const uint32_t STB = GSTW * 4u;

    float acc[4][4][4];
#pragma unroll
    for (int mt = 0; mt < 4; mt++)
#pragma unroll
        for (int nt = 0; nt < 4; nt++)
#pragma unroll
            for (int u = 0; u < 4; u++) acc[mt][nt][u] = 0.f;

    if (tid == 0) { mbar_init(mb0, 1); mbar_init(mb1, 1); }
    fence_async_init();
    __syncthreads();

    auto issue = [&](int ss, int kt) {
        const uint32_t base = sbase + (uint32_t)ss * GSTW * 4u;
        const uint32_t mb = ss ? mb1 : mb0;
        if (tid < 4) {
            const __nv_bfloat16* src;
            size_t off;
            if (tid < 2) {
                src = tid ? Al : Ah;
                off = ((size_t)kt * AR + arow0 + bm) * RSTR;
            } else {
                src = (tid == 2) ? Bh : Bl;
                off = ((size_t)kt * BR + brow0 + bn) * RSTR;
            }
            bulk_g2s(base + (uint32_t)tid * MATW * 4u, src + off, MATW * 4u, mb);
        }
    };

    if (tid == 0) mbar_expect(mb0, STB);
    __syncthreads();
    issue(0, 0);

    for (int kt = 0; kt < NKT; kt++) {
        const int s = kt & 1;
        if (kt < NKT - 1) {
            if (tid == 0) mbar_expect(s ? mb0 : mb1, STB);
            __syncthreads();
            issue(s ^ 1, kt + 1);
        }
        mbar_wait(s ? mb1 : mb0, (uint32_t)((kt >> 1) & 1));

        const uint32_t* Sw  = smem + s * GSTW;
        const uint32_t* AhW = Sw;
        const uint32_t* AlW = Sw + MATW;
        const uint32_t* BhW = Sw + 2 * MATW;
        const uint32_t* BlW = Sw + 3 * MATW;

#pragma unroll
        for (int ks = 0; ks < 2; ks++) {
            uint32_t bhf[4][2], blf[4][2];
#pragma unroll
            for (int nt = 0; nt < 4; nt++) {
                int wb = (n0 + nt * 8 + g) * (RSTR / 2) + ks * 8 + t;
                bhf[nt][0] = BhW[wb]; bhf[nt][1] = BhW[wb + 4];
                blf[nt][0] = BlW[wb]; blf[nt][1] = BlW[wb + 4];
            }
#pragma unroll
            for (int mt = 0; mt < 4; mt++) {
                int wa = (m0 + mt * 16 + g) * (RSTR / 2) + ks * 8 + t;
                uint32_t ah0 = AhW[wa],     ah1 = AhW[wa + 8 * (RSTR / 2)];
                uint32_t ah2 = AhW[wa + 4], ah3 = AhW[wa + 8 * (RSTR / 2) + 4];
                uint32_t al0 = AlW[wa],     al1 = AlW[wa + 8 * (RSTR / 2)];
                uint32_t al2 = AlW[wa + 4], al3 = AlW[wa + 8 * (RSTR / 2) + 4];
#pragma unroll
                for (int nt = 0; nt < 4; nt++) {
                    mma_bf16(acc[mt][nt], ah0, ah1, ah2, ah3, bhf[nt][0], bhf[nt][1]);
                    mma_bf16(acc[mt][nt], ah0, ah1, ah2, ah3, blf[nt][0], blf[nt][1]);
                    mma_bf16(acc[mt][nt], al0, al1, al2, al3, bhf[nt][0], bhf[nt][1]);
                }
            }
        }
    }

    // epilogue
#pragma unroll
    for (int mt = 0; mt < 4; mt++) {
#pragma unroll
        for (int nt = 0; nt < 4; nt++) {
            int r = bm + m0 + mt * 16 + g;
            int c = bn + n0 + nt * 8 + 2 * t;
            float bx = bias[c], by = bias[c + 1];
            float2 v0 = make_float2(acc[mt][nt][0] + bx, acc[mt][nt][1] + by);
            float2 v1 = make_float2(acc[mt][nt][2] + bx, acc[mt][nt][3] + by);
            if (mode == 0) {
                float* C = (float*)Cout;
                *(float2*)(C + (size_t)r * HDIM + c) = v0;
                *(float2*)(C + (size_t)(r + 8) * HDIM + c) = v1;
            } else if (mode == 1) {
                // K fp16: [bh][seq][PADKH], natural d order
                int b_ = r >> 10, sr = r & 1023, h_ = c >> 6, d0 = c & 63;
                __half* base = (__half*)Cout +
                    ((size_t)(b_ * NHEAD + h_) * SEQ + sr) * PADKH + d0;
                *(__half2*)base = __floats2half2_rn(v0.x, v0.y);
                *(__half2*)(base + (size_t)8 * PADKH) = __floats2half2_rn(v1.x, v1.y);
            } else {
                // V^T fp16: [bh][kb][d][PADVTH], natural k order
                int b_ = r >> 10, sr = r & 1023, h_ = c >> 6;
                int kb = sr >> 5, kin = sr & 31, d0 = c & 63;
                __half* base = (__half*)Cout +
                    (((size_t)(b_ * NHEAD + h_) * (SEQ / KB) + kb) * DHEAD) * PADVTH;
                base[(size_t)d0 * PADVTH + kin]           = __float2half_rn(v0.x);
                base[(size_t)(d0 + 1) * PADVTH + kin]     = __float2half_rn(v0.y);
                base[(size_t)d0 * PADVTH + kin + 8]       = __float2half_rn(v1.x);
                base[(size_t)(d0 + 1) * PADVTH + kin + 8] = __float2half_rn(v1.y);
            }
        }
    }
}

__global__ void __launch_bounds__(256, 2)
qkv_gemm_kernel(const float* __restrict__ ipb)
{
    extern __shared__ uint32_t smem_g[];
    const int z = blockIdx.z;
    void* outp = (z == 0) ? (void*)g_q : (z == 1) ? (void*)g_kh : (void*)g_vth;
    gemm_core(g_inh, g_inl, AIR, z * ROWS,
              g_wh, g_wl, WR, z * HDIM,
              ipb + z * HDIM, outp, z, smem_g);
}

__global__ void __launch_bounds__(256, 2)
outproj_kernel(const float* __restrict__ outb, float* __restrict__ out)
{
    extern __shared__ uint32_t smem_g[];
    gemm_core(g_ah, g_al, ROWS, 0,
              g_wh, g_wl, WR, 3 * HDIM,
              outb, out, 0, smem_g);
}

// ============================================================================
// fp16 flash attention, bulk 2-stage.
// Stage bytes: K[32x72 h] | V^T[64x40 h] | bias[32x132 f32] | mask[128x40 w]
// ============================================================================
#define QB 128
#define PADB 132
#define PADM 40
#define ST_V 4608                               // K bytes: 32*72*2
#define ST_B (ST_V + 5120)                      // V bytes: 64*40*2 -> 9728
#define ST_M (ST_B + KB*PADB*4)                 // 9728+16896 = 26624
#define ST_BYTES (ST_M + QB*PADM*4)             // 26624+20480 = 47104
#define ATTN_TX (4608 + 5120 + KB*512 + QB*128) // 42496
#define ATTN_SMEM (2 * ST_BYTES + 16)

__device__ __forceinline__ void mma_f16(float c[4],
    uint32_t a0, uint32_t a1, uint32_t a2, uint32_t a3,
    uint32_t b0, uint32_t b1)
{
    asm volatile(
        "mma.sync.aligned.m16n8k16.row.col.f32.f16.f16.f32 "
        "{%0,%1,%2,%3}, {%4,%5,%6,%7}, {%8,%9}, {%0,%1,%2,%3};"
        : "+f"(c[0]), "+f"(c[1]), "+f"(c[2]), "+f"(c[3])
        : "r"(a0), "r"(a1), "r"(a2), "r"(a3), "r"(b0), "r"(b1));
}

__device__ __forceinline__ uint32_t packh2(float x, float y) {
    __half2 h = __floats2half2_rn(x, y);
    return *(uint32_t*)&h;
}

__global__ void __launch_bounds__(256, 2)
attn_mma_kernel(const float* __restrict__ kern,
                const uint32_t* __restrict__ amask, float scale)
{
    extern __shared__ char smc[];
    const uint32_t sbase = (uint32_t)__cvta_generic_to_shared(smc);
    const uint32_t mb0 = sbase + 2u * ST_BYTES;
    const uint32_t mb1 = mb0 + 8u;

    const int bh = blockIdx.y, b = bh >> 3, h = bh & 7;
    const int qb = blockIdx.x * QB;
    const int tid  = threadIdx.x;
    const int w    = tid >> 5;
    const int lane = tid & 31;
    const int g = lane >> 2, t = lane & 3;

    const float*  Qg = g_q + (size_t)b * SEQ * HDIM + h * DHEAD;
    const __half* Kp = g_kh + (size_t)bh * SEQ * PADKH;
    const __half* Vt = g_vth + (size_t)bh * (SEQ / KB) * DHEAD * PADVTH;
    const float* kern_bh = kern + (size_t)bh * SEQ * SEQ;
    const uint32_t* mask_bh = amask + (size_t)bh * SEQ * SEQ;

    if (tid == 0) { mbar_init(mb0, 1); mbar_init(mb1, 1); }
    fence_async_init();
    __syncthreads();

    auto issue = [&](int ss, int kb) {
        const uint32_t base = sbase + (uint32_t)ss * ST_BYTES;
        const uint32_t mb = ss ? mb1 : mb0;
        if (tid == 0)
            bulk_g2s(base, Kp + (size_t)kb * KB * PADKH, 4608u, mb);
        else if (tid == 1)
            bulk_g2s(base + ST_V, Vt + (size_t)kb * DHEAD * PADVTH, 5120u, mb);
        else if (tid >= 32 && tid < 64) {
            int r = tid - 32;
            bulk_g2s(base + (uint32_t)(ST_B + r * PADB * 4),
                     kern_bh + (size_t)(kb * KB + r) * SEQ + qb, 512u, mb);
        } else if (tid >= 64 && tid < 192) {
            int r = tid - 64;
            bulk_g2s(base + (uint32_t)(ST_M + r * PADM * 4),
                     mask_bh + (size_t)(qb + r) * SEQ + kb * KB, 128u, mb);
        }
    };

    if (tid == 0) mbar_expect(mb0, ATTN_TX);
    __syncthreads();
    issue(0, 0);

    // Q fragments (fp16 pairs) straight from gmem
    uint32_t qa[4][4];
    {
        const float* Qr0 = Qg + (size_t)(qb + w * 16 + g) * HDIM;
        const float* Qr1 = Qr0 + 8 * (size_t)HDIM;
#pragma unroll
        for (int kk = 0; kk < 4; kk++) {
            int d0 = 16 * kk + 2 * t;
            float2 x0 = *(const float2*)(Qr0 + d0);
            float2 x1 = *(const float2*)(Qr1 + d0);
            float2 x2 = *(const float2*)(Qr0 + d0 + 8);
            float2 x3 = *(const float2*)(Qr1 + d0 + 8);
            qa[kk][0] = packh2(x0.x, x0.y);
            qa[kk][1] = packh2(x1.x, x1.y);
            qa[kk][2] = packh2(x2.x, x2.y);
            qa[kk][3] = packh2(x3.x, x3.y);
        }
    }

    float o[8][4];
#pragma unroll
    for (int f = 0; f < 8; f++)
#pragma unroll
        for (int u = 0; u < 4; u++) o[f][u] = 0.f;
    float m_[2] = {-1e30f, -1e30f}, l_[2] = {0.f, 0.f};

    const int NT = SEQ / KB;
    for (int kb = 0; kb < NT; kb++) {
        const int s = kb & 1;
        if (kb < NT - 1) {
            if (tid == 0) mbar_expect(s ? mb0 : mb1, ATTN_TX);
            __syncthreads();
            issue(s ^ 1, kb + 1);
        }
        mbar_wait(s ? mb1 : mb0, (uint32_t)((kb >> 1) & 1));

        const char* Sb = smc + (size_t)s * ST_BYTES;
        const __half* Ks = (const __half*)Sb;
        const __half* Vs = (const __half*)(Sb + ST_V);
        const float*  Bs = (const float*)(Sb + ST_B);
        const uint32_t* Ms = (const uint32_t*)(Sb + ST_M);

        // ---- S = Q K^T : fp16 m16n8k16, 16 MMAs ----
        float sc[4][4];
#pragma unroll
        for (int f = 0; f < 4; f++)
#pragma unroll
            for (int u = 0; u < 4; u++) sc[f][u] = 0.f;
#pragma unroll
        for (int kk = 0; kk < 4; kk++) {
#pragma unroll
            for (int f = 0; f < 4; f++) {
                const __half* kr = Ks + (f * 8 + g) * PADKH + 16 * kk + 2 * t;
                uint32_t b0 = *(const uint32_t*)kr;
                uint32_t b1 = *(const uint32_t*)(kr + 8);
                mma_f16(sc[f], qa[kk][0], qa[kk][1], qa[kk][2], qa[kk][3], b0, b1);
            }
        }

        // ---- scale + bias + mask + online softmax ----
#pragma unroll
        for (int e = 0; e < 2; e++) {
            const int qrl = w * 16 + g + e * 8;
            const uint2* Mrow = (const uint2*)(Ms + qrl * PADM);
            float rmax = -1e30f;
#pragma unroll
            for (int f = 0; f < 4; f++) {
                uint2 mw = Mrow[f * 4 + t];
                int kc = f * 8 + 2 * t;
                float s0 = sc[f][e * 2 + 0] * scale + Bs[kc * PADB + qrl];
                float s1 = sc[f][e * 2 + 1] * scale + Bs[(kc + 1) * PADB + qrl];
                s0 = mw.x ? -1e30f : s0;
                s1 = mw.y ? -1e30f : s1;
                sc[f][e * 2 + 0] = s0;
                sc[f][e * 2 + 1] = s1;
                rmax = fmaxf(rmax, fmaxf(s0, s1));
            }
            rmax = fmaxf(rmax, __shfl_xor_sync(0xffffffffu, rmax, 1));
            rmax = fmaxf(rmax, __shfl_xor_sync(0xffffffffu, rmax, 2));
            float mn = fmaxf(m_[e], rmax);
            float fe = __expf(m_[e] - mn);
            float ps = 0.f;
#pragma unroll
            for (int f = 0; f < 4; f++) {
#pragma unroll
                for (int u = 0; u < 2; u++) {
                    float sv = sc[f][e * 2 + u];
                    float p = (sv <= -1e29f) ? 0.f : __expf(sv - mn);
                    sc[f][e * 2 + u] = p;
                    ps += p;
                }
            }
            ps += __shfl_xor_sync(0xffffffffu, ps, 1);
            ps += __shfl_xor_sync(0xffffffffu, ps, 2);
            l_[e] = l_[e] * fe + ps;
            m_[e] = mn;
#pragma unroll
            for (int f = 0; f < 4; f++) {
                o[2 * f][e * 2 + 0] *= fe;     o[2 * f][e * 2 + 1] *= fe;
                o[2 * f + 1][e * 2 + 0] *= fe; o[2 * f + 1][e * 2 + 1] *= fe;
            }
        }

        // ---- O += P @ V : P packed straight from C-frags (no shuffle) ----
#pragma unroll
        for (int kk = 0; kk < 2; kk++) {
            uint32_t a0 = packh2(sc[2 * kk][0],     sc[2 * kk][1]);
            uint32_t a1 = packh2(sc[2 * kk][2],     sc[2 * kk][3]);
            uint32_t a2 = packh2(sc[2 * kk + 1][0], sc[2 * kk + 1][1]);
            uint32_t a3 = packh2(sc[2 * kk + 1][2], sc[2 * kk + 1][3]);
#pragma unroll
            for (int f = 0; f < 8; f++) {
                const __half* vr = Vs + (f * 8 + g) * PADVTH + 16 * kk + 2 * t;
                uint32_t b0 = *(const uint32_t*)vr;
                uint32_t b1 = *(const uint32_t*)(vr + 8);
                mma_f16(o[f], a0, a1, a2, a3, b0, b1);
            }
        }
    }

    // ---- normalize + write hi/lo bf16 in outproj's tiled layout ----
#pragma unroll
    for (int e = 0; e < 2; e++) {
        float inv = 1.0f / l_[e];
        int qrl = w * 16 + g + e * 8;
        size_t grow = (size_t)b * SEQ + qb + qrl;
#pragma unroll
        for (int f = 0; f < 8; f++) {
            float x = o[f][e * 2 + 0] * inv;
            float y = o[f][e * 2 + 1] * inv;
            __nv_bfloat16 hx = __float2bfloat16_rn(x);
            __nv_bfloat16 hy = __float2bfloat16_rn(y);
            __nv_bfloat16 lx = __float2bfloat16_rn(x - __bfloat162float(hx));
            __nv_bfloat16 ly = __float2bfloat16_rn(y - __bfloat162float(hy));
            __nv_bfloat162 hp(hx, hy), lp(lx, ly);
            int c = h * DHEAD + f * 8 + 2 * t;
            int kt = c >> 5, km = c & 31;
            size_t off = ((size_t)kt * ROWS + grow) * RSTR + km;
            *(uint32_t*)(g_ah + off) = *(uint32_t*)&hp;
            *(uint32_t*)(g_al + off) = *(uint32_t*)&lp;
        }
    }
}

// ============================================================================
// Launch
// ============================================================================
extern "C" void kernel_launch(void* const* d_in, const int* in_sizes, int n_in,
                              void* d_out, int out_size)
{
    const float* query    = (const float*)d_in[0];
    const float* key_     = (const float*)d_in[1];
    const float* value    = (const float*)d_in[2];
    const uint32_t* amask = (const uint32_t*)d_in[3];
    const float* kern     = (const float*)d_in[5];
    const float* ipw      = (const float*)d_in[6];
    const float* ipb      = (const float*)d_in[7];
    const float* outw     = (const float*)d_in[8];
    const float* outb     = (const float*)d_in[9];
    float* out = (float*)d_out;

    cudaFuncSetAttribute(attn_mma_kernel,
                         cudaFuncAttributeMaxDynamicSharedMemorySize, ATTN_SMEM);
    cudaFuncSetAttribute(qkv_gemm_kernel,
                         cudaFuncAttributeMaxDynamicSharedMemorySize, GEMM_SMEM);
    cudaFuncSetAttribute(outproj_kernel,
                         cudaFuncAttributeMaxDynamicSharedMemorySize, GEMM_SMEM);

    split_in_kernel<<<3 * ROWS * 64 / 256, 256>>>(query, key_, value);
    split_w_kernel<<<WR * 64 / 256, 256>>>(ipw, outw);

    dim3 gq(HDIM / TBN, ROWS / TBM, 3);
    qkv_gemm_kernel<<<gq, 256, GEMM_SMEM>>>(ipb);

    dim3 ga(SEQ / QB, BATCH * NHEAD, 1);
    attn_mma_kernel<<<ga, 256, ATTN_SMEM>>>(kern, amask, 0.125f);

    dim3 go(HDIM / TBN, ROWS / TBM, 1);
    outproj_kernel<<<go, 256, GEMM_SMEM>>>(outb, out);
}

// round 12
// speedup vs baseline: 4.2079x; 1.0162x over previous
#include <cuda_runtime.h>
#include <cuda_bf16.h>
#include <cuda_fp16.h>
#include <cstdint>

// ----------------------------------------------------------------------------
// PositionAttention: B=4, L=1024, HD=512, H=8, D=64
// Round 12: attention instruction diet —
//   * K/V fragment loads via ldmatrix.m8n8.x4 (32 LDS.64 -> 16 LDSM)
//   * scale folded into Q fragments (exact, 2^-3)
//   * bias preloaded into S accumulator init (no post-MMA bias FMA)
// GEMMs / splits unchanged from R11.
// ----------------------------------------------------------------------------

#define BATCH 4
#define SEQ   1024
#define HDIM  512
#define NHEAD 8
#define DHEAD 64
#define ROWS  (BATCH*SEQ)          // 4096

#define RSTR 40                    // bf16 per tiled row (32 data + 8 pad)
#define NKT  (HDIM/32)             // 16 k-tiles
#define AIR  (3*ROWS)
#define WR   2048

#define KB    32
#define PADKH 72                   // K row stride fp16 (144B: 8 distinct 16B banks)
#define PADVTH 40                  // V^T row stride fp16 (80B: 8 distinct 16B banks)

// scratch (allocation-free device globals)
__device__ __align__(16) float  g_q[ROWS * HDIM];
__device__ __align__(16) __half g_kh[(size_t)BATCH*NHEAD*SEQ*PADKH];
__device__ __align__(16) __half g_vth[(size_t)BATCH*NHEAD*(SEQ/KB)*DHEAD*PADVTH];
__device__ __align__(16) __nv_bfloat16 g_inh[(size_t)NKT*AIR*RSTR];
__device__ __align__(16) __nv_bfloat16 g_inl[(size_t)NKT*AIR*RSTR];
__device__ __align__(16) __nv_bfloat16 g_wh[(size_t)NKT*WR*RSTR];
__device__ __align__(16) __nv_bfloat16 g_wl[(size_t)NKT*WR*RSTR];
__device__ __align__(16) __nv_bfloat16 g_ah[(size_t)NKT*ROWS*RSTR];
__device__ __align__(16) __nv_bfloat16 g_al[(size_t)NKT*ROWS*RSTR];

// ============================================================================
// mbarrier / bulk-copy primitives
// ============================================================================
__device__ __forceinline__ void mbar_init(uint32_t a, uint32_t cnt) {
    asm volatile("mbarrier.init.shared.b64 [%0], %1;" :: "r"(a), "r"(cnt) : "memory");
}
__device__ __forceinline__ void mbar_expect(uint32_t a, uint32_t bytes) {
    asm volatile("mbarrier.arrive.expect_tx.shared.b64 _, [%0], %1;"
                 :: "r"(a), "r"(bytes) : "memory");
}
__device__ __forceinline__ void mbar_wait(uint32_t a, uint32_t parity) {
    asm volatile(
        "{\n\t.reg .pred P;\n\t"
        "WAIT_%=:\n\t"
        "mbarrier.try_wait.parity.acquire.cta.shared::cta.b64 P, [%0], %1, 0x989680;\n\t"
        "@P bra.uni DONE_%=;\n\t"
        "bra.uni WAIT_%=;\n\t"
        "DONE_%=:\n\t}"
        :: "r"(a), "r"(parity) : "memory");
}
__device__ __forceinline__ void bulk_g2s(uint32_t dst, const void* src,
                                         uint32_t bytes, uint32_t mbar) {
    asm volatile(
        "cp.async.bulk.shared::cta.global.mbarrier::complete_tx::bytes "
        "[%0], [%1], %2, [%3];"
        :: "r"(dst), "l"(src), "r"(bytes), "r"(mbar) : "memory");
}
__device__ __forceinline__ void fence_async_init() {
    asm volatile("fence.proxy.async.shared::cta;" ::: "memory");
}
__device__ __forceinline__ void ldsm4(uint32_t& r0, uint32_t& r1,
                                      uint32_t& r2, uint32_t& r3, uint32_t addr) {
    asm volatile("ldmatrix.sync.aligned.m8n8.x4.shared.b16 {%0,%1,%2,%3}, [%4];"
                 : "=r"(r0), "=r"(r1), "=r"(r2), "=r"(r3) : "r"(addr));
}

// ============================================================================
// split kernels (unchanged)
// ============================================================================
__device__ __forceinline__ void split8(const float* src, uint4& hw, uint4& lw)
{
    float4 a = *(const float4*)src;
    float4 b = *(const float4*)(src + 4);
    float v[8] = {a.x, a.y, a.z, a.w, b.x, b.y, b.z, b.w};
    uint32_t h[4], l[4];
#pragma unroll
    for (int i = 0; i < 4; i++) {
        __nv_bfloat16 h0 = __float2bfloat16_rn(v[2*i]);
        __nv_bfloat16 h1 = __float2bfloat16_rn(v[2*i+1]);
        __nv_bfloat16 l0 = __float2bfloat16_rn(v[2*i]   - __bfloat162float(h0));
        __nv_bfloat16 l1 = __float2bfloat16_rn(v[2*i+1] - __bfloat162float(h1));
        __nv_bfloat162 hp(h0, h1), lp(l0, l1);
        h[i] = *(uint32_t*)&hp; l[i] = *(uint32_t*)&lp;
    }
    hw = make_uint4(h[0], h[1], h[2], h[3]);
    lw = make_uint4(l[0], l[1], l[2], l[3]);
}

__global__ void __launch_bounds__(256)
split_in_kernel(const float* __restrict__ q, const float* __restrict__ k,
                const float* __restrict__ v)
{
    size_t i = (size_t)blockIdx.x * 256 + threadIdx.x;
    int mat = (int)(i / (ROWS * 64));
    size_t rem = i - (size_t)mat * (ROWS * 64);
    int r = (int)(rem >> 6);
    int kk = ((int)rem & 63) * 8;
    int kt = kk >> 5, km = kk & 31;
    const float* src = (mat == 0 ? q : mat == 1 ? k : v) + ((size_t)r << 9) + kk;
    uint4 hw, lw; split8(src, hw, lw);
    size_t d = ((size_t)kt * AIR + (size_t)mat * ROWS + r) * RSTR + km;
    *(uint4*)(g_inh + d) = hw;
    *(uint4*)(g_inl + d) = lw;
}

__global__ void __launch_bounds__(256)
split_w_kernel(const float* __restrict__ ipw, const float* __restrict__ outw)
{
    size_t i = (size_t)blockIdx.x * 256 + threadIdx.x;
    int r = (int)(i >> 6);
    int kk = ((int)i & 63) * 8;
    int kt = kk >> 5, km = kk & 31;
    const float* src = (r < 1536) ? (ipw + ((size_t)r << 9) + kk)
                                  : (outw + ((size_t)(r - 1536) << 9) + kk);
    uint4 hw, lw; split8(src, hw, lw);
    size_t d = ((size_t)kt * WR + r) * RSTR + km;
    *(uint4*)(g_wh + d) = hw;
    *(uint4*)(g_wl + d) = lw;
}

// ============================================================================
// bf16x3 GEMM, bulk 2-stage (unchanged from R11).
// ============================================================================
#define TBM 128
#define TBN 128
#define MATW (TBM * RSTR / 2)
#define GSTW (4 * MATW)
#define GEMM_SMEM (2 * GSTW * 4 + 16)

__device__ __forceinline__ void mma_bf16(float c[4],
    uint32_t a0, uint32_t a1, uint32_t a2, uint32_t a3,
    uint32_t b0, uint32_t b1)
{
    asm volatile(
        "mma.sync.aligned.m16n8k16.row.col.f32.bf16.bf16.f32 "
        "{%0,%1,%2,%3}, {%4,%5,%6,%7}, {%8,%9}, {%0,%1,%2,%3};"
        : "+f"(c[0]), "+f"(c[1]), "+f"(c[2]), "+f"(c[3])
        : "r"(a0), "r"(a1), "r"(a2), "r"(a3), "r"(b0), "r"(b1));
}

__device__ __forceinline__ void gemm_core(
    const __nv_bfloat16* __restrict__ Ah, const __nv_bfloat16* __restrict__ Al,
    int AR, int arow0,
    const __nv_bfloat16* __restrict__ Bh, const __nv_bfloat16* __restrict__ Bl,
    int BR, int brow0,
    const float* __restrict__ bias, void* __restrict__ Cout, int mode,
    uint32_t* smem)
{
    const int tid  = threadIdx.x;
    const int w    = tid >> 5;
    const int lane = tid & 31;
    const int g = lane >> 2, t = lane & 3;
    const int wm = w >> 2, wn = w & 3;
    const int m0 = wm * 64, n0 = wn * 32;
    const int bm = blockIdx.y * TBM;
    const int bn = blockIdx.x * TBN;
    const uint32_t sbase = (uint32_t)__cvta_generic_to_shared(smem);
    const uint32_t mb0 = sbase + 2u * GSTW * 4u;
    const uint32_t mb1 = mb0 + 8u;
    const uint32_t STB = GSTW * 4u;

    float acc[4][4][4];
#pragma unroll
    for (int mt = 0; mt < 4; mt++)
#pragma unroll
        for (int nt = 0; nt < 4; nt++)
#pragma unroll
            for (int u = 0; u < 4; u++) acc[mt][nt][u] = 0.f;

    if (tid == 0) { mbar_init(mb0, 1); mbar_init(mb1, 1); }
    fence_async_init();
    __syncthreads();

    auto issue = [&](int ss, int kt) {
        const uint32_t base = sbase + (uint32_t)ss * GSTW * 4u;
        const uint32_t mb = ss ? mb1 : mb0;
        if (tid < 4) {
            const __nv_bfloat16* src;
            size_t off;
            if (tid < 2) {
                src = tid ? Al : Ah;
                off = ((size_t)kt * AR + arow0 + bm) * RSTR;
            } else {
                src = (tid == 2) ? Bh : Bl;
                off = ((size_t)kt * BR + brow0 + bn) * RSTR;
            }
            bulk_g2s(base + (uint32_t)tid * MATW * 4u, src + off, MATW * 4u, mb);
        }
    };

    if (tid == 0) mbar_expect(mb0, STB);
    __syncthreads();
    issue(0, 0);

    for (int kt = 0; kt < NKT; kt++) {
        const int s = kt & 1;
        if (kt < NKT - 1) {
            if (tid == 0) mbar_expect(s ? mb0 : mb1, STB);
            __syncthreads();
            issue(s ^ 1, kt + 1);
        }
        mbar_wait(s ? mb1 : mb0, (uint32_t)((kt >> 1) & 1));

        const uint32_t* Sw  = smem + s * GSTW;
        const uint32_t* AhW = Sw;
        const uint32_t* AlW = Sw + MATW;
        const uint32_t* BhW = Sw + 2 * MATW;
        const uint32_t* BlW = Sw + 3 * MATW;

#pragma unroll
        for (int ks = 0; ks < 2; ks++) {
            uint32_t bhf[4][2], blf[4][2];
#pragma unroll
            for (int nt = 0; nt < 4; nt++) {
                int wb = (n0 + nt * 8 + g) * (RSTR / 2) + ks * 8 + t;
                bhf[nt][0] = BhW[wb]; bhf[nt][1] = BhW[wb + 4];
                blf[nt][0] = BlW[wb]; blf[nt][1] = BlW[wb + 4];
            }
#pragma unroll
            for (int mt = 0; mt < 4; mt++) {
                int wa = (m0 + mt * 16 + g) * (RSTR / 2) + ks * 8 + t;
                uint32_t ah0 = AhW[wa],     ah1 = AhW[wa + 8 * (RSTR / 2)];
                uint32_t ah2 = AhW[wa + 4], ah3 = AhW[wa + 8 * (RSTR / 2) + 4];
                uint32_t al0 = AlW[wa],     al1 = AlW[wa + 8 * (RSTR / 2)];
                uint32_t al2 = AlW[wa + 4], al3 = AlW[wa + 8 * (RSTR / 2) + 4];
#pragma unroll
                for (int nt = 0; nt < 4; nt++) {
                    mma_bf16(acc[mt][nt], ah0, ah1, ah2, ah3, bhf[nt][0], bhf[nt][1]);
                    mma_bf16(acc[mt][nt], ah0, ah1, ah2, ah3, blf[nt][0], blf[nt][1]);
                    mma_bf16(acc[mt][nt], al0, al1, al2, al3, bhf[nt][0], bhf[nt][1]);
                }
            }
        }
    }

    // epilogue
#pragma unroll
    for (int mt = 0; mt < 4; mt++) {
#pragma unroll
        for (int nt = 0; nt < 4; nt++) {
            int r = bm + m0 + mt * 16 + g;
            int c = bn + n0 + nt * 8 + 2 * t;
            float bx = bias[c], by = bias[c + 1];
            float2 v0 = make_float2(acc[mt][nt][0] + bx, acc[mt][nt][1] + by);
            float2 v1 = make_float2(acc[mt][nt][2] + bx, acc[mt][nt][3] + by);
            if (mode == 0) {
                float* C = (float*)Cout;
                *(float2*)(C + (size_t)r * HDIM + c) = v0;
                *(float2*)(C + (size_t)(r + 8) * HDIM + c) = v1;
            } else if (mode == 1) {
                int b_ = r >> 10, sr = r & 1023, h_ = c >> 6, d0 = c & 63;
                __half* base = (__half*)Cout +
                    ((size_t)(b_ * NHEAD + h_) * SEQ + sr) * PADKH + d0;
                *(__half2*)base = __floats2half2_rn(v0.x, v0.y);
                *(__half2*)(base + (size_t)8 * PADKH) = __floats2half2_rn(v1.x, v1.y);
            } else {
                int b_ = r >> 10, sr = r & 1023, h_ = c >> 6;
                int kb = sr >> 5, kin = sr & 31, d0 = c & 63;
                __half* base = (__half*)Cout +
                    (((size_t)(b_ * NHEAD + h_) * (SEQ / KB) + kb) * DHEAD) * PADVTH;
                base[(size_t)d0 * PADVTH + kin]           = __float2half_rn(v0.x);
                base[(size_t)(d0 + 1) * PADVTH + kin]     = __float2half_rn(v0.y);
                base[(size_t)d0 * PADVTH + kin + 8]       = __float2half_rn(v1.x);
                base[(size_t)(d0 + 1) * PADVTH + kin + 8] = __float2half_rn(v1.y);
            }
        }
    }
}

__global__ void __launch_bounds__(256, 2)
qkv_gemm_kernel(const float* __restrict__ ipb)
{
    extern __shared__ uint32_t smem_g[];
    const int z = blockIdx.z;
    void* outp = (z == 0) ? (void*)g_q : (z == 1) ? (void*)g_kh : (void*)g_vth;
    gemm_core(g_inh, g_inl, AIR, z * ROWS,
              g_wh, g_wl, WR, z * HDIM,
              ipb + z * HDIM, outp, z, smem_g);
}

__global__ void __launch_bounds__(256, 2)
outproj_kernel(const float* __restrict__ outb, float* __restrict__ out)
{
    extern __shared__ uint32_t smem_g[];
    gemm_core(g_ah, g_al, ROWS, 0,
              g_wh, g_wl, WR, 3 * HDIM,
              outb, out, 0, smem_g);
}

// ============================================================================
// fp16 flash attention, bulk 2-stage; LDSM fragments, bias-in-accumulator,
// scale folded into Q.
// Stage bytes: K[32x72 h] | V^T[64x40 h] | bias[32x132 f32] | mask[128x40 w]
// ============================================================================
#define QB 128
#define PADB 132
#define PADM 40
#define ST_V 4608
#define ST_B (ST_V + 5120)
#define ST_M (ST_B + KB*PADB*4)
#define ST_BYTES (ST_M + QB*PADM*4)
#define ATTN_TX (4608 + 5120 + KB*512 + QB*128)
#define ATTN_SMEM (2 * ST_BYTES + 16)

__device__ __forceinline__ void mma_f16(float c[4],
    uint32_t a0, uint32_t a1, uint32_t a2, uint32_t a3,
    uint32_t b0, uint32_t b1)
{
    asm volatile(
        "mma.sync.aligned.m16n8k16.row.col.f32.f16.f16.f32 "
        "{%0,%1,%2,%3}, {%4,%5,%6,%7}, {%8,%9}, {%0,%1,%2,%3};"
        : "+f"(c[0]), "+f"(c[1]), "+f"(c[2]), "+f"(c[3])
        : "r"(a0), "r"(a1), "r"(a2), "r"(a3), "r"(b0), "r"(b1));
}

__device__ __forceinline__ uint32_t packh2(float x, float y) {
    __half2 h = __floats2half2_rn(x, y);
    return *(uint32_t*)&h;
}

__global__ void __launch_bounds__(256, 2)
attn_mma_kernel(const float* __restrict__ kern,
                const uint32_t* __restrict__ amask, float scale)
{
    extern __shared__ char smc[];
    const uint32_t sbase = (uint32_t)__cvta_generic_to_shared(smc);
    const uint32_t mb0 = sbase + 2u * ST_BYTES;
    const uint32_t mb1 = mb0 + 8u;

    const int bh = blockIdx.y, b = bh >> 3, h = bh & 7;
    const int qb = blockIdx.x * QB;
    const int tid  = threadIdx.x;
    const int w    = tid >> 5;
    const int lane = tid & 31;
    const int g = lane >> 2, t = lane & 3;

    // ldmatrix lane geometry: matrix m = lane>>3, row r_ = lane&7
    const int m_  = lane >> 3, r_ = lane & 7;
    const int flo = m_ >> 1, hh = m_ & 1;
    const uint32_t klane = (uint32_t)((flo * 8 + r_) * (PADKH * 2) + hh * 16);
    const uint32_t vlane = (uint32_t)((flo * 8 + r_) * (PADVTH * 2) + hh * 16);

    const float*  Qg = g_q + (size_t)b * SEQ * HDIM + h * DHEAD;
    const __half* Kp = g_kh + (size_t)bh * SEQ * PADKH;
    const __half* Vt = g_vth + (size_t)bh * (SEQ / KB) * DHEAD * PADVTH;
    const float* kern_bh = kern + (size_t)bh * SEQ * SEQ;
    const uint32_t* mask_bh = amask + (size_t)bh * SEQ * SEQ;

    if (tid == 0) { mbar_init(mb0, 1); mbar_init(mb1, 1); }
    fence_async_init();
    __syncthreads();

    auto issue = [&](int ss, int kb) {
        const uint32_t base = sbase + (uint32_t)ss * ST_BYTES;
        const uint32_t mb = ss ? mb1 : mb0;
        if (tid == 0)
            bulk_g2s(base, Kp + (size_t)kb * KB * PADKH, 4608u, mb);
        else if (tid == 1)
            bulk_g2s(base + ST_V, Vt + (size_t)kb * DHEAD * PADVTH, 5120u, mb);
        else if (tid >= 32 && tid < 64) {
            int r = tid - 32;
            bulk_g2s(base + (uint32_t)(ST_B + r * PADB * 4),
                     kern_bh + (size_t)(kb * KB + r) * SEQ + qb, 512u, mb);
        } else if (tid >= 64 && tid < 192) {
            int r = tid - 64;
            bulk_g2s(base + (uint32_t)(ST_M + r * PADM * 4),
                     mask_bh + (size_t)(qb + r) * SEQ + kb * KB, 128u, mb);
        }
    };

    if (tid == 0) mbar_expect(mb0, ATTN_TX);
    __syncthreads();
    issue(0, 0);

    // Q fragments, pre-scaled by `scale` (exact: 2^-3)
    uint32_t qa[4][4];
    {
        const float* Qr0 = Qg + (size_t)(qb + w * 16 + g) * HDIM;
        const float* Qr1 = Qr0 + 8 * (size_t)HDIM;
#pragma unroll
        for (int kk = 0; kk < 4; kk++) {
            int d0 = 16 * kk + 2 * t;
            float2 x0 = *(const float2*)(Qr0 + d0);
            float2 x1 = *(const float2*)(Qr1 + d0);
            float2 x2 = *(const float2*)(Qr0 + d0 + 8);
            float2 x3 = *(const float2*)(Qr1 + d0 + 8);
            qa[kk][0] = packh2(x0.x * scale, x0.y * scale);
            qa[kk][1] = packh2(x1.x * scale, x1.y * scale);
            qa[kk][2] = packh2(x2.x * scale, x2.y * scale);
            qa[kk][3] = packh2(x3.x * scale, x3.y * scale);
        }
    }

    float o[8][4];
#pragma unroll
    for (int f = 0; f < 8; f++)
#pragma unroll
        for (int u = 0; u < 4; u++) o[f][u] = 0.f;
    float m_run[2] = {-1e30f, -1e30f}, l_run[2] = {0.f, 0.f};

    const int qrl0 = w * 16 + g;

    const int NT = SEQ / KB;
    for (int kb = 0; kb < NT; kb++) {
        const int s = kb & 1;
        if (kb < NT - 1) {
            if (tid == 0) mbar_expect(s ? mb0 : mb1, ATTN_TX);
            __syncthreads();
            issue(s ^ 1, kb + 1);
        }
        mbar_wait(s ? mb1 : mb0, (uint32_t)((kb >> 1) & 1));

        const char* Sb = smc + (size_t)s * ST_BYTES;
        const uint32_t stg = sbase + (uint32_t)s * ST_BYTES;
        const float*  Bs = (const float*)(Sb + ST_B);
        const uint32_t* Ms = (const uint32_t*)(Sb + ST_M);

        // ---- S accumulators initialized with the bias tile ----
        float sc[4][4];
#pragma unroll
        for (int f = 0; f < 4; f++) {
            int kc = f * 8 + 2 * t;
            sc[f][0] = Bs[kc * PADB + qrl0];
            sc[f][1] = Bs[(kc + 1) * PADB + qrl0];
            sc[f][2] = Bs[kc * PADB + qrl0 + 8];
            sc[f][3] = Bs[(kc + 1) * PADB + qrl0 + 8];
        }

        // ---- S += (scale*Q) K^T : LDSM.x4 fragments ----
#pragma unroll
        for (int kk = 0; kk < 4; kk++) {
#pragma unroll
            for (int j = 0; j < 2; j++) {
                uint32_t b00, b01, b10, b11;
                ldsm4(b00, b01, b10, b11,
                      stg + klane + (uint32_t)(j * 16 * PADKH * 2 + kk * 32));
                mma_f16(sc[2 * j],     qa[kk][0], qa[kk][1], qa[kk][2], qa[kk][3], b00, b01);
                mma_f16(sc[2 * j + 1], qa[kk][0], qa[kk][1], qa[kk][2], qa[kk][3], b10, b11);
            }
        }

        // ---- mask + online softmax (bias & scale already in) ----
#pragma unroll
        for (int e = 0; e < 2; e++) {
            const int qrl = qrl0 + e * 8;
            const uint2* Mrow = (const uint2*)(Ms + qrl * PADM);
            float rmax = -1e30f;
#pragma unroll
            for (int f = 0; f < 4; f++) {
                uint2 mw = Mrow[f * 4 + t];
                float s0 = sc[f][e * 2 + 0];
                float s1 = sc[f][e * 2 + 1];
                s0 = mw.x ? -1e30f : s0;
                s1 = mw.y ? -1e30f : s1;
                sc[f][e * 2 + 0] = s0;
                sc[f][e * 2 + 1] = s1;
                rmax = fmaxf(rmax, fmaxf(s0, s1));
            }
            rmax = fmaxf(rmax, __shfl_xor_sync(0xffffffffu, rmax, 1));
            rmax = fmaxf(rmax, __shfl_xor_sync(0xffffffffu, rmax, 2));
            float mn = fmaxf(m_run[e], rmax);
            float fe = __expf(m_run[e] - mn);
            float ps = 0.f;
#pragma unroll
            for (int f = 0; f < 4; f++) {
#pragma unroll
                for (int u = 0; u < 2; u++) {
                    float sv = sc[f][e * 2 + u];
                    float p = (sv <= -1e29f) ? 0.f : __expf(sv - mn);
                    sc[f][e * 2 + u] = p;
                    ps += p;
                }
            }
            ps += __shfl_xor_sync(0xffffffffu, ps, 1);
            ps += __shfl_xor_sync(0xffffffffu, ps, 2);
            l_run[e] = l_run[e] * fe + ps;
            m_run[e] = mn;
#pragma unroll
            for (int f = 0; f < 4; f++) {
                o[2 * f][e * 2 + 0] *= fe;     o[2 * f][e * 2 + 1] *= fe;
                o[2 * f + 1][e * 2 + 0] *= fe; o[2 * f + 1][e * 2 + 1] *= fe;
            }
        }

        // ---- O += P @ V : P packed straight from C-frags; LDSM V frags ----
#pragma unroll
        for (int kk = 0; kk < 2; kk++) {
            uint32_t a0 = packh2(sc[2 * kk][0],     sc[2 * kk][1]);
            uint32_t a1 = packh2(sc[2 * kk][2],     sc[2 * kk][3]);
            uint32_t a2 = packh2(sc[2 * kk + 1][0], sc[2 * kk + 1][1]);
            uint32_t a3 = packh2(sc[2 * kk + 1][2], sc[2 * kk + 1][3]);
#pragma unroll
            for (int j = 0; j < 4; j++) {
                uint32_t v00, v01, v10, v11;
                ldsm4(v00, v01, v10, v11,
                      stg + (uint32_t)ST_V + vlane +
                      (uint32_t)(j * 16 * PADVTH * 2 + kk * 32));
                mma_f16(o[2 * j],     a0, a1, a2, a3, v00, v01);
                mma_f16(o[2 * j + 1], a0, a1, a2, a3, v10, v11);
            }
        }
    }

    // ---- normalize + write hi/lo bf16 in outproj's tiled layout ----
#pragma unroll
    for (int e = 0; e < 2; e++) {
        float inv = 1.0f / l_run[e];
        int qrl = qrl0 + e * 8;
        size_t grow = (size_t)b * SEQ + qb + qrl;
#pragma unroll
        for (int f = 0; f < 8; f++) {
            float x = o[f][e * 2 + 0] * inv;
            float y = o[f][e * 2 + 1] * inv;
            __nv_bfloat16 hx = __float2bfloat16_rn(x);
            __nv_bfloat16 hy = __float2bfloat16_rn(y);
            __nv_bfloat16 lx = __float2bfloat16_rn(x - __bfloat162float(hx));
            __nv_bfloat16 ly = __float2bfloat16_rn(y - __bfloat162float(hy));
            __nv_bfloat162 hp(hx, hy), lp(lx, ly);
            int c = h * DHEAD + f * 8 + 2 * t;
            int kt = c >> 5, km = c & 31;
            size_t off = ((size_t)kt * ROWS + grow) * RSTR + km;
            *(uint32_t*)(g_ah + off) = *(uint32_t*)&hp;
            *(uint32_t*)(g_al + off) = *(uint32_t*)&lp;
        }
    }
}

// ============================================================================
// Launch
// ============================================================================
extern "C" void kernel_launch(void* const* d_in, const int* in_sizes, int n_in,
                              void* d_out, int out_size)
{
    const float* query    = (const float*)d_in[0];
    const float* key_     = (const float*)d_in[1];
    const float* value    = (const float*)d_in[2];
    const uint32_t* amask = (const uint32_t*)d_in[3];
    const float* kern     = (const float*)d_in[5];
    const float* ipw      = (const float*)d_in[6];
    const float* ipb      = (const float*)d_in[7];
    const float* outw     = (const float*)d_in[8];
    const float* outb     = (const float*)d_in[9];
    float* out = (float*)d_out;

    cudaFuncSetAttribute(attn_mma_kernel,
                         cudaFuncAttributeMaxDynamicSharedMemorySize, ATTN_SMEM);
    cudaFuncSetAttribute(qkv_gemm_kernel,
                         cudaFuncAttributeMaxDynamicSharedMemorySize, GEMM_SMEM);
    cudaFuncSetAttribute(outproj_kernel,
                         cudaFuncAttributeMaxDynamicSharedMemorySize, GEMM_SMEM);

    split_in_kernel<<<3 * ROWS * 64 / 256, 256>>>(query, key_, value);
    split_w_kernel<<<WR * 64 / 256, 256>>>(ipw, outw);

    dim3 gq(HDIM / TBN, ROWS / TBM, 3);
    qkv_gemm_kernel<<<gq, 256, GEMM_SMEM>>>(ipb);

    dim3 ga(SEQ / QB, BATCH * NHEAD, 1);
    attn_mma_kernel<<<ga, 256, ATTN_SMEM>>>(kern, amask, 0.125f);

    dim3 go(HDIM / TBN, ROWS / TBM, 1);
    outproj_kernel<<<go, 256, GEMM_SMEM>>>(outb, out);
}